// round 3
// baseline (speedup 1.0000x reference)
#include <cuda_runtime.h>

#define HWD 56
#define NPIX 3136

// ---------------- device scratch (rewritten every launch) -------------------
__device__ float g_wT[3*64*9*64];      // [e][ci][k9][co]
__device__ float g_S1x[32*64*16];      // phase sums of x
__device__ float g_SM [32*32*16];      // phase sums of matching
__device__ float g_Pconv[32*64*16];    // s-weighted relu(conv) phase sums
__device__ float g_sel1[32*3];
__device__ int   g_topidx[32*2];
__device__ float g_topval[32*2];
__device__ float g_tb[32];
__device__ int   g_e3[32];
__device__ float g_s3[32];
__device__ float g_noise2[96];
__device__ float g_lbent;
__device__ float g_sel2eff[96];
__device__ float g_feat[32*160];

// ---------------- threefry2x32 core ------------------------------------------
__device__ __forceinline__ unsigned rotl32(unsigned x, int d){ return (x<<d)|(x>>(32-d)); }
__device__ void threefry(unsigned k0, unsigned k1, unsigned c0, unsigned c1,
                         unsigned &o0, unsigned &o1){
    unsigned ks[3] = {k0, k1, 0x1BD11BDAu ^ k0 ^ k1};
    unsigned x0 = c0 + ks[0], x1 = c1 + ks[1];
    const int ra[4] = {13,15,26,6};
    const int rb[4] = {17,29,16,24};
    #pragma unroll
    for (int i = 0; i < 5; i++){
        const int* rr = ((i & 1) == 0) ? ra : rb;
        #pragma unroll
        for (int j = 0; j < 4; j++){ x0 += x1; x1 = rotl32(x1, rr[j]); x1 ^= x0; }
        x0 += ks[(i+1)%3];
        x1 += ks[(i+2)%3] + (unsigned)(i+1);
    }
    o0 = x0; o1 = x1;
}
// partitionable 32-bit random bits: counter = element index (hi=0, lo=i), XOR halves
__device__ __forceinline__ unsigned rbits32(unsigned k0, unsigned k1, unsigned i){
    unsigned a, b; threefry(k0, k1, 0u, i, a, b); return a ^ b;
}
__device__ __forceinline__ float bits2unif(unsigned b){
    return __uint_as_float((b >> 9) | 0x3F800000u) - 1.0f;
}

// ---------------- packed f32x2 helpers ---------------------------------------
__device__ __forceinline__ void fma2(unsigned long long &d, unsigned long long a,
                                     unsigned long long b){
    asm("fma.rn.f32x2 %0, %1, %2, %0;" : "+l"(d) : "l"(a), "l"(b));
}
__device__ __forceinline__ unsigned long long pack2(float x, float y){
    unsigned long long r; asm("mov.b64 %0, {%1, %2};" : "=l"(r) : "f"(x), "f"(y)); return r;
}
__device__ __forceinline__ float2 unpack2(unsigned long long v){
    float2 r; asm("mov.b64 {%0, %1}, %2;" : "=f"(r.x), "=f"(r.y) : "l"(v)); return r;
}

// ---------------- expert1 weight transpose OIHW -> [ci][k][co] --------------
__global__ void k_wtrans(const float* __restrict__ e1w){
    int i = blockIdx.x * 256 + threadIdx.x;
    if (i >= 3*64*9*64) return;
    int co = i % 64;
    int t  = i / 64;
    int k  = t % 9;  t /= 9;
    int ci = t % 64;
    int e  = t / 64;
    g_wT[i] = e1w[((e*64 + co)*64 + ci)*9 + k];
}

// ---------------- phase sums of x & matching; copy matching to output -------
__global__ void k_phase(const float* __restrict__ x, const float* __restrict__ matching,
                        float* __restrict__ out_match){
    int c = blockIdx.x;          // 0..63: x channel, 64..95: matching channel
    int b = blockIdx.y;
    int tid = threadIdx.x;       // 224
    int rr = tid / 56, w = tid % 56;
    bool ism = (c >= 64);
    const float* src = ism ? (matching + (size_t)(b*32 + (c-64))*NPIX)
                           : (x        + (size_t)(b*64 + c)*NPIX);
    float* dst = ism ? (out_match + (size_t)(b*32 + (c-64))*NPIX) : (float*)0;
    float acc = 0.f;
    #pragma unroll
    for (int k = 0; k < 14; k++){
        int idx = (rr + 4*k)*56 + w;
        float v = src[idx];
        acc += v;
        if (ism) dst[idx] = v;
    }
    __shared__ float part[224];
    part[tid] = acc;
    __syncthreads();
    if (tid < 16){
        int p = tid / 4, q = tid % 4;
        float s = 0.f;
        #pragma unroll
        for (int t = 0; t < 14; t++) s += part[p*56 + q + 4*t];
        if (!ism){
            g_S1x[(b*64 + c)*16 + tid] = s;
            g_Pconv[(b*64 + c)*16 + tid] = 0.f;
        } else {
            g_SM[(b*32 + (c-64))*16 + tid] = s;
        }
    }
}

// ---------------- router1 + threefry noise + top2 + layer1 losses -----------
__global__ void k_router1(const float* __restrict__ r1w, const float* __restrict__ r1b){
    __shared__ unsigned key1[2], key2[2];
    __shared__ float noise1[96];
    __shared__ float lg[96];
    __shared__ float sall[32][3];
    __shared__ int   iall[32][2];
    int tid = threadIdx.x;   // 128
    if (tid == 0){
        // partitionable split: key i = threefry(key, hi=0, lo=i), both outputs
        unsigned a0,b0,a1,b1;
        threefry(0u, 42u, 0u, 0u, a0, b0);
        threefry(0u, 42u, 0u, 1u, a1, b1);
        key1[0]=a0; key1[1]=b0; key2[0]=a1; key2[1]=b1;
    }
    __syncthreads();
    if (tid < 96){
        noise1[tid] = bits2unif(rbits32(key1[0], key1[1], (unsigned)tid));
        g_noise2[tid] = bits2unif(rbits32(key2[0], key2[1], (unsigned)tid));
    }
    __syncthreads();
    if (tid < 96){
        int b = tid / 3, e = tid % 3;
        const float* S = &g_S1x[b*64*16];
        const float* W = &r1w[e*64*16];
        float acc = 0.f;
        for (int i = 0; i < 64*16; i++) acc += S[i]*W[i];
        lg[tid] = acc * (1.0f/196.0f) + r1b[e] + 0.05f*noise1[tid];
    }
    __syncthreads();
    if (tid < 32){
        int b = tid;
        float l0 = lg[b*3], l1 = lg[b*3+1], l2 = lg[b*3+2];
        float m  = fmaxf(l0, fmaxf(l1, l2));
        float x0 = expf(l0-m), x1 = expf(l1-m), x2 = expf(l2-m);
        float s  = x0 + x1 + x2;
        float pv[3] = {x0/s, x1/s, x2/s};
        int i0 = 0; if (pv[1] > pv[i0]) i0 = 1; if (pv[2] > pv[i0]) i0 = 2;
        int i1 = -1;
        for (int e = 0; e < 3; e++){ if (e == i0) continue; if (i1 < 0 || pv[e] > pv[i1]) i1 = e; }
        int e3 = 3 - i0 - i1;
        g_sel1[b*3]=pv[0]; g_sel1[b*3+1]=pv[1]; g_sel1[b*3+2]=pv[2];
        g_topidx[b*2]=i0;  g_topidx[b*2+1]=i1;
        g_topval[b*2]=pv[i0]; g_topval[b*2+1]=pv[i1];
        g_tb[b]=pv[i0]+pv[i1];
        g_e3[b]=e3; g_s3[b]=pv[e3];
        sall[b][0]=pv[0]; sall[b][1]=pv[1]; sall[b][2]=pv[2];
        iall[b][0]=i0; iall[b][1]=i1;
    }
    __syncthreads();
    if (tid == 0){
        float sbar[3]={0,0,0}, cnt[3]={0,0,0}; float ent = 0.f;
        for (int b = 0; b < 32; b++){
            for (int e = 0; e < 3; e++){ float sv = sall[b][e]; sbar[e]+=sv; ent -= sv*logf(sv+1e-9f); }
            cnt[iall[b][0]] += 1.f; cnt[iall[b][1]] += 1.f;
        }
        float lb = 0.f;
        for (int e = 0; e < 3; e++) lb += (sbar[e]/32.f)*(cnt[e]/32.f);
        g_lbent = lb + 0.01f*(ent/32.f);
    }
}

// ---------------- 3x3 SAME conv (top-2 experts) -> weighted relu phase sums -
// grid (7, 2, 32); block 448 = 4 co-groups x (8 rows x 14 col-groups)
__global__ void __launch_bounds__(448) k_conv(const float* __restrict__ x,
                                              const float* __restrict__ e1b){
    __shared__ __align__(16) float xs[8][10][58];
    __shared__ __align__(16) float ws[8*9*64];
    __shared__ float pl[1024];
    int rb = blockIdx.x, slot = blockIdx.y, b = blockIdx.z;
    int e = g_topidx[b*2+slot];
    float s = g_topval[b*2+slot];
    int tid = threadIdx.x;
    int cog = tid/112, t = tid%112, tr = t/14, cg = t%14;
    int h0 = rb*8, wc = cg*4;
    for (int i = tid; i < 1024; i += 448) pl[i] = 0.f;
    unsigned long long acc[4][8];
    #pragma unroll
    for (int px=0;px<4;px++)
        #pragma unroll
        for (int p=0;p<8;p++) acc[px][p] = 0ull;
    const float* xb = x + (size_t)b*64*NPIX;
    const float* wb = g_wT + (size_t)e*64*9*64;
    for (int c0 = 0; c0 < 64; c0 += 8){
        __syncthreads();
        for (int i = tid; i < 8*10*58; i += 448){
            int ci = i/580, r = (i/58)%10, col = i%58;
            int h = h0 - 1 + r, gw = col - 1;
            float v = 0.f;
            if (h >= 0 && h < 56 && gw >= 0 && gw < 56)
                v = xb[(size_t)(c0+ci)*NPIX + h*56 + gw];
            xs[ci][r][col] = v;
        }
        for (int i = tid; i < 8*9*64; i += 448)
            ws[i] = wb[(size_t)c0*9*64 + i];
        __syncthreads();
        #pragma unroll 1
        for (int ci = 0; ci < 8; ci++){
            unsigned long long vp[3][6];
            #pragma unroll
            for (int rr=0;rr<3;rr++)
                #pragma unroll
                for (int cc=0;cc<6;cc++){
                    float v = xs[ci][tr+rr][wc+cc];
                    vp[rr][cc] = pack2(v, v);
                }
            #pragma unroll
            for (int p=0;p<8;p++){
                int co2 = cog*16 + 2*p;
                unsigned long long wk[9];
                #pragma unroll
                for (int k=0;k<9;k++)
                    wk[k] = *reinterpret_cast<const unsigned long long*>(&ws[(ci*9+k)*64 + co2]);
                #pragma unroll
                for (int rr=0;rr<3;rr++)
                    #pragma unroll
                    for (int cc=0;cc<3;cc++)
                        #pragma unroll
                        for (int px=0;px<4;px++)
                            fma2(acc[px][p], vp[rr][px+cc], wk[rr*3+cc]);
            }
        }
    }
    int ph = (h0 + tr) & 3;
    #pragma unroll
    for (int p=0;p<8;p++){
        int co = cog*16 + 2*p;
        float b0v = e1b[e*64+co], b1v = e1b[e*64+co+1];
        #pragma unroll
        for (int px=0;px<4;px++){
            float2 y = unpack2(acc[px][p]);
            float v0 = s * fmaxf(0.f, y.x + b0v);
            float v1 = s * fmaxf(0.f, y.y + b1v);
            int bin = ph*4 + px;  // col phase q == px
            atomicAdd(&pl[co*16 + bin], v0);
            atomicAdd(&pl[(co+1)*16 + bin], v1);
        }
    }
    __syncthreads();
    for (int i = tid; i < 1024; i += 448)
        atomicAdd(&g_Pconv[(size_t)b*1024 + i], pl[i]);
}

// ---------------- feat, router2, losses -------------------------------------
__global__ void k_final(const float* __restrict__ r2w, const float* __restrict__ r2b,
                        const float* __restrict__ e1b, float* __restrict__ out,
                        const int* __restrict__ epoch_p){
    __shared__ float fs[5120];
    __shared__ float lg[96];
    __shared__ float sels[96];
    __shared__ float c3s[2048];
    int tid = threadIdx.x;  // 256
    int epoch = epoch_p ? epoch_p[0] : 35;
    for (int i = tid; i < 2048; i += 256){
        int b = i >> 6, c = i & 63;
        c3s[i] = g_s3[b] * fmaxf(0.f, e1b[g_e3[b]*64 + c]);
    }
    __syncthreads();
    for (int i = tid; i < 5120; i += 256){
        int b = i/160, c = i%160;
        float v, sum = 0.f;
        if (c < 64){
            const float* P = &g_Pconv[(b*64+c)*16];
            for (int k=0;k<16;k++) sum += P[k];
            v = sum*(1.f/3136.f) + c3s[b*64+c];
        } else if (c < 128){
            const float* P = &g_S1x[(b*64+(c-64))*16];
            for (int k=0;k<16;k++) sum += P[k];
            v = g_tb[b]*sum*(1.f/3136.f);
        } else {
            const float* P = &g_SM[(b*32+(c-128))*16];
            for (int k=0;k<16;k++) sum += P[k];
            v = sum*(1.f/3136.f);
        }
        fs[i] = v; g_feat[i] = v;
    }
    __syncthreads();
    if (tid < 96){
        int b = tid/3, e = tid%3;
        const float* W = &r2w[e*160*16];
        float acc = 0.f, accC = 0.f;
        float tb = g_tb[b];
        for (int c = 0; c < 64; c++){
            const float* P = &g_Pconv[(b*64+c)*16];
            float wsum = 0.f;
            for (int k=0;k<16;k++){ acc += P[k]*W[c*16+k]; wsum += W[c*16+k]; }
            accC += c3s[b*64+c]*wsum;
        }
        for (int c = 0; c < 64; c++){
            const float* P = &g_S1x[(b*64+c)*16];
            const float* Wc = &W[(64+c)*16];
            for (int k=0;k<16;k++) acc += tb*P[k]*Wc[k];
        }
        for (int c = 0; c < 32; c++){
            const float* P = &g_SM[(b*32+c)*16];
            const float* Wc = &W[(128+c)*16];
            for (int k=0;k<16;k++) acc += P[k]*Wc[k];
        }
        lg[tid] = acc*(1.f/196.f) + accC + r2b[e] + 0.05f*g_noise2[tid];
    }
    __syncthreads();
    if (tid < 32){
        int b = tid;
        if (epoch < 30){
            sels[b*3] = sels[b*3+1] = sels[b*3+2] = 1.f/3.f;
        } else {
            float l0=lg[b*3], l1=lg[b*3+1], l2=lg[b*3+2];
            float m=fmaxf(l0,fmaxf(l1,l2));
            float x0=expf(l0-m), x1=expf(l1-m), x2=expf(l2-m);
            float sm=x0+x1+x2;
            sels[b*3]   = (x0/sm + 0.01f)/1.03f;
            sels[b*3+1] = (x1/sm + 0.01f)/1.03f;
            sels[b*3+2] = (x2/sm + 0.01f)/1.03f;
        }
        g_sel2eff[b*3]=sels[b*3]; g_sel2eff[b*3+1]=sels[b*3+1]; g_sel2eff[b*3+2]=sels[b*3+2];
    }
    __syncthreads();
    if (tid == 0){
        float loss2 = 0.f;
        if (epoch >= 30){
            for (int e=0;e<3;e++){
                float imp=0.f;
                for (int b=0;b<32;b++) imp += sels[b*3+e];
                imp /= 32.f;
                loss2 += imp*imp;
            }
            loss2 *= 3.f;
        }
        out[8192] = g_lbent + loss2;
        out[8192 + 1 + 32*32*NPIX] = loss2;
    }
}

// ---------------- output2 = sel-mixed expert2 GEMM ---------------------------
__global__ void k_out(const float* __restrict__ e2w, const float* __restrict__ e2b,
                      float* __restrict__ out){
    __shared__ float F[160];
    int b = blockIdx.x, a = threadIdx.x;  // 256 threads
    for (int i = a; i < 160; i += 256) F[i] = g_feat[b*160 + i];
    __syncthreads();
    float acc = 0.f;
    for (int e=0;e<3;e++){
        float se = g_sel2eff[b*3+e];
        acc += se * e2b[e*256+a];
        const float* W = &e2w[(size_t)e*160*256 + a];
        for (int c=0;c<160;c++)
            acc += se * F[c] * W[(size_t)c*256];
    }
    out[b*256 + a] = acc;
}

extern "C" void kernel_launch(void* const* d_in, const int* in_sizes, int n_in,
                              void* d_out, int out_size) {
    const float* x    = (const float*)d_in[0];
    const float* mat  = (const float*)d_in[1];
    const float* r1w  = (const float*)d_in[2];
    const float* r1b  = (const float*)d_in[3];
    const float* r2w  = (const float*)d_in[4];
    const float* r2b  = (const float*)d_in[5];
    const float* e1w  = (const float*)d_in[6];
    const float* e1b  = (const float*)d_in[7];
    const float* e2w  = (const float*)d_in[8];
    const float* e2b  = (const float*)d_in[9];
    const int*   ep   = (n_in > 10) ? (const int*)d_in[10] : (const int*)0;
    float* out = (float*)d_out;

    k_wtrans<<<(3*64*9*64 + 255)/256, 256>>>(e1w);
    k_phase<<<dim3(96, 32), 224>>>(x, mat, out + 8193);
    k_router1<<<1, 128>>>(r1w, r1b);
    k_conv<<<dim3(7, 2, 32), 448>>>(x, e1b);
    k_final<<<1, 256>>>(r2w, r2b, e1b, out, ep);
    k_out<<<32, 256>>>(e2w, e2b, out);
}

// round 4
// speedup vs baseline: 1.0004x; 1.0004x over previous
#include <cuda_runtime.h>

#define HWD 56
#define NPIX 3136

// ---------------- device scratch (rewritten every launch) -------------------
__device__ float g_wT[3*64*9*64];      // [e][ci][k9][co]
__device__ float g_S1x[32*64*16];      // phase sums of x
__device__ float g_SM [32*32*16];      // phase sums of matching
__device__ float g_Pconv[32*64*16];    // s-weighted relu(conv) phase sums
__device__ float g_sel1[32*3];
__device__ int   g_topidx[32*2];
__device__ float g_topval[32*2];
__device__ float g_tb[32];
__device__ int   g_e3[32];
__device__ float g_s3[32];
__device__ float g_noise2[96];
__device__ float g_lbent;
__device__ float g_sel2eff[96];
__device__ float g_feat[32*160];

// ---------------- threefry2x32 core ------------------------------------------
__device__ __forceinline__ unsigned rotl32(unsigned x, int d){ return (x<<d)|(x>>(32-d)); }
__device__ void threefry(unsigned k0, unsigned k1, unsigned c0, unsigned c1,
                         unsigned &o0, unsigned &o1){
    unsigned ks[3] = {k0, k1, 0x1BD11BDAu ^ k0 ^ k1};
    unsigned x0 = c0 + ks[0], x1 = c1 + ks[1];
    const int ra[4] = {13,15,26,6};
    const int rb[4] = {17,29,16,24};
    #pragma unroll
    for (int i = 0; i < 5; i++){
        const int* rr = ((i & 1) == 0) ? ra : rb;
        #pragma unroll
        for (int j = 0; j < 4; j++){ x0 += x1; x1 = rotl32(x1, rr[j]); x1 ^= x0; }
        x0 += ks[(i+1)%3];
        x1 += ks[(i+2)%3] + (unsigned)(i+1);
    }
    o0 = x0; o1 = x1;
}
// partitionable 32-bit random bits: counter = element index (hi=0, lo=i), XOR halves
__device__ __forceinline__ unsigned rbits32(unsigned k0, unsigned k1, unsigned i){
    unsigned a, b; threefry(k0, k1, 0u, i, a, b); return a ^ b;
}
__device__ __forceinline__ float bits2unif(unsigned b){
    return __uint_as_float((b >> 9) | 0x3F800000u) - 1.0f;
}

// ---------------- packed f32x2 helpers ---------------------------------------
__device__ __forceinline__ void fma2(unsigned long long &d, unsigned long long a,
                                     unsigned long long b){
    asm("fma.rn.f32x2 %0, %1, %2, %0;" : "+l"(d) : "l"(a), "l"(b));
}
__device__ __forceinline__ unsigned long long pack2(float x, float y){
    unsigned long long r; asm("mov.b64 %0, {%1, %2};" : "=l"(r) : "f"(x), "f"(y)); return r;
}
__device__ __forceinline__ float2 unpack2(unsigned long long v){
    float2 r; asm("mov.b64 {%0, %1}, %2;" : "=f"(r.x), "=f"(r.y) : "l"(v)); return r;
}

// ---------------- expert1 weight transpose OIHW -> [ci][k][co] --------------
__global__ void k_wtrans(const float* __restrict__ e1w){
    int i = blockIdx.x * 256 + threadIdx.x;
    if (i >= 3*64*9*64) return;
    int co = i % 64;
    int t  = i / 64;
    int k  = t % 9;  t /= 9;
    int ci = t % 64;
    int e  = t / 64;
    g_wT[i] = e1w[((e*64 + co)*64 + ci)*9 + k];
}

// ---------------- phase sums of x & matching; copy matching to output -------
__global__ void k_phase(const float* __restrict__ x, const float* __restrict__ matching,
                        float* __restrict__ out_match){
    int c = blockIdx.x;          // 0..63: x channel, 64..95: matching channel
    int b = blockIdx.y;
    int tid = threadIdx.x;       // 224
    int rr = tid / 56, w = tid % 56;
    bool ism = (c >= 64);
    const float* src = ism ? (matching + (size_t)(b*32 + (c-64))*NPIX)
                           : (x        + (size_t)(b*64 + c)*NPIX);
    float* dst = ism ? (out_match + (size_t)(b*32 + (c-64))*NPIX) : (float*)0;
    float acc = 0.f;
    #pragma unroll
    for (int k = 0; k < 14; k++){
        int idx = (rr + 4*k)*56 + w;
        float v = src[idx];
        acc += v;
        if (ism) dst[idx] = v;
    }
    __shared__ float part[224];
    part[tid] = acc;
    __syncthreads();
    if (tid < 16){
        int p = tid / 4, q = tid % 4;
        float s = 0.f;
        #pragma unroll
        for (int t = 0; t < 14; t++) s += part[p*56 + q + 4*t];
        if (!ism){
            g_S1x[(b*64 + c)*16 + tid] = s;
            g_Pconv[(b*64 + c)*16 + tid] = 0.f;
        } else {
            g_SM[(b*32 + (c-64))*16 + tid] = s;
        }
    }
}

// ---------------- router1 + threefry noise + top2 + layer1 losses -----------
__global__ void k_router1(const float* __restrict__ r1w, const float* __restrict__ r1b){
    __shared__ unsigned key1[2], key2[2];
    __shared__ float noise1[96];
    __shared__ float lg[96];
    __shared__ float sall[32][3];
    __shared__ int   iall[32][2];
    int tid = threadIdx.x;   // 128
    if (tid == 0){
        // partitionable split: key i = threefry(key, hi=0, lo=i), both outputs
        unsigned a0,b0,a1,b1;
        threefry(0u, 42u, 0u, 0u, a0, b0);
        threefry(0u, 42u, 0u, 1u, a1, b1);
        key1[0]=a0; key1[1]=b0; key2[0]=a1; key2[1]=b1;
    }
    __syncthreads();
    if (tid < 96){
        noise1[tid] = bits2unif(rbits32(key1[0], key1[1], (unsigned)tid));
        g_noise2[tid] = bits2unif(rbits32(key2[0], key2[1], (unsigned)tid));
    }
    __syncthreads();
    if (tid < 96){
        int b = tid / 3, e = tid % 3;
        const float* S = &g_S1x[b*64*16];
        const float* W = &r1w[e*64*16];
        float acc = 0.f;
        for (int i = 0; i < 64*16; i++) acc += S[i]*W[i];
        lg[tid] = acc * (1.0f/196.0f) + r1b[e] + 0.05f*noise1[tid];
    }
    __syncthreads();
    if (tid < 32){
        int b = tid;
        float l0 = lg[b*3], l1 = lg[b*3+1], l2 = lg[b*3+2];
        float m  = fmaxf(l0, fmaxf(l1, l2));
        float x0 = expf(l0-m), x1 = expf(l1-m), x2 = expf(l2-m);
        float s  = x0 + x1 + x2;
        float pv[3] = {x0/s, x1/s, x2/s};
        int i0 = 0; if (pv[1] > pv[i0]) i0 = 1; if (pv[2] > pv[i0]) i0 = 2;
        int i1 = -1;
        for (int e = 0; e < 3; e++){ if (e == i0) continue; if (i1 < 0 || pv[e] > pv[i1]) i1 = e; }
        int e3 = 3 - i0 - i1;
        g_sel1[b*3]=pv[0]; g_sel1[b*3+1]=pv[1]; g_sel1[b*3+2]=pv[2];
        g_topidx[b*2]=i0;  g_topidx[b*2+1]=i1;
        g_topval[b*2]=pv[i0]; g_topval[b*2+1]=pv[i1];
        g_tb[b]=pv[i0]+pv[i1];
        g_e3[b]=e3; g_s3[b]=pv[e3];
        sall[b][0]=pv[0]; sall[b][1]=pv[1]; sall[b][2]=pv[2];
        iall[b][0]=i0; iall[b][1]=i1;
    }
    __syncthreads();
    if (tid == 0){
        float sbar[3]={0,0,0}, cnt[3]={0,0,0}; float ent = 0.f;
        for (int b = 0; b < 32; b++){
            for (int e = 0; e < 3; e++){ float sv = sall[b][e]; sbar[e]+=sv; ent -= sv*logf(sv+1e-9f); }
            cnt[iall[b][0]] += 1.f; cnt[iall[b][1]] += 1.f;
        }
        float lb = 0.f;
        for (int e = 0; e < 3; e++) lb += (sbar[e]/32.f)*(cnt[e]/32.f);
        g_lbent = lb + 0.01f*(ent/32.f);
    }
}

// ---------------- 3x3 SAME conv (top-2 experts) -> weighted relu phase sums -
// grid (7, 2, 32); block 448 = 4 co-groups x (8 rows x 14 col-groups)
__global__ void __launch_bounds__(448) k_conv(const float* __restrict__ x,
                                              const float* __restrict__ e1b){
    __shared__ __align__(16) float xs[8][10][58];
    __shared__ __align__(16) float ws[8*9*64];
    __shared__ float pl[1024];
    int rb = blockIdx.x, slot = blockIdx.y, b = blockIdx.z;
    int e = g_topidx[b*2+slot];
    float s = g_topval[b*2+slot];
    int tid = threadIdx.x;
    int cog = tid/112, t = tid%112, tr = t/14, cg = t%14;
    int h0 = rb*8, wc = cg*4;
    for (int i = tid; i < 1024; i += 448) pl[i] = 0.f;
    unsigned long long acc[4][8];
    #pragma unroll
    for (int px=0;px<4;px++)
        #pragma unroll
        for (int p=0;p<8;p++) acc[px][p] = 0ull;
    const float* xb = x + (size_t)b*64*NPIX;
    const float* wb = g_wT + (size_t)e*64*9*64;
    for (int c0 = 0; c0 < 64; c0 += 8){
        __syncthreads();
        for (int i = tid; i < 8*10*58; i += 448){
            int ci = i/580, r = (i/58)%10, col = i%58;
            int h = h0 - 1 + r, gw = col - 1;
            float v = 0.f;
            if (h >= 0 && h < 56 && gw >= 0 && gw < 56)
                v = xb[(size_t)(c0+ci)*NPIX + h*56 + gw];
            xs[ci][r][col] = v;
        }
        for (int i = tid; i < 8*9*64; i += 448)
            ws[i] = wb[(size_t)c0*9*64 + i];
        __syncthreads();
        #pragma unroll 1
        for (int ci = 0; ci < 8; ci++){
            unsigned long long vp[3][6];
            #pragma unroll
            for (int rr=0;rr<3;rr++)
                #pragma unroll
                for (int cc=0;cc<6;cc++){
                    float v = xs[ci][tr+rr][wc+cc];
                    vp[rr][cc] = pack2(v, v);
                }
            #pragma unroll
            for (int p=0;p<8;p++){
                int co2 = cog*16 + 2*p;
                unsigned long long wk[9];
                #pragma unroll
                for (int k=0;k<9;k++)
                    wk[k] = *reinterpret_cast<const unsigned long long*>(&ws[(ci*9+k)*64 + co2]);
                #pragma unroll
                for (int rr=0;rr<3;rr++)
                    #pragma unroll
                    for (int cc=0;cc<3;cc++)
                        #pragma unroll
                        for (int px=0;px<4;px++)
                            fma2(acc[px][p], vp[rr][px+cc], wk[rr*3+cc]);
            }
        }
    }
    int ph = (h0 + tr) & 3;
    #pragma unroll
    for (int p=0;p<8;p++){
        int co = cog*16 + 2*p;
        float b0v = e1b[e*64+co], b1v = e1b[e*64+co+1];
        #pragma unroll
        for (int px=0;px<4;px++){
            float2 y = unpack2(acc[px][p]);
            float v0 = s * fmaxf(0.f, y.x + b0v);
            float v1 = s * fmaxf(0.f, y.y + b1v);
            int bin = ph*4 + px;  // col phase q == px
            atomicAdd(&pl[co*16 + bin], v0);
            atomicAdd(&pl[(co+1)*16 + bin], v1);
        }
    }
    __syncthreads();
    for (int i = tid; i < 1024; i += 448)
        atomicAdd(&g_Pconv[(size_t)b*1024 + i], pl[i]);
}

// ---------------- feat, router2, losses -------------------------------------
__global__ void k_final(const float* __restrict__ r2w, const float* __restrict__ r2b,
                        const float* __restrict__ e1b, float* __restrict__ out,
                        const int* __restrict__ epoch_p){
    __shared__ float fs[5120];
    __shared__ float lg[96];
    __shared__ float sels[96];
    __shared__ float c3s[2048];
    int tid = threadIdx.x;  // 256
    int epoch = epoch_p ? epoch_p[0] : 35;
    for (int i = tid; i < 2048; i += 256){
        int b = i >> 6, c = i & 63;
        c3s[i] = g_s3[b] * fmaxf(0.f, e1b[g_e3[b]*64 + c]);
    }
    __syncthreads();
    for (int i = tid; i < 5120; i += 256){
        int b = i/160, c = i%160;
        float v, sum = 0.f;
        if (c < 64){
            const float* P = &g_Pconv[(b*64+c)*16];
            for (int k=0;k<16;k++) sum += P[k];
            v = sum*(1.f/3136.f) + c3s[b*64+c];
        } else if (c < 128){
            const float* P = &g_S1x[(b*64+(c-64))*16];
            for (int k=0;k<16;k++) sum += P[k];
            v = g_tb[b]*sum*(1.f/3136.f);
        } else {
            const float* P = &g_SM[(b*32+(c-128))*16];
            for (int k=0;k<16;k++) sum += P[k];
            v = sum*(1.f/3136.f);
        }
        fs[i] = v; g_feat[i] = v;
    }
    __syncthreads();
    if (tid < 96){
        int b = tid/3, e = tid%3;
        const float* W = &r2w[e*160*16];
        float acc = 0.f, accC = 0.f;
        float tb = g_tb[b];
        for (int c = 0; c < 64; c++){
            const float* P = &g_Pconv[(b*64+c)*16];
            float wsum = 0.f;
            for (int k=0;k<16;k++){ acc += P[k]*W[c*16+k]; wsum += W[c*16+k]; }
            accC += c3s[b*64+c]*wsum;
        }
        for (int c = 0; c < 64; c++){
            const float* P = &g_S1x[(b*64+c)*16];
            const float* Wc = &W[(64+c)*16];
            for (int k=0;k<16;k++) acc += tb*P[k]*Wc[k];
        }
        for (int c = 0; c < 32; c++){
            const float* P = &g_SM[(b*32+c)*16];
            const float* Wc = &W[(128+c)*16];
            for (int k=0;k<16;k++) acc += P[k]*Wc[k];
        }
        lg[tid] = acc*(1.f/196.f) + accC + r2b[e] + 0.05f*g_noise2[tid];
    }
    __syncthreads();
    if (tid < 32){
        int b = tid;
        if (epoch < 30){
            sels[b*3] = sels[b*3+1] = sels[b*3+2] = 1.f/3.f;
        } else {
            float l0=lg[b*3], l1=lg[b*3+1], l2=lg[b*3+2];
            float m=fmaxf(l0,fmaxf(l1,l2));
            float x0=expf(l0-m), x1=expf(l1-m), x2=expf(l2-m);
            float sm=x0+x1+x2;
            sels[b*3]   = (x0/sm + 0.01f)/1.03f;
            sels[b*3+1] = (x1/sm + 0.01f)/1.03f;
            sels[b*3+2] = (x2/sm + 0.01f)/1.03f;
        }
        g_sel2eff[b*3]=sels[b*3]; g_sel2eff[b*3+1]=sels[b*3+1]; g_sel2eff[b*3+2]=sels[b*3+2];
    }
    __syncthreads();
    if (tid == 0){
        float loss2 = 0.f;
        if (epoch >= 30){
            for (int e=0;e<3;e++){
                float imp=0.f;
                for (int b=0;b<32;b++) imp += sels[b*3+e];
                imp /= 32.f;
                loss2 += imp*imp;
            }
            loss2 *= 3.f;
        }
        out[8192] = g_lbent + loss2;
        out[8192 + 1 + 32*32*NPIX] = loss2;
    }
}

// ---------------- output2 = sel-mixed expert2 GEMM ---------------------------
__global__ void k_out(const float* __restrict__ e2w, const float* __restrict__ e2b,
                      float* __restrict__ out){
    __shared__ float F[160];
    int b = blockIdx.x, a = threadIdx.x;  // 256 threads
    for (int i = a; i < 160; i += 256) F[i] = g_feat[b*160 + i];
    __syncthreads();
    float acc = 0.f;
    for (int e=0;e<3;e++){
        float se = g_sel2eff[b*3+e];
        acc += se * e2b[e*256+a];
        const float* W = &e2w[(size_t)e*160*256 + a];
        for (int c=0;c<160;c++)
            acc += se * F[c] * W[(size_t)c*256];
    }
    out[b*256 + a] = acc;
}

extern "C" void kernel_launch(void* const* d_in, const int* in_sizes, int n_in,
                              void* d_out, int out_size) {
    const float* x    = (const float*)d_in[0];
    const float* mat  = (const float*)d_in[1];
    const float* r1w  = (const float*)d_in[2];
    const float* r1b  = (const float*)d_in[3];
    const float* r2w  = (const float*)d_in[4];
    const float* r2b  = (const float*)d_in[5];
    const float* e1w  = (const float*)d_in[6];
    const float* e1b  = (const float*)d_in[7];
    const float* e2w  = (const float*)d_in[8];
    const float* e2b  = (const float*)d_in[9];
    const int*   ep   = (n_in > 10) ? (const int*)d_in[10] : (const int*)0;
    float* out = (float*)d_out;

    k_wtrans<<<(3*64*9*64 + 255)/256, 256>>>(e1w);
    k_phase<<<dim3(96, 32), 224>>>(x, mat, out + 8193);
    k_router1<<<1, 128>>>(r1w, r1b);
    k_conv<<<dim3(7, 2, 32), 448>>>(x, e1b);
    k_final<<<1, 256>>>(r2w, r2b, e1b, out, ep);
    k_out<<<32, 256>>>(e2w, e2b, out);
}

// round 9
// speedup vs baseline: 2.1481x; 2.1472x over previous
#include <cuda_runtime.h>
#include <cuda_bf16.h>
#include <cstdint>

#define NPIX 3136
#define XR 3364   // 58*58 padded pixels

__device__ __align__(16) __nv_bfloat16 g_xh[32u*XR*64];
__device__ __align__(16) unsigned g_wf[3*9*4*8*128];   // frag-ordered weights
__device__ float g_S1x[32*64*16];
__device__ float g_SM [32*32*16];
__device__ float g_Pconv[32*64*16];
__device__ int   g_topidx[32*2];
__device__ float g_topval[32*2];
__device__ float g_tb[32];
__device__ int   g_e3[32];
__device__ float g_s3[32];
__device__ float g_noise2[96];
__device__ float g_lbent;
__device__ float g_sel2eff[96];
__device__ float g_feat[32*160];

// ---- threefry (jax partitionable) ----
__device__ __forceinline__ unsigned rotl32(unsigned x,int d){ return (x<<d)|(x>>(32-d)); }
__device__ void threefry(unsigned k0,unsigned k1,unsigned c0,unsigned c1,unsigned&o0,unsigned&o1){
    unsigned ks[3]={k0,k1,0x1BD11BDAu^k0^k1};
    unsigned x0=c0+ks[0],x1=c1+ks[1];
    const int ra[4]={13,15,26,6}, rb[4]={17,29,16,24};
    #pragma unroll
    for(int i=0;i<5;i++){
        const int* rr=((i&1)==0)?ra:rb;
        #pragma unroll
        for(int j=0;j<4;j++){ x0+=x1; x1=rotl32(x1,rr[j]); x1^=x0; }
        x0+=ks[(i+1)%3]; x1+=ks[(i+2)%3]+(unsigned)(i+1);
    }
    o0=x0;o1=x1;
}
__device__ __forceinline__ unsigned rbits32(unsigned k0,unsigned k1,unsigned i){
    unsigned a,b; threefry(k0,k1,0u,i,a,b); return a^b;
}
__device__ __forceinline__ float bits2unif(unsigned b){
    return __uint_as_float((b>>9)|0x3F800000u)-1.0f;
}

__device__ __forceinline__ uint32_t s2u(const void* p){
    uint32_t a; asm("{ .reg .u64 t; cvta.to.shared.u64 t, %1; cvt.u32.u64 %0, t; }":"=r"(a):"l"(p)); return a;
}
__device__ __forceinline__ unsigned packbf(float a,float b){
    __nv_bfloat16 x=__float2bfloat16(a), y=__float2bfloat16(b);
    return ((unsigned)__bfloat16_as_ushort(y)<<16)|__bfloat16_as_ushort(x);
}

__global__ void k_zero(){
    size_t i=(size_t)blockIdx.x*256+threadIdx.x;
    if(i<861184u) ((uint4*)g_xh)[i]=make_uint4(0,0,0,0);
}

__global__ void k_xpad(const float* __restrict__ x){
    __shared__ float sx[64][57];
    int h=blockIdx.x, b=blockIdx.y, tid=threadIdx.x;
    for(int i=tid;i<64*56;i+=256){ int ci=i/56,w=i%56; sx[ci][w]=x[((size_t)(b*64+ci))*NPIX+h*56+w]; }
    __syncthreads();
    for(int i=tid;i<56*32;i+=256){
        int px=i>>5, pr=i&31;
        size_t row=(size_t)b*XR+(size_t)(h+1)*58+(px+1);
        ((unsigned*)g_xh)[row*32+pr]=packbf(sx[2*pr][px],sx[2*pr+1][px]);
    }
}

// weights -> exact B-fragment order: [e][s][k][nt][lane]{hi_b0,hi_b1,lo_b0,lo_b1}
__global__ void k_wfrag(const float* __restrict__ e1w){
    int i=blockIdx.x*256+threadIdx.x;
    if(i>=27648) return;
    int lane=i&31, f=i>>5;
    int nt=f&7, k=(f>>3)&3, s=(f>>5)%9, e=f/288;
    int co=nt*8+lane/4, kb=(lane&3)*2;
    unsigned o[4];
    #pragma unroll
    for(int r=0;r<2;r++){
        int ci=k*16+kb+r*8;
        float w0=e1w[((size_t)(e*64+co)*64+ci)*9+s];
        float w1=e1w[((size_t)(e*64+co)*64+ci+1)*9+s];
        __nv_bfloat16 h0=__float2bfloat16(w0), h1=__float2bfloat16(w1);
        float l0=w0-__bfloat162float(h0), l1=w1-__bfloat162float(h1);
        o[r]=((unsigned)__bfloat16_as_ushort(h1)<<16)|__bfloat16_as_ushort(h0);
        o[2+r]=packbf(l0,l1);
    }
    unsigned* dst=&g_wf[f*128+lane*4];
    dst[0]=o[0]; dst[1]=o[1]; dst[2]=o[2]; dst[3]=o[3];
}

__global__ void k_phase(const float* __restrict__ x, const float* __restrict__ matching,
                        float* __restrict__ out_match){
    int c=blockIdx.x, b=blockIdx.y, tid=threadIdx.x;
    int rr=tid/56, w=tid%56;
    bool ism=(c>=64);
    const float* src = ism ? (matching+(size_t)(b*32+(c-64))*NPIX) : (x+(size_t)(b*64+c)*NPIX);
    float* dst = ism ? (out_match+(size_t)(b*32+(c-64))*NPIX) : (float*)0;
    float acc=0.f;
    #pragma unroll
    for(int k=0;k<14;k++){ int idx=(rr+4*k)*56+w; float v=src[idx]; acc+=v; if(ism) dst[idx]=v; }
    __shared__ float part[224];
    part[tid]=acc; __syncthreads();
    if(tid<16){
        int p=tid/4,q=tid%4; float s=0.f;
        #pragma unroll
        for(int t=0;t<14;t++) s+=part[p*56+q+4*t];
        if(!ism){ g_S1x[(b*64+c)*16+tid]=s; g_Pconv[(b*64+c)*16+tid]=0.f; }
        else g_SM[(b*32+(c-64))*16+tid]=s;
    }
}

__global__ void k_router1(const float* __restrict__ r1w, const float* __restrict__ r1b){
    __shared__ unsigned key1[2],key2[2];
    __shared__ float noise1[96], lg[96], sall[32][3];
    __shared__ int iall[32][2];
    int tid=threadIdx.x;
    if(tid==0){
        unsigned a0,b0,a1,b1;
        threefry(0u,42u,0u,0u,a0,b0); threefry(0u,42u,0u,1u,a1,b1);
        key1[0]=a0;key1[1]=b0;key2[0]=a1;key2[1]=b1;
    }
    __syncthreads();
    if(tid<96){ noise1[tid]=bits2unif(rbits32(key1[0],key1[1],(unsigned)tid));
                g_noise2[tid]=bits2unif(rbits32(key2[0],key2[1],(unsigned)tid)); }
    __syncthreads();
    if(tid<96){
        int b=tid/3,e=tid%3;
        const float* S=&g_S1x[b*64*16]; const float* W=&r1w[e*64*16];
        float acc=0.f;
        for(int i=0;i<1024;i++) acc+=S[i]*W[i];
        lg[tid]=acc*(1.0f/196.0f)+r1b[e]+0.05f*noise1[tid];
    }
    __syncthreads();
    if(tid<32){
        int b=tid;
        float l0=lg[b*3],l1=lg[b*3+1],l2=lg[b*3+2];
        float m=fmaxf(l0,fmaxf(l1,l2));
        float x0=expf(l0-m),x1=expf(l1-m),x2=expf(l2-m);
        float s=x0+x1+x2;
        float pv[3]={x0/s,x1/s,x2/s};
        int i0=0; if(pv[1]>pv[i0])i0=1; if(pv[2]>pv[i0])i0=2;
        int i1=-1;
        for(int e=0;e<3;e++){ if(e==i0)continue; if(i1<0||pv[e]>pv[i1])i1=e; }
        int e3=3-i0-i1;
        g_topidx[b*2]=i0; g_topidx[b*2+1]=i1;
        g_topval[b*2]=pv[i0]; g_topval[b*2+1]=pv[i1];
        g_tb[b]=pv[i0]+pv[i1]; g_e3[b]=e3; g_s3[b]=pv[e3];
        sall[b][0]=pv[0];sall[b][1]=pv[1];sall[b][2]=pv[2];
        iall[b][0]=i0; iall[b][1]=i1;
    }
    __syncthreads();
    if(tid==0){
        float sbar[3]={0,0,0},cnt[3]={0,0,0},ent=0.f;
        for(int b=0;b<32;b++){
            for(int e=0;e<3;e++){ float sv=sall[b][e]; sbar[e]+=sv; ent-=sv*logf(sv+1e-9f); }
            cnt[iall[b][0]]+=1.f; cnt[iall[b][1]]+=1.f;
        }
        float lb=0.f;
        for(int e=0;e<3;e++) lb+=(sbar[e]/32.f)*(cnt[e]/32.f);
        g_lbent=lb+0.01f*(ent/32.f);
    }
}

// smem layout (bytes)
#define SM_PL   0        // 4096
#define SM_BIAS 4096     // 256
#define SM_A    4608     // 256 rows * 128B = 32768
#define SM_W    37376    // 36864 u32 = 147456
#define SM_TOT  184832

// ---- mma.sync conv: grid (2 halves, 2 slots, 32 b), 256 threads ----
__global__ void __launch_bounds__(256,1) k_conv_mma(const float* __restrict__ e1b){
    extern __shared__ char smem[];
    uint32_t sb=s2u(smem);
    int tid=threadIdx.x, wid=tid>>5, lane=tid&31;
    int half=blockIdx.x, slot=blockIdx.y, b=blockIdx.z;
    int e=g_topidx[b*2+slot];
    float gate=g_topval[b*2+slot];

    float* plf=(float*)(smem+SM_PL);
    for(int i=tid;i<1024;i+=256) plf[i]=0.f;
    if(tid<64) *(float*)(smem+SM_BIAS+tid*4)=e1b[e*64+tid];
    {
        const uint4* src=(const uint4*)&g_wf[(size_t)e*36864];
        uint4* dst=(uint4*)(smem+SM_W);
        for(int i=tid;i<9216;i+=256) dst[i]=src[i];
    }
    const float* biasS=(const float*)(smem+SM_BIAS);
    const char* xb=(const char*)(g_xh+(size_t)b*XR*64);

    const int offs[9]={-59,-58,-57,-1,0,1,57,58,59};
    int m0=wid*16;
    int lrow=(lane&7)+8*((lane>>3)&1);
    int lcg=(lane>=16)?1:0;
    int prow=lane>>2;

    int t0=half*14, t1=half?27:14;
    for(int t=t0;t<t1;t++){
        int p0=t*128;
        __syncthreads();
        for(int i=tid;i<2048;i+=256){
            int r=i>>3, j=i&7;
            int pp=p0-64+r; pp=min(max(pp,0),XR-1);
            uint4 v=*(const uint4*)(xb+(size_t)pp*128+j*16);
            *(uint4*)(smem+SM_A+r*128+((j^(r&7))*16))=v;
        }
        __syncthreads();

        float c[8][4];
        #pragma unroll
        for(int nt=0;nt<8;nt++){ c[nt][0]=0.f;c[nt][1]=0.f;c[nt][2]=0.f;c[nt][3]=0.f; }

        #pragma unroll 1
        for(int s=0;s<9;s++){
            int R=64+m0+lrow+offs[s];
            uint32_t rowaddr=sb+SM_A+R*128;
            int rx=R&7;
            #pragma unroll
            for(int k=0;k<4;k++){
                int j=k*2+lcg;
                uint32_t aaddr=rowaddr+((j^rx)<<4);
                uint32_t a0,a1,a2,a3;
                asm volatile("ldmatrix.sync.aligned.m8n8.x4.shared.b16 {%0,%1,%2,%3}, [%4];"
                    :"=r"(a0),"=r"(a1),"=r"(a2),"=r"(a3):"r"(aaddr));
                const char* wptr=smem+SM_W+(size_t)(((s*4+k)*8)*128+lane*4)*4;
                #pragma unroll
                for(int nt=0;nt<8;nt++){
                    uint4 wv=*(const uint4*)(wptr+nt*512);
                    asm volatile("mma.sync.aligned.m16n8k16.row.col.f32.bf16.bf16.f32 "
                        "{%0,%1,%2,%3}, {%4,%5,%6,%7}, {%8,%9}, {%0,%1,%2,%3};"
                        :"+f"(c[nt][0]),"+f"(c[nt][1]),"+f"(c[nt][2]),"+f"(c[nt][3])
                        :"r"(a0),"r"(a1),"r"(a2),"r"(a3),"r"(wv.x),"r"(wv.y));
                    asm volatile("mma.sync.aligned.m16n8k16.row.col.f32.bf16.bf16.f32 "
                        "{%0,%1,%2,%3}, {%4,%5,%6,%7}, {%8,%9}, {%0,%1,%2,%3};"
                        :"+f"(c[nt][0]),"+f"(c[nt][1]),"+f"(c[nt][2]),"+f"(c[nt][3])
                        :"r"(a0),"r"(a1),"r"(a2),"r"(a3),"r"(wv.z),"r"(wv.w));
                }
            }
        }
        int px0=p0+m0+prow, px1=px0+8;
        int r0=px0/58, c0_=px0%58, r1=px1/58, c1_=px1%58;
        bool v0=(px0<XR)&&(r0>=1)&&(r0<=56)&&(c0_>=1)&&(c0_<=56);
        bool v1=(px1<XR)&&(r1>=1)&&(r1<=56)&&(c1_>=1)&&(c1_<=56);
        int bin0=((r0-1)&3)*4+((c0_-1)&3);
        int bin1=((r1-1)&3)*4+((c1_-1)&3);
        int cobase=(lane&3)*2;
        #pragma unroll
        for(int nt=0;nt<8;nt++){
            int co=nt*8+cobase;
            float b0v=biasS[co], b1v=biasS[co+1];
            if(v0){
                atomicAdd(&plf[co*16+bin0],     gate*fmaxf(0.f,c[nt][0]+b0v));
                atomicAdd(&plf[(co+1)*16+bin0], gate*fmaxf(0.f,c[nt][1]+b1v));
            }
            if(v1){
                atomicAdd(&plf[co*16+bin1],     gate*fmaxf(0.f,c[nt][2]+b0v));
                atomicAdd(&plf[(co+1)*16+bin1], gate*fmaxf(0.f,c[nt][3]+b1v));
            }
        }
    }
    __syncthreads();
    for(int i=tid;i<1024;i+=256)
        atomicAdd(&g_Pconv[(size_t)b*1024+i],plf[i]);
}

__global__ void k_final(const float* __restrict__ r2w, const float* __restrict__ r2b,
                        const float* __restrict__ e1b, float* __restrict__ out,
                        const int* __restrict__ epoch_p){
    __shared__ float lg[96], sels[96], c3s[2048];
    int tid=threadIdx.x;
    int epoch=epoch_p?epoch_p[0]:35;
    for(int i=tid;i<2048;i+=256){
        int b=i>>6,c=i&63;
        c3s[i]=g_s3[b]*fmaxf(0.f,e1b[g_e3[b]*64+c]);
    }
    __syncthreads();
    for(int i=tid;i<5120;i+=256){
        int b=i/160,c=i%160;
        float v,sum=0.f;
        if(c<64){
            const float* P=&g_Pconv[(b*64+c)*16];
            for(int k=0;k<16;k++) sum+=P[k];
            v=sum*(1.f/3136.f)+c3s[b*64+c];
        }else if(c<128){
            const float* P=&g_S1x[(b*64+(c-64))*16];
            for(int k=0;k<16;k++) sum+=P[k];
            v=g_tb[b]*sum*(1.f/3136.f);
        }else{
            const float* P=&g_SM[(b*32+(c-128))*16];
            for(int k=0;k<16;k++) sum+=P[k];
            v=sum*(1.f/3136.f);
        }
        g_feat[i]=v;
    }
    __syncthreads();
    if(tid<96){
        int b=tid/3,e=tid%3;
        const float* W=&r2w[e*160*16];
        float acc=0.f,accC=0.f,tb=g_tb[b];
        for(int c=0;c<64;c++){
            const float* P=&g_Pconv[(b*64+c)*16];
            float wsum=0.f;
            for(int k=0;k<16;k++){ acc+=P[k]*W[c*16+k]; wsum+=W[c*16+k]; }
            accC+=c3s[b*64+c]*wsum;
        }
        for(int c=0;c<64;c++){
            const float* P=&g_S1x[(b*64+c)*16];
            const float* Wc=&W[(64+c)*16];
            for(int k=0;k<16;k++) acc+=tb*P[k]*Wc[k];
        }
        for(int c=0;c<32;c++){
            const float* P=&g_SM[(b*32+c)*16];
            const float* Wc=&W[(128+c)*16];
            for(int k=0;k<16;k++) acc+=P[k]*Wc[k];
        }
        lg[tid]=acc*(1.f/196.f)+accC+r2b[e]+0.05f*g_noise2[tid];
    }
    __syncthreads();
    if(tid<32){
        int b=tid;
        if(epoch<30){ sels[b*3]=sels[b*3+1]=sels[b*3+2]=1.f/3.f; }
        else{
            float l0=lg[b*3],l1=lg[b*3+1],l2=lg[b*3+2];
            float m=fmaxf(l0,fmaxf(l1,l2));
            float x0=expf(l0-m),x1=expf(l1-m),x2=expf(l2-m);
            float sm=x0+x1+x2;
            sels[b*3]=(x0/sm+0.01f)/1.03f;
            sels[b*3+1]=(x1/sm+0.01f)/1.03f;
            sels[b*3+2]=(x2/sm+0.01f)/1.03f;
        }
        g_sel2eff[b*3]=sels[b*3]; g_sel2eff[b*3+1]=sels[b*3+1]; g_sel2eff[b*3+2]=sels[b*3+2];
    }
    __syncthreads();
    if(tid==0){
        float loss2=0.f;
        if(epoch>=30){
            for(int e=0;e<3;e++){
                float imp=0.f;
                for(int b=0;b<32;b++) imp+=sels[b*3+e];
                imp/=32.f;
                loss2+=imp*imp;
            }
            loss2*=3.f;
        }
        out[8192]=g_lbent+loss2;
        out[8192+1+32*32*NPIX]=loss2;
    }
}

__global__ void k_out(const float* __restrict__ e2w, const float* __restrict__ e2b,
                      float* __restrict__ out){
    __shared__ float F[160];
    int b=blockIdx.x, a=threadIdx.x;
    for(int i=a;i<160;i+=256) F[i]=g_feat[b*160+i];
    __syncthreads();
    float acc=0.f;
    for(int e=0;e<3;e++){
        float se=g_sel2eff[b*3+e];
        acc+=se*e2b[e*256+a];
        const float* W=&e2w[(size_t)e*160*256+a];
        for(int c=0;c<160;c++) acc+=se*F[c]*W[(size_t)c*256];
    }
    out[b*256+a]=acc;
}

extern "C" void kernel_launch(void* const* d_in, const int* in_sizes, int n_in,
                              void* d_out, int out_size) {
    const float* x   =(const float*)d_in[0];
    const float* mat =(const float*)d_in[1];
    const float* r1w =(const float*)d_in[2];
    const float* r1b =(const float*)d_in[3];
    const float* r2w =(const float*)d_in[4];
    const float* r2b =(const float*)d_in[5];
    const float* e1w =(const float*)d_in[6];
    const float* e1b =(const float*)d_in[7];
    const float* e2w =(const float*)d_in[8];
    const float* e2b =(const float*)d_in[9];
    const int*   ep  =(n_in>10)?(const int*)d_in[10]:(const int*)0;
    float* out=(float*)d_out;

    cudaFuncSetAttribute(k_conv_mma, cudaFuncAttributeMaxDynamicSharedMemorySize, SM_TOT);
    k_zero<<<3364,256>>>();
    k_xpad<<<dim3(56,32),256>>>(x);
    k_wfrag<<<108,256>>>(e1w);
    k_phase<<<dim3(96,32),224>>>(x,mat,out+8193);
    k_router1<<<1,128>>>(r1w,r1b);
    k_conv_mma<<<dim3(2,2,32),256,SM_TOT>>>(e1b);
    k_final<<<1,256>>>(r2w,r2b,e1b,out,ep);
    k_out<<<32,256>>>(e2w,e2b,out);
}

// round 10
// speedup vs baseline: 2.1841x; 1.0168x over previous
#include <cuda_runtime.h>
#include <cuda_bf16.h>
#include <cstdint>

#define NPIX 3136
#define XR 3364   // 58*58 padded pixels

__device__ __align__(16) __nv_bfloat16 g_xh[32u*XR*64];
__device__ __align__(16) unsigned g_wf[3*9*4*8*128];   // frag-ordered weights
__device__ float g_S1x[32*64*16];
__device__ float g_SM [32*32*16];
__device__ float g_Pconv[32*64*16];
__device__ int   g_topidx[32*2];
__device__ float g_topval[32*2];
__device__ float g_tb[32];
__device__ int   g_e3[32];
__device__ float g_s3[32];
__device__ float g_noise2[96];
__device__ float g_lbent;
__device__ float g_sel2eff[96];
__device__ float g_feat[32*160];

// ---- threefry (jax partitionable) ----
__device__ __forceinline__ unsigned rotl32(unsigned x,int d){ return (x<<d)|(x>>(32-d)); }
__device__ void threefry(unsigned k0,unsigned k1,unsigned c0,unsigned c1,unsigned&o0,unsigned&o1){
    unsigned ks[3]={k0,k1,0x1BD11BDAu^k0^k1};
    unsigned x0=c0+ks[0],x1=c1+ks[1];
    const int ra[4]={13,15,26,6}, rb[4]={17,29,16,24};
    #pragma unroll
    for(int i=0;i<5;i++){
        const int* rr=((i&1)==0)?ra:rb;
        #pragma unroll
        for(int j=0;j<4;j++){ x0+=x1; x1=rotl32(x1,rr[j]); x1^=x0; }
        x0+=ks[(i+1)%3]; x1+=ks[(i+2)%3]+(unsigned)(i+1);
    }
    o0=x0;o1=x1;
}
__device__ __forceinline__ unsigned rbits32(unsigned k0,unsigned k1,unsigned i){
    unsigned a,b; threefry(k0,k1,0u,i,a,b); return a^b;
}
__device__ __forceinline__ float bits2unif(unsigned b){
    return __uint_as_float((b>>9)|0x3F800000u)-1.0f;
}

__device__ __forceinline__ uint32_t s2u(const void* p){
    uint32_t a; asm("{ .reg .u64 t; cvta.to.shared.u64 t, %1; cvt.u32.u64 %0, t; }":"=r"(a):"l"(p)); return a;
}
__device__ __forceinline__ unsigned packbf(float a,float b){
    __nv_bfloat16 x=__float2bfloat16(a), y=__float2bfloat16(b);
    return ((unsigned)__bfloat16_as_ushort(y)<<16)|__bfloat16_as_ushort(x);
}

__global__ void k_zero(){
    size_t i=(size_t)blockIdx.x*256+threadIdx.x;
    if(i<861184u) ((uint4*)g_xh)[i]=make_uint4(0,0,0,0);
}

__global__ void k_xpad(const float* __restrict__ x){
    __shared__ float sx[64][57];
    int h=blockIdx.x, b=blockIdx.y, tid=threadIdx.x;
    for(int i=tid;i<64*56;i+=256){ int ci=i/56,w=i%56; sx[ci][w]=x[((size_t)(b*64+ci))*NPIX+h*56+w]; }
    __syncthreads();
    for(int i=tid;i<56*32;i+=256){
        int px=i>>5, pr=i&31;
        size_t row=(size_t)b*XR+(size_t)(h+1)*58+(px+1);
        ((unsigned*)g_xh)[row*32+pr]=packbf(sx[2*pr][px],sx[2*pr+1][px]);
    }
}

// weights -> exact B-fragment order: [e][s][k][nt][lane]{hi_b0,hi_b1,lo_b0,lo_b1}
__global__ void k_wfrag(const float* __restrict__ e1w){
    int i=blockIdx.x*256+threadIdx.x;
    if(i>=27648) return;
    int lane=i&31, f=i>>5;
    int nt=f&7, k=(f>>3)&3, s=(f>>5)%9, e=f/288;
    int co=nt*8+lane/4, kb=(lane&3)*2;
    unsigned o[4];
    #pragma unroll
    for(int r=0;r<2;r++){
        int ci=k*16+kb+r*8;
        float w0=e1w[((size_t)(e*64+co)*64+ci)*9+s];
        float w1=e1w[((size_t)(e*64+co)*64+ci+1)*9+s];
        __nv_bfloat16 h0=__float2bfloat16(w0), h1=__float2bfloat16(w1);
        float l0=w0-__bfloat162float(h0), l1=w1-__bfloat162float(h1);
        o[r]=((unsigned)__bfloat16_as_ushort(h1)<<16)|__bfloat16_as_ushort(h0);
        o[2+r]=packbf(l0,l1);
    }
    unsigned* dst=&g_wf[f*128+lane*4];
    dst[0]=o[0]; dst[1]=o[1]; dst[2]=o[2]; dst[3]=o[3];
}

__global__ void k_phase(const float* __restrict__ x, const float* __restrict__ matching,
                        float* __restrict__ out_match){
    int c=blockIdx.x, b=blockIdx.y, tid=threadIdx.x;
    int rr=tid/56, w=tid%56;
    bool ism=(c>=64);
    const float* src = ism ? (matching+(size_t)(b*32+(c-64))*NPIX) : (x+(size_t)(b*64+c)*NPIX);
    float* dst = ism ? (out_match+(size_t)(b*32+(c-64))*NPIX) : (float*)0;
    float acc=0.f;
    #pragma unroll
    for(int k=0;k<14;k++){ int idx=(rr+4*k)*56+w; float v=src[idx]; acc+=v; if(ism) dst[idx]=v; }
    __shared__ float part[224];
    part[tid]=acc; __syncthreads();
    if(tid<16){
        int p=tid/4,q=tid%4; float s=0.f;
        #pragma unroll
        for(int t=0;t<14;t++) s+=part[p*56+q+4*t];
        if(!ism){ g_S1x[(b*64+c)*16+tid]=s; g_Pconv[(b*64+c)*16+tid]=0.f; }
        else g_SM[(b*32+(c-64))*16+tid]=s;
    }
}

__global__ void k_router1(const float* __restrict__ r1w, const float* __restrict__ r1b){
    __shared__ unsigned key1[2],key2[2];
    __shared__ float noise1[96], lg[96], sall[32][3];
    __shared__ int iall[32][2];
    int tid=threadIdx.x;
    if(tid==0){
        unsigned a0,b0,a1,b1;
        threefry(0u,42u,0u,0u,a0,b0); threefry(0u,42u,0u,1u,a1,b1);
        key1[0]=a0;key1[1]=b0;key2[0]=a1;key2[1]=b1;
    }
    __syncthreads();
    if(tid<96){ noise1[tid]=bits2unif(rbits32(key1[0],key1[1],(unsigned)tid));
                g_noise2[tid]=bits2unif(rbits32(key2[0],key2[1],(unsigned)tid)); }
    __syncthreads();
    if(tid<96){
        int b=tid/3,e=tid%3;
        const float* S=&g_S1x[b*64*16]; const float* W=&r1w[e*64*16];
        float acc=0.f;
        for(int i=0;i<1024;i++) acc+=S[i]*W[i];
        lg[tid]=acc*(1.0f/196.0f)+r1b[e]+0.05f*noise1[tid];
    }
    __syncthreads();
    if(tid<32){
        int b=tid;
        float l0=lg[b*3],l1=lg[b*3+1],l2=lg[b*3+2];
        float m=fmaxf(l0,fmaxf(l1,l2));
        float x0=expf(l0-m),x1=expf(l1-m),x2=expf(l2-m);
        float s=x0+x1+x2;
        float pv[3]={x0/s,x1/s,x2/s};
        int i0=0; if(pv[1]>pv[i0])i0=1; if(pv[2]>pv[i0])i0=2;
        int i1=-1;
        for(int e=0;e<3;e++){ if(e==i0)continue; if(i1<0||pv[e]>pv[i1])i1=e; }
        int e3=3-i0-i1;
        g_topidx[b*2]=i0; g_topidx[b*2+1]=i1;
        g_topval[b*2]=pv[i0]; g_topval[b*2+1]=pv[i1];
        g_tb[b]=pv[i0]+pv[i1]; g_e3[b]=e3; g_s3[b]=pv[e3];
        sall[b][0]=pv[0];sall[b][1]=pv[1];sall[b][2]=pv[2];
        iall[b][0]=i0; iall[b][1]=i1;
    }
    __syncthreads();
    if(tid==0){
        float sbar[3]={0,0,0},cnt[3]={0,0,0},ent=0.f;
        for(int b=0;b<32;b++){
            for(int e=0;e<3;e++){ float sv=sall[b][e]; sbar[e]+=sv; ent-=sv*logf(sv+1e-9f); }
            cnt[iall[b][0]]+=1.f; cnt[iall[b][1]]+=1.f;
        }
        float lb=0.f;
        for(int e=0;e<3;e++) lb+=(sbar[e]/32.f)*(cnt[e]/32.f);
        g_lbent=lb+0.01f*(ent/32.f);
    }
}

// smem layout (bytes)
#define SM_PL   0        // 4096
#define SM_BIAS 4096     // 256
#define SM_A    4608     // 384 rows * 128B = 49152
#define SM_W    53760    // 36864 u32 = 147456
#define SM_TOT  201216

// ---- mma.sync conv: grid (2 halves, 2 slots, 32 b), 512 threads, 256-px tiles ----
__global__ void __launch_bounds__(512,1) k_conv_mma(const float* __restrict__ e1b){
    extern __shared__ char smem[];
    uint32_t sb=s2u(smem);
    int tid=threadIdx.x, wid=tid>>5, lane=tid&31;
    int half=blockIdx.x, slot=blockIdx.y, b=blockIdx.z;
    int e=g_topidx[b*2+slot];
    float gate=g_topval[b*2+slot];

    float* plf=(float*)(smem+SM_PL);
    for(int i=tid;i<1024;i+=512) plf[i]=0.f;
    if(tid<64) *(float*)(smem+SM_BIAS+tid*4)=e1b[e*64+tid];
    {
        const uint4* src=(const uint4*)&g_wf[(size_t)e*36864];
        uint4* dst=(uint4*)(smem+SM_W);
        for(int i=tid;i<9216;i+=512) dst[i]=src[i];
    }
    const float* biasS=(const float*)(smem+SM_BIAS);
    const char* xb=(const char*)(g_xh+(size_t)b*XR*64);

    const int offs[9]={-59,-58,-57,-1,0,1,57,58,59};
    int m0=wid*16;                 // 0..240 within 256-px tile
    int lrow=(lane&7)+8*((lane>>3)&1);
    int lcg=(lane>=16)?1:0;
    int prow=lane>>2;

    int t0=half*7, t1=t0+7;
    for(int t=t0;t<t1;t++){
        int p0=t*256;
        __syncthreads();
        // stage A: rows [p0-64, p0+320), swizzled 16B chunks
        for(int i=tid;i<3072;i+=512){
            int r=i>>3, j=i&7;
            int pp=p0-64+r; pp=min(max(pp,0),XR-1);
            uint4 v=*(const uint4*)(xb+(size_t)pp*128+j*16);
            *(uint4*)(smem+SM_A+r*128+((j^(r&7))*16))=v;
        }
        __syncthreads();

        float c[8][4];
        #pragma unroll
        for(int nt=0;nt<8;nt++){ c[nt][0]=0.f;c[nt][1]=0.f;c[nt][2]=0.f;c[nt][3]=0.f; }

        #pragma unroll 1
        for(int s=0;s<9;s++){
            int R=64+m0+lrow+offs[s];
            uint32_t rowaddr=sb+SM_A+R*128;
            int rx=R&7;
            #pragma unroll
            for(int k=0;k<4;k++){
                int j=k*2+lcg;
                uint32_t aaddr=rowaddr+((j^rx)<<4);
                uint32_t a0,a1,a2,a3;
                asm volatile("ldmatrix.sync.aligned.m8n8.x4.shared.b16 {%0,%1,%2,%3}, [%4];"
                    :"=r"(a0),"=r"(a1),"=r"(a2),"=r"(a3):"r"(aaddr));
                const char* wptr=smem+SM_W+(size_t)(((s*4+k)*8)*128+lane*4)*4;
                #pragma unroll
                for(int nt=0;nt<8;nt++){
                    uint4 wv=*(const uint4*)(wptr+nt*512);
                    asm volatile("mma.sync.aligned.m16n8k16.row.col.f32.bf16.bf16.f32 "
                        "{%0,%1,%2,%3}, {%4,%5,%6,%7}, {%8,%9}, {%0,%1,%2,%3};"
                        :"+f"(c[nt][0]),"+f"(c[nt][1]),"+f"(c[nt][2]),"+f"(c[nt][3])
                        :"r"(a0),"r"(a1),"r"(a2),"r"(a3),"r"(wv.x),"r"(wv.y));
                    asm volatile("mma.sync.aligned.m16n8k16.row.col.f32.bf16.bf16.f32 "
                        "{%0,%1,%2,%3}, {%4,%5,%6,%7}, {%8,%9}, {%0,%1,%2,%3};"
                        :"+f"(c[nt][0]),"+f"(c[nt][1]),"+f"(c[nt][2]),"+f"(c[nt][3])
                        :"r"(a0),"r"(a1),"r"(a2),"r"(a3),"r"(wv.z),"r"(wv.w));
                }
            }
        }
        int px0=p0+m0+prow, px1=px0+8;
        int r0=px0/58, c0_=px0%58, r1=px1/58, c1_=px1%58;
        bool v0=(px0<XR)&&(r0>=1)&&(r0<=56)&&(c0_>=1)&&(c0_<=56);
        bool v1=(px1<XR)&&(r1>=1)&&(r1<=56)&&(c1_>=1)&&(c1_<=56);
        int bin0=((r0-1)&3)*4+((c0_-1)&3);
        int bin1=((r1-1)&3)*4+((c1_-1)&3);
        int cobase=(lane&3)*2;
        #pragma unroll
        for(int nt=0;nt<8;nt++){
            int co=nt*8+cobase;
            float b0v=biasS[co], b1v=biasS[co+1];
            if(v0){
                atomicAdd(&plf[co*16+bin0],     gate*fmaxf(0.f,c[nt][0]+b0v));
                atomicAdd(&plf[(co+1)*16+bin0], gate*fmaxf(0.f,c[nt][1]+b1v));
            }
            if(v1){
                atomicAdd(&plf[co*16+bin1],     gate*fmaxf(0.f,c[nt][2]+b0v));
                atomicAdd(&plf[(co+1)*16+bin1], gate*fmaxf(0.f,c[nt][3]+b1v));
            }
        }
    }
    __syncthreads();
    for(int i=tid;i<1024;i+=512)
        atomicAdd(&g_Pconv[(size_t)b*1024+i],plf[i]);
}

__global__ void k_final(const float* __restrict__ r2w, const float* __restrict__ r2b,
                        const float* __restrict__ e1b, float* __restrict__ out,
                        const int* __restrict__ epoch_p){
    __shared__ float lg[96], sels[96], c3s[2048];
    int tid=threadIdx.x;
    int epoch=epoch_p?epoch_p[0]:35;
    for(int i=tid;i<2048;i+=256){
        int b=i>>6,c=i&63;
        c3s[i]=g_s3[b]*fmaxf(0.f,e1b[g_e3[b]*64+c]);
    }
    __syncthreads();
    for(int i=tid;i<5120;i+=256){
        int b=i/160,c=i%160;
        float v,sum=0.f;
        if(c<64){
            const float* P=&g_Pconv[(b*64+c)*16];
            for(int k=0;k<16;k++) sum+=P[k];
            v=sum*(1.f/3136.f)+c3s[b*64+c];
        }else if(c<128){
            const float* P=&g_S1x[(b*64+(c-64))*16];
            for(int k=0;k<16;k++) sum+=P[k];
            v=g_tb[b]*sum*(1.f/3136.f);
        }else{
            const float* P=&g_SM[(b*32+(c-128))*16];
            for(int k=0;k<16;k++) sum+=P[k];
            v=sum*(1.f/3136.f);
        }
        g_feat[i]=v;
    }
    __syncthreads();
    if(tid<96){
        int b=tid/3,e=tid%3;
        const float* W=&r2w[e*160*16];
        float acc=0.f,accC=0.f,tb=g_tb[b];
        for(int c=0;c<64;c++){
            const float* P=&g_Pconv[(b*64+c)*16];
            float wsum=0.f;
            for(int k=0;k<16;k++){ acc+=P[k]*W[c*16+k]; wsum+=W[c*16+k]; }
            accC+=c3s[b*64+c]*wsum;
        }
        for(int c=0;c<64;c++){
            const float* P=&g_S1x[(b*64+c)*16];
            const float* Wc=&W[(64+c)*16];
            for(int k=0;k<16;k++) acc+=tb*P[k]*Wc[k];
        }
        for(int c=0;c<32;c++){
            const float* P=&g_SM[(b*32+c)*16];
            const float* Wc=&W[(128+c)*16];
            for(int k=0;k<16;k++) acc+=P[k]*Wc[k];
        }
        lg[tid]=acc*(1.f/196.f)+accC+r2b[e]+0.05f*g_noise2[tid];
    }
    __syncthreads();
    if(tid<32){
        int b=tid;
        if(epoch<30){ sels[b*3]=sels[b*3+1]=sels[b*3+2]=1.f/3.f; }
        else{
            float l0=lg[b*3],l1=lg[b*3+1],l2=lg[b*3+2];
            float m=fmaxf(l0,fmaxf(l1,l2));
            float x0=expf(l0-m),x1=expf(l1-m),x2=expf(l2-m);
            float sm=x0+x1+x2;
            sels[b*3]=(x0/sm+0.01f)/1.03f;
            sels[b*3+1]=(x1/sm+0.01f)/1.03f;
            sels[b*3+2]=(x2/sm+0.01f)/1.03f;
        }
        g_sel2eff[b*3]=sels[b*3]; g_sel2eff[b*3+1]=sels[b*3+1]; g_sel2eff[b*3+2]=sels[b*3+2];
    }
    __syncthreads();
    if(tid==0){
        float loss2=0.f;
        if(epoch>=30){
            for(int e=0;e<3;e++){
                float imp=0.f;
                for(int b=0;b<32;b++) imp+=sels[b*3+e];
                imp/=32.f;
                loss2+=imp*imp;
            }
            loss2*=3.f;
        }
        out[8192]=g_lbent+loss2;
        out[8192+1+32*32*NPIX]=loss2;
    }
}

__global__ void k_out(const float* __restrict__ e2w, const float* __restrict__ e2b,
                      float* __restrict__ out){
    __shared__ float F[160];
    int b=blockIdx.x, a=threadIdx.x;
    for(int i=a;i<160;i+=256) F[i]=g_feat[b*160+i];
    __syncthreads();
    float acc=0.f;
    for(int e=0;e<3;e++){
        float se=g_sel2eff[b*3+e];
        acc+=se*e2b[e*256+a];
        const float* W=&e2w[(size_t)e*160*256+a];
        for(int c=0;c<160;c++) acc+=se*F[c]*W[(size_t)c*256];
    }
    out[b*256+a]=acc;
}

extern "C" void kernel_launch(void* const* d_in, const int* in_sizes, int n_in,
                              void* d_out, int out_size) {
    const float* x   =(const float*)d_in[0];
    const float* mat =(const float*)d_in[1];
    const float* r1w =(const float*)d_in[2];
    const float* r1b =(const float*)d_in[3];
    const float* r2w =(const float*)d_in[4];
    const float* r2b =(const float*)d_in[5];
    const float* e1w =(const float*)d_in[6];
    const float* e1b =(const float*)d_in[7];
    const float* e2w =(const float*)d_in[8];
    const float* e2b =(const float*)d_in[9];
    const int*   ep  =(n_in>10)?(const int*)d_in[10]:(const int*)0;
    float* out=(float*)d_out;

    cudaFuncSetAttribute(k_conv_mma, cudaFuncAttributeMaxDynamicSharedMemorySize, SM_TOT);
    k_zero<<<3364,256>>>();
    k_xpad<<<dim3(56,32),256>>>(x);
    k_wfrag<<<108,256>>>(e1w);
    k_phase<<<dim3(96,32),224>>>(x,mat,out+8193);
    k_router1<<<1,128>>>(r1w,r1b);
    k_conv_mma<<<dim3(2,2,32),512,SM_TOT>>>(e1b);
    k_final<<<1,256>>>(r2w,r2b,e1b,out,ep);
    k_out<<<32,256>>>(e2w,e2b,out);
}

// round 11
// speedup vs baseline: 2.5526x; 1.1687x over previous
#include <cuda_runtime.h>
#include <cuda_fp16.h>
#include <cstdint>

#define NPIX 3136
#define XR 3364   // 58*58 padded pixels

__device__ __align__(16) __half g_xh[32u*XR*64];
__device__ __align__(16) unsigned g_wf[3*9*4*4*128];   // frag-ordered fp16 weights
__device__ float g_S1x[32*64*16];
__device__ float g_SM [32*32*16];
__device__ float g_Pconv[32*64*16];
__device__ int   g_topidx[32*2];
__device__ float g_topval[32*2];
__device__ float g_tb[32];
__device__ int   g_e3[32];
__device__ float g_s3[32];
__device__ float g_noise2[96];
__device__ float g_lbent;
__device__ float g_sel2eff[96];
__device__ float g_feat[32*160];

// ---- threefry (jax partitionable) ----
__device__ __forceinline__ unsigned rotl32(unsigned x,int d){ return (x<<d)|(x>>(32-d)); }
__device__ void threefry(unsigned k0,unsigned k1,unsigned c0,unsigned c1,unsigned&o0,unsigned&o1){
    unsigned ks[3]={k0,k1,0x1BD11BDAu^k0^k1};
    unsigned x0=c0+ks[0],x1=c1+ks[1];
    const int ra[4]={13,15,26,6}, rb[4]={17,29,16,24};
    #pragma unroll
    for(int i=0;i<5;i++){
        const int* rr=((i&1)==0)?ra:rb;
        #pragma unroll
        for(int j=0;j<4;j++){ x0+=x1; x1=rotl32(x1,rr[j]); x1^=x0; }
        x0+=ks[(i+1)%3]; x1+=ks[(i+2)%3]+(unsigned)(i+1);
    }
    o0=x0;o1=x1;
}
__device__ __forceinline__ unsigned rbits32(unsigned k0,unsigned k1,unsigned i){
    unsigned a,b; threefry(k0,k1,0u,i,a,b); return a^b;
}
__device__ __forceinline__ float bits2unif(unsigned b){
    return __uint_as_float((b>>9)|0x3F800000u)-1.0f;
}

__device__ __forceinline__ uint32_t s2u(const void* p){
    uint32_t a; asm("{ .reg .u64 t; cvta.to.shared.u64 t, %1; cvt.u32.u64 %0, t; }":"=r"(a):"l"(p)); return a;
}
__device__ __forceinline__ unsigned packh(float a,float b){
    __half x=__float2half_rn(a), y=__float2half_rn(b);
    return ((unsigned)__half_as_ushort(y)<<16)|__half_as_ushort(x);
}

__global__ void k_zero(){
    size_t i=(size_t)blockIdx.x*256+threadIdx.x;
    if(i<861184u) ((uint4*)g_xh)[i]=make_uint4(0,0,0,0);
}

__global__ void k_xpad(const float* __restrict__ x){
    __shared__ float sx[64][57];
    int h=blockIdx.x, b=blockIdx.y, tid=threadIdx.x;
    for(int i=tid;i<64*56;i+=256){ int ci=i/56,w=i%56; sx[ci][w]=x[((size_t)(b*64+ci))*NPIX+h*56+w]; }
    __syncthreads();
    for(int i=tid;i<56*32;i+=256){
        int px=i>>5, pr=i&31;
        size_t row=(size_t)b*XR+(size_t)(h+1)*58+(px+1);
        ((unsigned*)g_xh)[row*32+pr]=packh(sx[2*pr][px],sx[2*pr+1][px]);
    }
}

// weights -> fp16 B-fragments: [e][s][k][ntp][lane] {b0_even, b1_even, b0_odd, b1_odd}
__global__ void k_wfrag(const float* __restrict__ e1w){
    int i=blockIdx.x*256+threadIdx.x;
    if(i>=13824) return;
    int lane=i&31, f=i>>5;
    int ntp=f&3, k=(f>>2)&3, s=(f>>4)%9, e=f/144;
    int kb=(lane&3)*2, ci0=k*16+kb;
    int co_e=16*ntp+(lane>>2), co_o=co_e+8;
    unsigned o[4];
    o[0]=packh(e1w[((size_t)(e*64+co_e)*64+ci0)*9+s],   e1w[((size_t)(e*64+co_e)*64+ci0+1)*9+s]);
    o[1]=packh(e1w[((size_t)(e*64+co_e)*64+ci0+8)*9+s], e1w[((size_t)(e*64+co_e)*64+ci0+9)*9+s]);
    o[2]=packh(e1w[((size_t)(e*64+co_o)*64+ci0)*9+s],   e1w[((size_t)(e*64+co_o)*64+ci0+1)*9+s]);
    o[3]=packh(e1w[((size_t)(e*64+co_o)*64+ci0+8)*9+s], e1w[((size_t)(e*64+co_o)*64+ci0+9)*9+s]);
    unsigned* dst=&g_wf[f*128+lane*4];
    dst[0]=o[0]; dst[1]=o[1]; dst[2]=o[2]; dst[3]=o[3];
}

__global__ void k_phase(const float* __restrict__ x, const float* __restrict__ matching,
                        float* __restrict__ out_match){
    int c=blockIdx.x, b=blockIdx.y, tid=threadIdx.x;
    int rr=tid/56, w=tid%56;
    bool ism=(c>=64);
    const float* src = ism ? (matching+(size_t)(b*32+(c-64))*NPIX) : (x+(size_t)(b*64+c)*NPIX);
    float* dst = ism ? (out_match+(size_t)(b*32+(c-64))*NPIX) : (float*)0;
    float acc=0.f;
    #pragma unroll
    for(int k=0;k<14;k++){ int idx=(rr+4*k)*56+w; float v=src[idx]; acc+=v; if(ism) dst[idx]=v; }
    __shared__ float part[224];
    part[tid]=acc; __syncthreads();
    if(tid<16){
        int p=tid/4,q=tid%4; float s=0.f;
        #pragma unroll
        for(int t=0;t<14;t++) s+=part[p*56+q+4*t];
        if(!ism){ g_S1x[(b*64+c)*16+tid]=s; g_Pconv[(b*64+c)*16+tid]=0.f; }
        else g_SM[(b*32+(c-64))*16+tid]=s;
    }
}

__global__ void k_router1(const float* __restrict__ r1w, const float* __restrict__ r1b){
    __shared__ unsigned key1[2],key2[2];
    __shared__ float noise1[96], lg[96], sall[32][3];
    __shared__ int iall[32][2];
    int tid=threadIdx.x;
    if(tid==0){
        unsigned a0,b0,a1,b1;
        threefry(0u,42u,0u,0u,a0,b0); threefry(0u,42u,0u,1u,a1,b1);
        key1[0]=a0;key1[1]=b0;key2[0]=a1;key2[1]=b1;
    }
    __syncthreads();
    if(tid<96){ noise1[tid]=bits2unif(rbits32(key1[0],key1[1],(unsigned)tid));
                g_noise2[tid]=bits2unif(rbits32(key2[0],key2[1],(unsigned)tid)); }
    __syncthreads();
    if(tid<96){
        int b=tid/3,e=tid%3;
        const float* S=&g_S1x[b*64*16]; const float* W=&r1w[e*64*16];
        float acc=0.f;
        for(int i=0;i<1024;i++) acc+=S[i]*W[i];
        lg[tid]=acc*(1.0f/196.0f)+r1b[e]+0.05f*noise1[tid];
    }
    __syncthreads();
    if(tid<32){
        int b=tid;
        float l0=lg[b*3],l1=lg[b*3+1],l2=lg[b*3+2];
        float m=fmaxf(l0,fmaxf(l1,l2));
        float x0=expf(l0-m),x1=expf(l1-m),x2=expf(l2-m);
        float s=x0+x1+x2;
        float pv[3]={x0/s,x1/s,x2/s};
        int i0=0; if(pv[1]>pv[i0])i0=1; if(pv[2]>pv[i0])i0=2;
        int i1=-1;
        for(int e=0;e<3;e++){ if(e==i0)continue; if(i1<0||pv[e]>pv[i1])i1=e; }
        int e3=3-i0-i1;
        g_topidx[b*2]=i0; g_topidx[b*2+1]=i1;
        g_topval[b*2]=pv[i0]; g_topval[b*2+1]=pv[i1];
        g_tb[b]=pv[i0]+pv[i1]; g_e3[b]=e3; g_s3[b]=pv[e3];
        sall[b][0]=pv[0];sall[b][1]=pv[1];sall[b][2]=pv[2];
        iall[b][0]=i0; iall[b][1]=i1;
    }
    __syncthreads();
    if(tid==0){
        float sbar[3]={0,0,0},cnt[3]={0,0,0},ent=0.f;
        for(int b=0;b<32;b++){
            for(int e=0;e<3;e++){ float sv=sall[b][e]; sbar[e]+=sv; ent-=sv*logf(sv+1e-9f); }
            cnt[iall[b][0]]+=1.f; cnt[iall[b][1]]+=1.f;
        }
        float lb=0.f;
        for(int e=0;e<3;e++) lb+=(sbar[e]/32.f)*(cnt[e]/32.f);
        g_lbent=lb+0.01f*(ent/32.f);
    }
}

// smem layout (bytes)
#define SM_PL   0        // 4096
#define SM_BIAS 4096     // 256
#define SM_A    4608     // 384 rows * 128B = 49152
#define SM_W    53760    // 18432 u32 = 73728
#define SM_TOT  127488

// ---- fp16 mma.sync conv: grid (2 halves, 2 slots, 32 b), 512 threads, 256-px tiles ----
__global__ void __launch_bounds__(512,1) k_conv_mma(const float* __restrict__ e1b){
    extern __shared__ char smem[];
    uint32_t sb=s2u(smem);
    int tid=threadIdx.x, wid=tid>>5, lane=tid&31;
    int half=blockIdx.x, slot=blockIdx.y, b=blockIdx.z;
    int e=g_topidx[b*2+slot];
    float gate=g_topval[b*2+slot];

    float* plf=(float*)(smem+SM_PL);
    for(int i=tid;i<1024;i+=512) plf[i]=0.f;
    if(tid<64) *(float*)(smem+SM_BIAS+tid*4)=e1b[e*64+tid];
    {
        const uint4* src=(const uint4*)&g_wf[(size_t)e*18432];
        uint4* dst=(uint4*)(smem+SM_W);
        for(int i=tid;i<4608;i+=512) dst[i]=src[i];
    }
    const float* biasS=(const float*)(smem+SM_BIAS);
    const char* xb=(const char*)(g_xh+(size_t)b*XR*64);

    const int offs[9]={-59,-58,-57,-1,0,1,57,58,59};
    int m0=wid*16;
    int lrow=(lane&7)+8*((lane>>3)&1);
    int lcg=(lane>=16)?1:0;
    int prow=lane>>2;

    int t0=half*7, t1=t0+7;
    for(int t=t0;t<t1;t++){
        int p0=t*256;
        __syncthreads();
        for(int i=tid;i<3072;i+=512){
            int r=i>>3, j=i&7;
            int pp=p0-64+r; pp=min(max(pp,0),XR-1);
            uint4 v=*(const uint4*)(xb+(size_t)pp*128+j*16);
            *(uint4*)(smem+SM_A+r*128+((j^(r&7))*16))=v;
        }
        __syncthreads();

        float c[8][4];
        #pragma unroll
        for(int nt=0;nt<8;nt++){ c[nt][0]=0.f;c[nt][1]=0.f;c[nt][2]=0.f;c[nt][3]=0.f; }

        #pragma unroll 1
        for(int s=0;s<9;s++){
            int R=64+m0+lrow+offs[s];
            uint32_t rowaddr=sb+SM_A+R*128;
            int rx=R&7;
            #pragma unroll
            for(int k=0;k<4;k++){
                int j=k*2+lcg;
                uint32_t aaddr=rowaddr+((j^rx)<<4);
                uint32_t a0,a1,a2,a3;
                asm volatile("ldmatrix.sync.aligned.m8n8.x4.shared.b16 {%0,%1,%2,%3}, [%4];"
                    :"=r"(a0),"=r"(a1),"=r"(a2),"=r"(a3):"r"(aaddr));
                const char* wptr=smem+SM_W+(size_t)(((s*4+k)*4)*128+lane*4)*4;
                #pragma unroll
                for(int ntp=0;ntp<4;ntp++){
                    uint4 wv=*(const uint4*)(wptr+ntp*512);
                    asm volatile("mma.sync.aligned.m16n8k16.row.col.f32.f16.f16.f32 "
                        "{%0,%1,%2,%3}, {%4,%5,%6,%7}, {%8,%9}, {%0,%1,%2,%3};"
                        :"+f"(c[2*ntp][0]),"+f"(c[2*ntp][1]),"+f"(c[2*ntp][2]),"+f"(c[2*ntp][3])
                        :"r"(a0),"r"(a1),"r"(a2),"r"(a3),"r"(wv.x),"r"(wv.y));
                    asm volatile("mma.sync.aligned.m16n8k16.row.col.f32.f16.f16.f32 "
                        "{%0,%1,%2,%3}, {%4,%5,%6,%7}, {%8,%9}, {%0,%1,%2,%3};"
                        :"+f"(c[2*ntp+1][0]),"+f"(c[2*ntp+1][1]),"+f"(c[2*ntp+1][2]),"+f"(c[2*ntp+1][3])
                        :"r"(a0),"r"(a1),"r"(a2),"r"(a3),"r"(wv.z),"r"(wv.w));
                }
            }
        }
        int px0=p0+m0+prow, px1=px0+8;
        int r0=px0/58, c0_=px0%58, r1=px1/58, c1_=px1%58;
        bool v0=(px0<XR)&&(r0>=1)&&(r0<=56)&&(c0_>=1)&&(c0_<=56);
        bool v1=(px1<XR)&&(r1>=1)&&(r1<=56)&&(c1_>=1)&&(c1_<=56);
        int bin0=((r0-1)&3)*4+((c0_-1)&3);
        int bin1=((r1-1)&3)*4+((c1_-1)&3);
        int cobase=(lane&3)*2;
        #pragma unroll
        for(int nt=0;nt<8;nt++){
            int co=nt*8+cobase;
            float b0v=biasS[co], b1v=biasS[co+1];
            if(v0){
                atomicAdd(&plf[co*16+bin0],     gate*fmaxf(0.f,c[nt][0]+b0v));
                atomicAdd(&plf[(co+1)*16+bin0], gate*fmaxf(0.f,c[nt][1]+b1v));
            }
            if(v1){
                atomicAdd(&plf[co*16+bin1],     gate*fmaxf(0.f,c[nt][2]+b0v));
                atomicAdd(&plf[(co+1)*16+bin1], gate*fmaxf(0.f,c[nt][3]+b1v));
            }
        }
    }
    __syncthreads();
    for(int i=tid;i<1024;i+=512)
        atomicAdd(&g_Pconv[(size_t)b*1024+i],plf[i]);
}

__global__ void k_final(const float* __restrict__ r2w, const float* __restrict__ r2b,
                        const float* __restrict__ e1b, float* __restrict__ out,
                        const int* __restrict__ epoch_p){
    __shared__ float lg[96], sels[96], c3s[2048];
    int tid=threadIdx.x;
    int epoch=epoch_p?epoch_p[0]:35;
    for(int i=tid;i<2048;i+=256){
        int b=i>>6,c=i&63;
        c3s[i]=g_s3[b]*fmaxf(0.f,e1b[g_e3[b]*64+c]);
    }
    __syncthreads();
    for(int i=tid;i<5120;i+=256){
        int b=i/160,c=i%160;
        float v,sum=0.f;
        if(c<64){
            const float* P=&g_Pconv[(b*64+c)*16];
            for(int k=0;k<16;k++) sum+=P[k];
            v=sum*(1.f/3136.f)+c3s[b*64+c];
        }else if(c<128){
            const float* P=&g_S1x[(b*64+(c-64))*16];
            for(int k=0;k<16;k++) sum+=P[k];
            v=g_tb[b]*sum*(1.f/3136.f);
        }else{
            const float* P=&g_SM[(b*32+(c-128))*16];
            for(int k=0;k<16;k++) sum+=P[k];
            v=sum*(1.f/3136.f);
        }
        g_feat[i]=v;
    }
    __syncthreads();
    if(tid<96){
        int b=tid/3,e=tid%3;
        const float* W=&r2w[e*160*16];
        float acc=0.f,accC=0.f,tb=g_tb[b];
        for(int c=0;c<64;c++){
            const float* P=&g_Pconv[(b*64+c)*16];
            float wsum=0.f;
            for(int k=0;k<16;k++){ acc+=P[k]*W[c*16+k]; wsum+=W[c*16+k]; }
            accC+=c3s[b*64+c]*wsum;
        }
        for(int c=0;c<64;c++){
            const float* P=&g_S1x[(b*64+c)*16];
            const float* Wc=&W[(64+c)*16];
            for(int k=0;k<16;k++) acc+=tb*P[k]*Wc[k];
        }
        for(int c=0;c<32;c++){
            const float* P=&g_SM[(b*32+c)*16];
            const float* Wc=&W[(128+c)*16];
            for(int k=0;k<16;k++) acc+=P[k]*Wc[k];
        }
        lg[tid]=acc*(1.f/196.f)+accC+r2b[e]+0.05f*g_noise2[tid];
    }
    __syncthreads();
    if(tid<32){
        int b=tid;
        if(epoch<30){ sels[b*3]=sels[b*3+1]=sels[b*3+2]=1.f/3.f; }
        else{
            float l0=lg[b*3],l1=lg[b*3+1],l2=lg[b*3+2];
            float m=fmaxf(l0,fmaxf(l1,l2));
            float x0=expf(l0-m),x1=expf(l1-m),x2=expf(l2-m);
            float sm=x0+x1+x2;
            sels[b*3]=(x0/sm+0.01f)/1.03f;
            sels[b*3+1]=(x1/sm+0.01f)/1.03f;
            sels[b*3+2]=(x2/sm+0.01f)/1.03f;
        }
        g_sel2eff[b*3]=sels[b*3]; g_sel2eff[b*3+1]=sels[b*3+1]; g_sel2eff[b*3+2]=sels[b*3+2];
    }
    __syncthreads();
    if(tid==0){
        float loss2=0.f;
        if(epoch>=30){
            for(int e=0;e<3;e++){
                float imp=0.f;
                for(int b=0;b<32;b++) imp+=sels[b*3+e];
                imp/=32.f;
                loss2+=imp*imp;
            }
            loss2*=3.f;
        }
        out[8192]=g_lbent+loss2;
        out[8192+1+32*32*NPIX]=loss2;
    }
}

__global__ void k_out(const float* __restrict__ e2w, const float* __restrict__ e2b,
                      float* __restrict__ out){
    __shared__ float F[160];
    int b=blockIdx.x, a=threadIdx.x;
    for(int i=a;i<160;i+=256) F[i]=g_feat[b*160+i];
    __syncthreads();
    float acc=0.f;
    for(int e=0;e<3;e++){
        float se=g_sel2eff[b*3+e];
        acc+=se*e2b[e*256+a];
        const float* W=&e2w[(size_t)e*160*256+a];
        for(int c=0;c<160;c++) acc+=se*F[c]*W[(size_t)c*256];
    }
    out[b*256+a]=acc;
}

extern "C" void kernel_launch(void* const* d_in, const int* in_sizes, int n_in,
                              void* d_out, int out_size) {
    const float* x   =(const float*)d_in[0];
    const float* mat =(const float*)d_in[1];
    const float* r1w =(const float*)d_in[2];
    const float* r1b =(const float*)d_in[3];
    const float* r2w =(const float*)d_in[4];
    const float* r2b =(const float*)d_in[5];
    const float* e1w =(const float*)d_in[6];
    const float* e1b =(const float*)d_in[7];
    const float* e2w =(const float*)d_in[8];
    const float* e2b =(const float*)d_in[9];
    const int*   ep  =(n_in>10)?(const int*)d_in[10]:(const int*)0;
    float* out=(float*)d_out;

    cudaFuncSetAttribute(k_conv_mma, cudaFuncAttributeMaxDynamicSharedMemorySize, SM_TOT);
    k_zero<<<3364,256>>>();
    k_xpad<<<dim3(56,32),256>>>(x);
    k_wfrag<<<54,256>>>(e1w);
    k_phase<<<dim3(96,32),224>>>(x,mat,out+8193);
    k_router1<<<1,128>>>(r1w,r1b);
    k_conv_mma<<<dim3(2,2,32),512,SM_TOT>>>(e1b);
    k_final<<<1,256>>>(r2w,r2b,e1b,out,ep);
    k_out<<<32,256>>>(e2w,e2b,out);
}

// round 13
// speedup vs baseline: 2.7231x; 1.0668x over previous
#include <cuda_runtime.h>
#include <cuda_fp16.h>
#include <cstdint>

#define NPIX 3136
#define XR 3364   // 58*58 padded pixels

__device__ __align__(16) __half g_xh[32u*XR*64];
__device__ __align__(16) unsigned g_wf[3*9*4*4*128];   // frag-ordered fp16 weights
__device__ float g_S1x[32*64*16];
__device__ float g_SM [32*32*16];
__device__ float g_Pconv[32*64*16];
__device__ int   g_topidx[32*2];
__device__ float g_topval[32*2];
__device__ float g_tb[32];
__device__ int   g_e3[32];
__device__ float g_s3[32];
__device__ float g_noise2[96];
__device__ float g_lbent;
__device__ float g_sel2eff[96];
__device__ float g_feat[32*160];

// ---- threefry (jax partitionable) ----
__device__ __forceinline__ unsigned rotl32(unsigned x,int d){ return (x<<d)|(x>>(32-d)); }
__device__ void threefry(unsigned k0,unsigned k1,unsigned c0,unsigned c1,unsigned&o0,unsigned&o1){
    unsigned ks[3]={k0,k1,0x1BD11BDAu^k0^k1};
    unsigned x0=c0+ks[0],x1=c1+ks[1];
    const int ra[4]={13,15,26,6}, rb[4]={17,29,16,24};
    #pragma unroll
    for(int i=0;i<5;i++){
        const int* rr=((i&1)==0)?ra:rb;
        #pragma unroll
        for(int j=0;j<4;j++){ x0+=x1; x1=rotl32(x1,rr[j]); x1^=x0; }
        x0+=ks[(i+1)%3]; x1+=ks[(i+2)%3]+(unsigned)(i+1);
    }
    o0=x0;o1=x1;
}
__device__ __forceinline__ unsigned rbits32(unsigned k0,unsigned k1,unsigned i){
    unsigned a,b; threefry(k0,k1,0u,i,a,b); return a^b;
}
__device__ __forceinline__ float bits2unif(unsigned b){
    return __uint_as_float((b>>9)|0x3F800000u)-1.0f;
}

__device__ __forceinline__ uint32_t s2u(const void* p){
    uint32_t a; asm("{ .reg .u64 t; cvta.to.shared.u64 t, %1; cvt.u32.u64 %0, t; }":"=r"(a):"l"(p)); return a;
}
__device__ __forceinline__ unsigned packh(float a,float b){
    __half x=__float2half_rn(a), y=__float2half_rn(b);
    return ((unsigned)__half_as_ushort(y)<<16)|__half_as_ushort(x);
}

__global__ void k_zero(){
    size_t i=(size_t)blockIdx.x*256+threadIdx.x;
    if(i<861184u) ((uint4*)g_xh)[i]=make_uint4(0,0,0,0);
}

__global__ void k_xpad(const float* __restrict__ x){
    __shared__ float sx[64][57];
    int h=blockIdx.x, b=blockIdx.y, tid=threadIdx.x;
    for(int i=tid;i<64*56;i+=256){ int ci=i/56,w=i%56; sx[ci][w]=x[((size_t)(b*64+ci))*NPIX+h*56+w]; }
    __syncthreads();
    for(int i=tid;i<56*32;i+=256){
        int px=i>>5, pr=i&31;
        size_t row=(size_t)b*XR+(size_t)(h+1)*58+(px+1);
        ((unsigned*)g_xh)[row*32+pr]=packh(sx[2*pr][px],sx[2*pr+1][px]);
    }
}

// weights -> fp16 B-fragments: [e][s][k][ntp][lane] {b0_even, b1_even, b0_odd, b1_odd}
__global__ void k_wfrag(const float* __restrict__ e1w){
    int i=blockIdx.x*256+threadIdx.x;
    if(i>=13824) return;
    int lane=i&31, f=i>>5;
    int ntp=f&3, k=(f>>2)&3, s=(f>>4)%9, e=f/144;
    int kb=(lane&3)*2, ci0=k*16+kb;
    int co_e=16*ntp+(lane>>2), co_o=co_e+8;
    unsigned o[4];
    o[0]=packh(e1w[((size_t)(e*64+co_e)*64+ci0)*9+s],   e1w[((size_t)(e*64+co_e)*64+ci0+1)*9+s]);
    o[1]=packh(e1w[((size_t)(e*64+co_e)*64+ci0+8)*9+s], e1w[((size_t)(e*64+co_e)*64+ci0+9)*9+s]);
    o[2]=packh(e1w[((size_t)(e*64+co_o)*64+ci0)*9+s],   e1w[((size_t)(e*64+co_o)*64+ci0+1)*9+s]);
    o[3]=packh(e1w[((size_t)(e*64+co_o)*64+ci0+8)*9+s], e1w[((size_t)(e*64+co_o)*64+ci0+9)*9+s]);
    unsigned* dst=&g_wf[f*128+lane*4];
    dst[0]=o[0]; dst[1]=o[1]; dst[2]=o[2]; dst[3]=o[3];
}

__global__ void k_phase(const float* __restrict__ x, const float* __restrict__ matching,
                        float* __restrict__ out_match){
    int c=blockIdx.x, b=blockIdx.y, tid=threadIdx.x;
    int rr=tid/56, w=tid%56;
    bool ism=(c>=64);
    const float* src = ism ? (matching+(size_t)(b*32+(c-64))*NPIX) : (x+(size_t)(b*64+c)*NPIX);
    float* dst = ism ? (out_match+(size_t)(b*32+(c-64))*NPIX) : (float*)0;
    float acc=0.f;
    #pragma unroll
    for(int k=0;k<14;k++){ int idx=(rr+4*k)*56+w; float v=src[idx]; acc+=v; if(ism) dst[idx]=v; }
    __shared__ float part[224];
    part[tid]=acc; __syncthreads();
    if(tid<16){
        int p=tid/4,q=tid%4; float s=0.f;
        #pragma unroll
        for(int t=0;t<14;t++) s+=part[p*56+q+4*t];
        if(!ism){ g_S1x[(b*64+c)*16+tid]=s; g_Pconv[(b*64+c)*16+tid]=0.f; }
        else g_SM[(b*32+(c-64))*16+tid]=s;
    }
}

__global__ void k_router1(const float* __restrict__ r1w, const float* __restrict__ r1b){
    __shared__ unsigned key1[2],key2[2];
    __shared__ float noise1[96], lg[96], sall[32][3];
    __shared__ int iall[32][2];
    int tid=threadIdx.x;
    if(tid==0){
        unsigned a0,b0,a1,b1;
        threefry(0u,42u,0u,0u,a0,b0); threefry(0u,42u,0u,1u,a1,b1);
        key1[0]=a0;key1[1]=b0;key2[0]=a1;key2[1]=b1;
    }
    __syncthreads();
    if(tid<96){ noise1[tid]=bits2unif(rbits32(key1[0],key1[1],(unsigned)tid));
                g_noise2[tid]=bits2unif(rbits32(key2[0],key2[1],(unsigned)tid)); }
    __syncthreads();
    if(tid<96){
        int b=tid/3,e=tid%3;
        const float* S=&g_S1x[b*64*16]; const float* W=&r1w[e*64*16];
        float acc=0.f;
        for(int i=0;i<1024;i++) acc+=S[i]*W[i];
        lg[tid]=acc*(1.0f/196.0f)+r1b[e]+0.05f*noise1[tid];
    }
    __syncthreads();
    if(tid<32){
        int b=tid;
        float l0=lg[b*3],l1=lg[b*3+1],l2=lg[b*3+2];
        float m=fmaxf(l0,fmaxf(l1,l2));
        float x0=expf(l0-m),x1=expf(l1-m),x2=expf(l2-m);
        float s=x0+x1+x2;
        float pv[3]={x0/s,x1/s,x2/s};
        int i0=0; if(pv[1]>pv[i0])i0=1; if(pv[2]>pv[i0])i0=2;
        int i1=-1;
        for(int e=0;e<3;e++){ if(e==i0)continue; if(i1<0||pv[e]>pv[i1])i1=e; }
        int e3=3-i0-i1;
        g_topidx[b*2]=i0; g_topidx[b*2+1]=i1;
        g_topval[b*2]=pv[i0]; g_topval[b*2+1]=pv[i1];
        g_tb[b]=pv[i0]+pv[i1]; g_e3[b]=e3; g_s3[b]=pv[e3];
        sall[b][0]=pv[0];sall[b][1]=pv[1];sall[b][2]=pv[2];
        iall[b][0]=i0; iall[b][1]=i1;
    }
    __syncthreads();
    if(tid==0){
        float sbar[3]={0,0,0},cnt[3]={0,0,0},ent=0.f;
        for(int b=0;b<32;b++){
            for(int e=0;e<3;e++){ float sv=sall[b][e]; sbar[e]+=sv; ent-=sv*logf(sv+1e-9f); }
            cnt[iall[b][0]]+=1.f; cnt[iall[b][1]]+=1.f;
        }
        float lb=0.f;
        for(int e=0;e<3;e++) lb+=(sbar[e]/32.f)*(cnt[e]/32.f);
        g_lbent=lb+0.01f*(ent/32.f);
    }
}

// smem layout (bytes)
#define SM_PL   0        // 4096
#define SM_BIAS 4096     // 256
#define SM_A    4608     // 384 rows * 128B = 49152
#define SM_W    53760    // 18432 u32 = 73728
#define SM_TOT  127488

// ---- fp16 mma.sync conv: grid (2 halves, 2 slots, 32 b), 512 threads, 256-px tiles ----
__global__ void __launch_bounds__(512,1) k_conv_mma(const float* __restrict__ e1b){
    extern __shared__ char smem[];
    uint32_t sb=s2u(smem);
    int tid=threadIdx.x, wid=tid>>5, lane=tid&31;
    int half=blockIdx.x, slot=blockIdx.y, b=blockIdx.z;
    int e=g_topidx[b*2+slot];
    float gate=g_topval[b*2+slot];

    float* plf=(float*)(smem+SM_PL);
    for(int i=tid;i<1024;i+=512) plf[i]=0.f;
    if(tid<64) *(float*)(smem+SM_BIAS+tid*4)=e1b[e*64+tid];
    {
        const uint4* src=(const uint4*)&g_wf[(size_t)e*18432];
        uint4* dst=(uint4*)(smem+SM_W);
        for(int i=tid;i<4608;i+=512) dst[i]=src[i];
    }
    const float* biasS=(const float*)(smem+SM_BIAS);
    const char* xb=(const char*)(g_xh+(size_t)b*XR*64);

    const int offs[9]={-59,-58,-57,-1,0,1,57,58,59};
    int m0=wid*16;
    int lrow=(lane&7)+8*((lane>>3)&1);
    int lcg=(lane>=16)?1:0;
    int prow=lane>>2;

    int t0=half*7, t1=t0+7;
    for(int t=t0;t<t1;t++){
        int p0=t*256;
        __syncthreads();
        for(int i=tid;i<3072;i+=512){
            int r=i>>3, j=i&7;
            int pp=p0-64+r; pp=min(max(pp,0),XR-1);
            uint4 v=*(const uint4*)(xb+(size_t)pp*128+j*16);
            *(uint4*)(smem+SM_A+r*128+((j^(r&7))*16))=v;
        }
        __syncthreads();

        float c[8][4];
        #pragma unroll
        for(int nt=0;nt<8;nt++){ c[nt][0]=0.f;c[nt][1]=0.f;c[nt][2]=0.f;c[nt][3]=0.f; }

        #pragma unroll 3
        for(int s=0;s<9;s++){
            int R=64+m0+lrow+offs[s];
            uint32_t rowaddr=sb+SM_A+R*128;
            int rx=R&7;
            #pragma unroll
            for(int k=0;k<4;k++){
                int j=k*2+lcg;
                uint32_t aaddr=rowaddr+((j^rx)<<4);
                uint32_t a0,a1,a2,a3;
                asm volatile("ldmatrix.sync.aligned.m8n8.x4.shared.b16 {%0,%1,%2,%3}, [%4];"
                    :"=r"(a0),"=r"(a1),"=r"(a2),"=r"(a3):"r"(aaddr));
                const char* wptr=smem+SM_W+(size_t)(((s*4+k)*4)*128+lane*4)*4;
                #pragma unroll
                for(int ntp=0;ntp<4;ntp++){
                    uint4 wv=*(const uint4*)(wptr+ntp*512);
                    asm volatile("mma.sync.aligned.m16n8k16.row.col.f32.f16.f16.f32 "
                        "{%0,%1,%2,%3}, {%4,%5,%6,%7}, {%8,%9}, {%0,%1,%2,%3};"
                        :"+f"(c[2*ntp][0]),"+f"(c[2*ntp][1]),"+f"(c[2*ntp][2]),"+f"(c[2*ntp][3])
                        :"r"(a0),"r"(a1),"r"(a2),"r"(a3),"r"(wv.x),"r"(wv.y));
                    asm volatile("mma.sync.aligned.m16n8k16.row.col.f32.f16.f16.f32 "
                        "{%0,%1,%2,%3}, {%4,%5,%6,%7}, {%8,%9}, {%0,%1,%2,%3};"
                        :"+f"(c[2*ntp+1][0]),"+f"(c[2*ntp+1][1]),"+f"(c[2*ntp+1][2]),"+f"(c[2*ntp+1][3])
                        :"r"(a0),"r"(a1),"r"(a2),"r"(a3),"r"(wv.z),"r"(wv.w));
                }
            }
        }
        // ---- reduced-atomic epilogue ----
        int px0=p0+m0+prow, px1=px0+8;
        int r0=px0/58, c0_=px0%58, r1=px1/58, c1_=px1%58;
        bool v0=(px0<XR)&&(r0>=1)&&(r0<=56)&&(c0_>=1)&&(c0_<=56);
        bool v1=(px1<XR)&&(r1>=1)&&(r1<=56)&&(c1_>=1)&&(c1_<=56);
        int bin0=((r0-1)&3)*4+((c0_-1)&3);   // always in [0,16)
        int bin1=((r1-1)&3)*4+((c1_-1)&3);
        bool m01=(bin0==bin1);
        int ob0=__shfl_xor_sync(0xFFFFFFFFu,bin0,16);
        int ob1=__shfl_xor_sync(0xFFFFFFFFu,bin1,16);
        bool pair=(ob0==bin0)&&(ob1==bin1);
        int cobase=(lane&3)*2;
        #pragma unroll
        for(int nt=0;nt<8;nt++){
            int co=nt*8+cobase;
            float b0v=biasS[co], b1v=biasS[co+1];
            float x0=v0?gate*fmaxf(0.f,c[nt][0]+b0v):0.f;
            float x1=v0?gate*fmaxf(0.f,c[nt][1]+b1v):0.f;
            float y0=v1?gate*fmaxf(0.f,c[nt][2]+b0v):0.f;
            float y1=v1?gate*fmaxf(0.f,c[nt][3]+b1v):0.f;
            float a0=x0+(m01?y0:0.f), a1=x1+(m01?y1:0.f);
            float e0=m01?0.f:y0,      e1=m01?0.f:y1;
            float pa0=__shfl_xor_sync(0xFFFFFFFFu,a0,16);
            float pa1=__shfl_xor_sync(0xFFFFFFFFu,a1,16);
            float pe0=__shfl_xor_sync(0xFFFFFFFFu,e0,16);
            float pe1=__shfl_xor_sync(0xFFFFFFFFu,e1,16);
            if(pair){ a0+=pa0; a1+=pa1; e0+=pe0; e1+=pe1; }
            if(!pair || lane<16){
                atomicAdd(&plf[co*16+bin0], a0);
                atomicAdd(&plf[(co+1)*16+bin0], a1);
                if(!m01){
                    atomicAdd(&plf[co*16+bin1], e0);
                    atomicAdd(&plf[(co+1)*16+bin1], e1);
                }
            }
        }
    }
    __syncthreads();
    for(int i=tid;i<1024;i+=512)
        atomicAdd(&g_Pconv[(size_t)b*1024+i],plf[i]);
}

__global__ void k_final(const float* __restrict__ r2w, const float* __restrict__ r2b,
                        const float* __restrict__ e1b, float* __restrict__ out,
                        const int* __restrict__ epoch_p){
    __shared__ float lg[96], sels[96], c3s[2048];
    int tid=threadIdx.x;
    int epoch=epoch_p?epoch_p[0]:35;
    for(int i=tid;i<2048;i+=256){
        int b=i>>6,c=i&63;
        c3s[i]=g_s3[b]*fmaxf(0.f,e1b[g_e3[b]*64+c]);
    }
    __syncthreads();
    for(int i=tid;i<5120;i+=256){
        int b=i/160,c=i%160;
        float v,sum=0.f;
        if(c<64){
            const float* P=&g_Pconv[(b*64+c)*16];
            for(int k=0;k<16;k++) sum+=P[k];
            v=sum*(1.f/3136.f)+c3s[b*64+c];
        }else if(c<128){
            const float* P=&g_S1x[(b*64+(c-64))*16];
            for(int k=0;k<16;k++) sum+=P[k];
            v=g_tb[b]*sum*(1.f/3136.f);
        }else{
            const float* P=&g_SM[(b*32+(c-128))*16];
            for(int k=0;k<16;k++) sum+=P[k];
            v=sum*(1.f/3136.f);
        }
        g_feat[i]=v;
    }
    __syncthreads();
    if(tid<96){
        int b=tid/3,e=tid%3;
        const float* W=&r2w[e*160*16];
        float acc=0.f,accC=0.f,tb=g_tb[b];
        for(int c=0;c<64;c++){
            const float* P=&g_Pconv[(b*64+c)*16];
            float wsum=0.f;
            for(int k=0;k<16;k++){ acc+=P[k]*W[c*16+k]; wsum+=W[c*16+k]; }
            accC+=c3s[b*64+c]*wsum;
        }
        for(int c=0;c<64;c++){
            const float* P=&g_S1x[(b*64+c)*16];
            const float* Wc=&W[(64+c)*16];
            for(int k=0;k<16;k++) acc+=tb*P[k]*Wc[k];
        }
        for(int c=0;c<32;c++){
            const float* P=&g_SM[(b*32+c)*16];
            const float* Wc=&W[(128+c)*16];
            for(int k=0;k<16;k++) acc+=P[k]*Wc[k];
        }
        lg[tid]=acc*(1.f/196.f)+accC+r2b[e]+0.05f*g_noise2[tid];
    }
    __syncthreads();
    if(tid<32){
        int b=tid;
        if(epoch<30){ sels[b*3]=sels[b*3+1]=sels[b*3+2]=1.f/3.f; }
        else{
            float l0=lg[b*3],l1=lg[b*3+1],l2=lg[b*3+2];
            float m=fmaxf(l0,fmaxf(l1,l2));
            float x0=expf(l0-m),x1=expf(l1-m),x2=expf(l2-m);
            float sm=x0+x1+x2;
            sels[b*3]=(x0/sm+0.01f)/1.03f;
            sels[b*3+1]=(x1/sm+0.01f)/1.03f;
            sels[b*3+2]=(x2/sm+0.01f)/1.03f;
        }
        g_sel2eff[b*3]=sels[b*3]; g_sel2eff[b*3+1]=sels[b*3+1]; g_sel2eff[b*3+2]=sels[b*3+2];
    }
    __syncthreads();
    if(tid==0){
        float loss2=0.f;
        if(epoch>=30){
            for(int e=0;e<3;e++){
                float imp=0.f;
                for(int b=0;b<32;b++) imp+=sels[b*3+e];
                imp/=32.f;
                loss2+=imp*imp;
            }
            loss2*=3.f;
        }
        out[8192]=g_lbent+loss2;
        out[8192+1+32*32*NPIX]=loss2;
    }
}

__global__ void k_out(const float* __restrict__ e2w, const float* __restrict__ e2b,
                      float* __restrict__ out){
    __shared__ float F[160];
    int b=blockIdx.x, a=threadIdx.x;
    for(int i=a;i<160;i+=256) F[i]=g_feat[b*160+i];
    __syncthreads();
    float acc=0.f;
    for(int e=0;e<3;e++){
        float se=g_sel2eff[b*3+e];
        acc+=se*e2b[e*256+a];
        const float* W=&e2w[(size_t)e*160*256+a];
        for(int c=0;c<160;c++) acc+=se*F[c]*W[(size_t)c*256];
    }
    out[b*256+a]=acc;
}

extern "C" void kernel_launch(void* const* d_in, const int* in_sizes, int n_in,
                              void* d_out, int out_size) {
    const float* x   =(const float*)d_in[0];
    const float* mat =(const float*)d_in[1];
    const float* r1w =(const float*)d_in[2];
    const float* r1b =(const float*)d_in[3];
    const float* r2w =(const float*)d_in[4];
    const float* r2b =(const float*)d_in[5];
    const float* e1w =(const float*)d_in[6];
    const float* e1b =(const float*)d_in[7];
    const float* e2w =(const float*)d_in[8];
    const float* e2b =(const float*)d_in[9];
    const int*   ep  =(n_in>10)?(const int*)d_in[10]:(const int*)0;
    float* out=(float*)d_out;

    cudaFuncSetAttribute(k_conv_mma, cudaFuncAttributeMaxDynamicSharedMemorySize, SM_TOT);
    k_zero<<<3364,256>>>();
    k_xpad<<<dim3(56,32),256>>>(x);
    k_wfrag<<<54,256>>>(e1w);
    k_phase<<<dim3(96,32),224>>>(x,mat,out+8193);
    k_router1<<<1,128>>>(r1w,r1b);
    k_conv_mma<<<dim3(2,2,32),512,SM_TOT>>>(e1b);
    k_final<<<1,256>>>(r2w,r2b,e1b,out,ep);
    k_out<<<32,256>>>(e2w,e2b,out);
}

// round 14
// speedup vs baseline: 2.7492x; 1.0096x over previous
#include <cuda_runtime.h>
#include <cuda_fp16.h>
#include <cstdint>

#define NPIX 3136
#define XR 3364   // 58*58 padded pixels

__device__ __align__(16) __half g_xh[32u*XR*64];
__device__ __align__(16) unsigned g_wf[3*9*4*4*128];   // frag-ordered fp16 weights
__device__ float g_S1x[32*64*16];
__device__ float g_SM [32*32*16];
__device__ float g_Pconv[32*64*16];
__device__ int   g_topidx[32*2];
__device__ float g_topval[32*2];
__device__ float g_tb[32];
__device__ int   g_e3[32];
__device__ float g_s3[32];
__device__ float g_noise2[96];
__device__ float g_lbent;
__device__ float g_sel2eff[96];
__device__ float g_feat[32*160];

// ---- threefry (jax partitionable) ----
__device__ __forceinline__ unsigned rotl32(unsigned x,int d){ return (x<<d)|(x>>(32-d)); }
__device__ void threefry(unsigned k0,unsigned k1,unsigned c0,unsigned c1,unsigned&o0,unsigned&o1){
    unsigned ks[3]={k0,k1,0x1BD11BDAu^k0^k1};
    unsigned x0=c0+ks[0],x1=c1+ks[1];
    const int ra[4]={13,15,26,6}, rb[4]={17,29,16,24};
    #pragma unroll
    for(int i=0;i<5;i++){
        const int* rr=((i&1)==0)?ra:rb;
        #pragma unroll
        for(int j=0;j<4;j++){ x0+=x1; x1=rotl32(x1,rr[j]); x1^=x0; }
        x0+=ks[(i+1)%3]; x1+=ks[(i+2)%3]+(unsigned)(i+1);
    }
    o0=x0;o1=x1;
}
__device__ __forceinline__ unsigned rbits32(unsigned k0,unsigned k1,unsigned i){
    unsigned a,b; threefry(k0,k1,0u,i,a,b); return a^b;
}
__device__ __forceinline__ float bits2unif(unsigned b){
    return __uint_as_float((b>>9)|0x3F800000u)-1.0f;
}

__device__ __forceinline__ uint32_t s2u(const void* p){
    uint32_t a; asm("{ .reg .u64 t; cvta.to.shared.u64 t, %1; cvt.u32.u64 %0, t; }":"=r"(a):"l"(p)); return a;
}
__device__ __forceinline__ unsigned packh(float a,float b){
    __half x=__float2half_rn(a), y=__float2half_rn(b);
    return ((unsigned)__half_as_ushort(y)<<16)|__half_as_ushort(x);
}

// ---- merged prep: pad-image build + border zero + weight fragments ----
// grid (57, 32), 256 threads
__global__ void k_prep(const float* __restrict__ x, const float* __restrict__ e1w){
    __shared__ float sx[64][57];
    int xb=blockIdx.x, b=blockIdx.y, tid=threadIdx.x;
    if(xb<56){
        int h=xb;
        for(int i=tid;i<64*56;i+=256){ int ci=i/56,w=i%56; sx[ci][w]=x[((size_t)(b*64+ci))*NPIX+h*56+w]; }
        __syncthreads();
        for(int i=tid;i<56*32;i+=256){
            int px=i>>5, pr=i&31;
            size_t row=(size_t)b*XR+(size_t)(h+1)*58+(px+1);
            ((unsigned*)g_xh)[row*32+pr]=packh(sx[2*pr][px],sx[2*pr+1][px]);
        }
        // zero col 0 and col 57 of this padded row
        if(tid<64){
            int col=(tid>=32)?57:0, pr=tid&31;
            size_t row=(size_t)b*XR+(size_t)(h+1)*58+col;
            ((unsigned*)g_xh)[row*32+pr]=0u;
        }
    } else {
        // zero padded pixel rows 0 and 57 entirely
        for(int i=tid;i<2*58*32;i+=256){
            int hf=i/(58*32), px=(i/32)%58, pr=i&31;
            size_t row=(size_t)b*XR+(size_t)(hf*57)*58+px;
            ((unsigned*)g_xh)[row*32+pr]=0u;
        }
        // weight fragments: items [b*432, b*432+432)  (32*432 = 13824 total)
        for(int i=b*432+tid;i<b*432+432;i+=256){
            int lane=i&31, f=i>>5;
            int ntp=f&3, k=(f>>2)&3, s=(f>>4)%9, e=f/144;
            int kb=(lane&3)*2, ci0=k*16+kb;
            int co_e=16*ntp+(lane>>2), co_o=co_e+8;
            unsigned o0=packh(e1w[((size_t)(e*64+co_e)*64+ci0)*9+s],   e1w[((size_t)(e*64+co_e)*64+ci0+1)*9+s]);
            unsigned o1=packh(e1w[((size_t)(e*64+co_e)*64+ci0+8)*9+s], e1w[((size_t)(e*64+co_e)*64+ci0+9)*9+s]);
            unsigned o2=packh(e1w[((size_t)(e*64+co_o)*64+ci0)*9+s],   e1w[((size_t)(e*64+co_o)*64+ci0+1)*9+s]);
            unsigned o3=packh(e1w[((size_t)(e*64+co_o)*64+ci0+8)*9+s], e1w[((size_t)(e*64+co_o)*64+ci0+9)*9+s]);
            unsigned* dst=&g_wf[f*128+lane*4];
            dst[0]=o0; dst[1]=o1; dst[2]=o2; dst[3]=o3;
        }
    }
}

__global__ void k_phase(const float* __restrict__ x, const float* __restrict__ matching,
                        float* __restrict__ out_match){
    int c=blockIdx.x, b=blockIdx.y, tid=threadIdx.x;
    int rr=tid/56, w=tid%56;
    bool ism=(c>=64);
    const float* src = ism ? (matching+(size_t)(b*32+(c-64))*NPIX) : (x+(size_t)(b*64+c)*NPIX);
    float* dst = ism ? (out_match+(size_t)(b*32+(c-64))*NPIX) : (float*)0;
    float acc=0.f;
    #pragma unroll
    for(int k=0;k<14;k++){ int idx=(rr+4*k)*56+w; float v=src[idx]; acc+=v; if(ism) dst[idx]=v; }
    __shared__ float part[224];
    part[tid]=acc; __syncthreads();
    if(tid<16){
        int p=tid/4,q=tid%4; float s=0.f;
        #pragma unroll
        for(int t=0;t<14;t++) s+=part[p*56+q+4*t];
        if(!ism){ g_S1x[(b*64+c)*16+tid]=s; g_Pconv[(b*64+c)*16+tid]=0.f; }
        else g_SM[(b*32+(c-64))*16+tid]=s;
    }
}

__global__ void k_router1(const float* __restrict__ r1w, const float* __restrict__ r1b){
    __shared__ unsigned key1[2],key2[2];
    __shared__ float noise1[96], lg[96], sall[32][3];
    __shared__ int iall[32][2];
    int tid=threadIdx.x;
    if(tid==0){
        unsigned a0,b0,a1,b1;
        threefry(0u,42u,0u,0u,a0,b0); threefry(0u,42u,0u,1u,a1,b1);
        key1[0]=a0;key1[1]=b0;key2[0]=a1;key2[1]=b1;
    }
    __syncthreads();
    if(tid<96){ noise1[tid]=bits2unif(rbits32(key1[0],key1[1],(unsigned)tid));
                g_noise2[tid]=bits2unif(rbits32(key2[0],key2[1],(unsigned)tid)); }
    __syncthreads();
    if(tid<96){
        int b=tid/3,e=tid%3;
        const float* S=&g_S1x[b*64*16]; const float* W=&r1w[e*64*16];
        float acc=0.f;
        for(int i=0;i<1024;i++) acc+=S[i]*W[i];
        lg[tid]=acc*(1.0f/196.0f)+r1b[e]+0.05f*noise1[tid];
    }
    __syncthreads();
    if(tid<32){
        int b=tid;
        float l0=lg[b*3],l1=lg[b*3+1],l2=lg[b*3+2];
        float m=fmaxf(l0,fmaxf(l1,l2));
        float x0=expf(l0-m),x1=expf(l1-m),x2=expf(l2-m);
        float s=x0+x1+x2;
        float pv[3]={x0/s,x1/s,x2/s};
        int i0=0; if(pv[1]>pv[i0])i0=1; if(pv[2]>pv[i0])i0=2;
        int i1=-1;
        for(int e=0;e<3;e++){ if(e==i0)continue; if(i1<0||pv[e]>pv[i1])i1=e; }
        int e3=3-i0-i1;
        g_topidx[b*2]=i0; g_topidx[b*2+1]=i1;
        g_topval[b*2]=pv[i0]; g_topval[b*2+1]=pv[i1];
        g_tb[b]=pv[i0]+pv[i1]; g_e3[b]=e3; g_s3[b]=pv[e3];
        sall[b][0]=pv[0];sall[b][1]=pv[1];sall[b][2]=pv[2];
        iall[b][0]=i0; iall[b][1]=i1;
    }
    __syncthreads();
    if(tid==0){
        float sbar[3]={0,0,0},cnt[3]={0,0,0},ent=0.f;
        for(int b=0;b<32;b++){
            for(int e=0;e<3;e++){ float sv=sall[b][e]; sbar[e]+=sv; ent-=sv*logf(sv+1e-9f); }
            cnt[iall[b][0]]+=1.f; cnt[iall[b][1]]+=1.f;
        }
        float lb=0.f;
        for(int e=0;e<3;e++) lb+=(sbar[e]/32.f)*(cnt[e]/32.f);
        g_lbent=lb+0.01f*(ent/32.f);
    }
}

// smem layout (bytes)
#define SM_PL   0        // 4096
#define SM_BIAS 4096     // 256
#define SM_A    4608     // 384 rows * 128B = 49152
#define SM_W    53760    // 18432 u32 = 73728
#define SM_TOT  127488

// ---- fp16 mma.sync conv: grid (2 halves, 2 slots, 32 b), 512 threads, 256-px tiles ----
__global__ void __launch_bounds__(512,1) k_conv_mma(const float* __restrict__ e1b){
    extern __shared__ char smem[];
    uint32_t sb=s2u(smem);
    int tid=threadIdx.x, wid=tid>>5, lane=tid&31;
    int half=blockIdx.x, slot=blockIdx.y, b=blockIdx.z;
    int e=g_topidx[b*2+slot];
    float gate=g_topval[b*2+slot];

    float* plf=(float*)(smem+SM_PL);
    for(int i=tid;i<1024;i+=512) plf[i]=0.f;
    if(tid<64) *(float*)(smem+SM_BIAS+tid*4)=e1b[e*64+tid];
    {
        const uint4* src=(const uint4*)&g_wf[(size_t)e*18432];
        uint4* dst=(uint4*)(smem+SM_W);
        for(int i=tid;i<4608;i+=512) dst[i]=src[i];
    }
    const float* biasS=(const float*)(smem+SM_BIAS);
    const char* xb=(const char*)(g_xh+(size_t)b*XR*64);

    const int offs[9]={-59,-58,-57,-1,0,1,57,58,59};
    int m0=wid*16;
    int lrow=(lane&7)+8*((lane>>3)&1);
    int lcg=(lane>=16)?1:0;
    int prow=lane>>2;

    int t0=half*7, t1=t0+7;
    for(int t=t0;t<t1;t++){
        int p0=t*256;
        __syncthreads();
        for(int i=tid;i<3072;i+=512){
            int r=i>>3, j=i&7;
            int pp=p0-64+r; pp=min(max(pp,0),XR-1);
            uint4 v=*(const uint4*)(xb+(size_t)pp*128+j*16);
            *(uint4*)(smem+SM_A+r*128+((j^(r&7))*16))=v;
        }
        __syncthreads();

        float c[8][4];
        #pragma unroll
        for(int nt=0;nt<8;nt++){ c[nt][0]=0.f;c[nt][1]=0.f;c[nt][2]=0.f;c[nt][3]=0.f; }

        #pragma unroll 3
        for(int s=0;s<9;s++){
            int R=64+m0+lrow+offs[s];
            uint32_t rowaddr=sb+SM_A+R*128;
            int rx=R&7;
            #pragma unroll
            for(int k=0;k<4;k++){
                int j=k*2+lcg;
                uint32_t aaddr=rowaddr+((j^rx)<<4);
                uint32_t a0,a1,a2,a3;
                asm volatile("ldmatrix.sync.aligned.m8n8.x4.shared.b16 {%0,%1,%2,%3}, [%4];"
                    :"=r"(a0),"=r"(a1),"=r"(a2),"=r"(a3):"r"(aaddr));
                const char* wptr=smem+SM_W+(size_t)(((s*4+k)*4)*128+lane*4)*4;
                #pragma unroll
                for(int ntp=0;ntp<4;ntp++){
                    uint4 wv=*(const uint4*)(wptr+ntp*512);
                    asm volatile("mma.sync.aligned.m16n8k16.row.col.f32.f16.f16.f32 "
                        "{%0,%1,%2,%3}, {%4,%5,%6,%7}, {%8,%9}, {%0,%1,%2,%3};"
                        :"+f"(c[2*ntp][0]),"+f"(c[2*ntp][1]),"+f"(c[2*ntp][2]),"+f"(c[2*ntp][3])
                        :"r"(a0),"r"(a1),"r"(a2),"r"(a3),"r"(wv.x),"r"(wv.y));
                    asm volatile("mma.sync.aligned.m16n8k16.row.col.f32.f16.f16.f32 "
                        "{%0,%1,%2,%3}, {%4,%5,%6,%7}, {%8,%9}, {%0,%1,%2,%3};"
                        :"+f"(c[2*ntp+1][0]),"+f"(c[2*ntp+1][1]),"+f"(c[2*ntp+1][2]),"+f"(c[2*ntp+1][3])
                        :"r"(a0),"r"(a1),"r"(a2),"r"(a3),"r"(wv.z),"r"(wv.w));
                }
            }
        }
        // ---- reduced-atomic epilogue ----
        int px0=p0+m0+prow, px1=px0+8;
        int r0=px0/58, c0_=px0%58, r1=px1/58, c1_=px1%58;
        bool v0=(px0<XR)&&(r0>=1)&&(r0<=56)&&(c0_>=1)&&(c0_<=56);
        bool v1=(px1<XR)&&(r1>=1)&&(r1<=56)&&(c1_>=1)&&(c1_<=56);
        int bin0=((r0-1)&3)*4+((c0_-1)&3);
        int bin1=((r1-1)&3)*4+((c1_-1)&3);
        bool m01=(bin0==bin1);
        int ob0=__shfl_xor_sync(0xFFFFFFFFu,bin0,16);
        int ob1=__shfl_xor_sync(0xFFFFFFFFu,bin1,16);
        bool pair=(ob0==bin0)&&(ob1==bin1);
        int cobase=(lane&3)*2;
        #pragma unroll
        for(int nt=0;nt<8;nt++){
            int co=nt*8+cobase;
            float b0v=biasS[co], b1v=biasS[co+1];
            float x0=v0?gate*fmaxf(0.f,c[nt][0]+b0v):0.f;
            float x1=v0?gate*fmaxf(0.f,c[nt][1]+b1v):0.f;
            float y0=v1?gate*fmaxf(0.f,c[nt][2]+b0v):0.f;
            float y1=v1?gate*fmaxf(0.f,c[nt][3]+b1v):0.f;
            float a0=x0+(m01?y0:0.f), a1=x1+(m01?y1:0.f);
            float e0=m01?0.f:y0,      e1=m01?0.f:y1;
            float pa0=__shfl_xor_sync(0xFFFFFFFFu,a0,16);
            float pa1=__shfl_xor_sync(0xFFFFFFFFu,a1,16);
            float pe0=__shfl_xor_sync(0xFFFFFFFFu,e0,16);
            float pe1=__shfl_xor_sync(0xFFFFFFFFu,e1,16);
            if(pair){ a0+=pa0; a1+=pa1; e0+=pe0; e1+=pe1; }
            if(!pair || lane<16){
                atomicAdd(&plf[co*16+bin0], a0);
                atomicAdd(&plf[(co+1)*16+bin0], a1);
                if(!m01){
                    atomicAdd(&plf[co*16+bin1], e0);
                    atomicAdd(&plf[(co+1)*16+bin1], e1);
                }
            }
        }
    }
    __syncthreads();
    for(int i=tid;i<1024;i+=512)
        atomicAdd(&g_Pconv[(size_t)b*1024+i],plf[i]);
}

__global__ void k_final(const float* __restrict__ r2w, const float* __restrict__ r2b,
                        const float* __restrict__ e1b, float* __restrict__ out,
                        const int* __restrict__ epoch_p){
    __shared__ float lg[96], sels[96], c3s[2048];
    int tid=threadIdx.x;
    int epoch=epoch_p?epoch_p[0]:35;
    for(int i=tid;i<2048;i+=256){
        int b=i>>6,c=i&63;
        c3s[i]=g_s3[b]*fmaxf(0.f,e1b[g_e3[b]*64+c]);
    }
    __syncthreads();
    for(int i=tid;i<5120;i+=256){
        int b=i/160,c=i%160;
        float v,sum=0.f;
        if(c<64){
            const float* P=&g_Pconv[(b*64+c)*16];
            for(int k=0;k<16;k++) sum+=P[k];
            v=sum*(1.f/3136.f)+c3s[b*64+c];
        }else if(c<128){
            const float* P=&g_S1x[(b*64+(c-64))*16];
            for(int k=0;k<16;k++) sum+=P[k];
            v=g_tb[b]*sum*(1.f/3136.f);
        }else{
            const float* P=&g_SM[(b*32+(c-128))*16];
            for(int k=0;k<16;k++) sum+=P[k];
            v=sum*(1.f/3136.f);
        }
        g_feat[i]=v;
    }
    __syncthreads();
    if(tid<96){
        int b=tid/3,e=tid%3;
        const float* W=&r2w[e*160*16];
        float acc=0.f,accC=0.f,tb=g_tb[b];
        for(int c=0;c<64;c++){
            const float* P=&g_Pconv[(b*64+c)*16];
            float wsum=0.f;
            for(int k=0;k<16;k++){ acc+=P[k]*W[c*16+k]; wsum+=W[c*16+k]; }
            accC+=c3s[b*64+c]*wsum;
        }
        for(int c=0;c<64;c++){
            const float* P=&g_S1x[(b*64+c)*16];
            const float* Wc=&W[(64+c)*16];
            for(int k=0;k<16;k++) acc+=tb*P[k]*Wc[k];
        }
        for(int c=0;c<32;c++){
            const float* P=&g_SM[(b*32+c)*16];
            const float* Wc=&W[(128+c)*16];
            for(int k=0;k<16;k++) acc+=P[k]*Wc[k];
        }
        lg[tid]=acc*(1.f/196.f)+accC+r2b[e]+0.05f*g_noise2[tid];
    }
    __syncthreads();
    if(tid<32){
        int b=tid;
        if(epoch<30){ sels[b*3]=sels[b*3+1]=sels[b*3+2]=1.f/3.f; }
        else{
            float l0=lg[b*3],l1=lg[b*3+1],l2=lg[b*3+2];
            float m=fmaxf(l0,fmaxf(l1,l2));
            float x0=expf(l0-m),x1=expf(l1-m),x2=expf(l2-m);
            float sm=x0+x1+x2;
            sels[b*3]=(x0/sm+0.01f)/1.03f;
            sels[b*3+1]=(x1/sm+0.01f)/1.03f;
            sels[b*3+2]=(x2/sm+0.01f)/1.03f;
        }
        g_sel2eff[b*3]=sels[b*3]; g_sel2eff[b*3+1]=sels[b*3+1]; g_sel2eff[b*3+2]=sels[b*3+2];
    }
    __syncthreads();
    if(tid==0){
        float loss2=0.f;
        if(epoch>=30){
            for(int e=0;e<3;e++){
                float imp=0.f;
                for(int b=0;b<32;b++) imp+=sels[b*3+e];
                imp/=32.f;
                loss2+=imp*imp;
            }
            loss2*=3.f;
        }
        out[8192]=g_lbent+loss2;
        out[8192+1+32*32*NPIX]=loss2;
    }
}

__global__ void k_out(const float* __restrict__ e2w, const float* __restrict__ e2b,
                      float* __restrict__ out){
    __shared__ float F[160];
    int b=blockIdx.x, a=threadIdx.x;
    for(int i=a;i<160;i+=256) F[i]=g_feat[b*160+i];
    __syncthreads();
    float acc=0.f;
    for(int e=0;e<3;e++){
        float se=g_sel2eff[b*3+e];
        acc+=se*e2b[e*256+a];
        const float* W=&e2w[(size_t)e*160*256+a];
        for(int c=0;c<160;c++) acc+=se*F[c]*W[(size_t)c*256];
    }
    out[b*256+a]=acc;
}

extern "C" void kernel_launch(void* const* d_in, const int* in_sizes, int n_in,
                              void* d_out, int out_size) {
    const float* x   =(const float*)d_in[0];
    const float* mat =(const float*)d_in[1];
    const float* r1w =(const float*)d_in[2];
    const float* r1b =(const float*)d_in[3];
    const float* r2w =(const float*)d_in[4];
    const float* r2b =(const float*)d_in[5];
    const float* e1w =(const float*)d_in[6];
    const float* e1b =(const float*)d_in[7];
    const float* e2w =(const float*)d_in[8];
    const float* e2b =(const float*)d_in[9];
    const int*   ep  =(n_in>10)?(const int*)d_in[10]:(const int*)0;
    float* out=(float*)d_out;

    cudaFuncSetAttribute(k_conv_mma, cudaFuncAttributeMaxDynamicSharedMemorySize, SM_TOT);
    k_prep<<<dim3(57,32),256>>>(x,e1w);
    k_phase<<<dim3(96,32),224>>>(x,mat,out+8193);
    k_router1<<<1,128>>>(r1w,r1b);
    k_conv_mma<<<dim3(2,2,32),512,SM_TOT>>>(e1b);
    k_final<<<1,256>>>(r2w,r2b,e1b,out,ep);
    k_out<<<32,256>>>(e2w,e2b,out);
}

// round 15
// speedup vs baseline: 5.3786x; 1.9564x over previous
#include <cuda_runtime.h>
#include <cuda_fp16.h>
#include <cstdint>

#define NPIX 3136
#define XR 3364   // 58*58 padded pixels

__device__ __align__(16) __half g_xh[32u*XR*64];
__device__ __align__(16) unsigned g_wf[3*9*4*4*128];   // frag-ordered fp16 weights
__device__ float g_S1x[32*64*16];
__device__ float g_SM [32*32*16];
__device__ float g_Pconv[32*64*16];
__device__ float g_lg1[96];
__device__ float g_lg2[96];
__device__ int   g_topidx[32*2];
__device__ float g_topval[32*2];
__device__ float g_tb[32];
__device__ int   g_e3[32];
__device__ float g_s3[32];
__device__ float g_noise2[96];
__device__ float g_lbent;
__device__ float g_sel2eff[96];
__device__ float g_feat[32*160];

// ---- threefry (jax partitionable) ----
__device__ __forceinline__ unsigned rotl32(unsigned x,int d){ return (x<<d)|(x>>(32-d)); }
__device__ void threefry(unsigned k0,unsigned k1,unsigned c0,unsigned c1,unsigned&o0,unsigned&o1){
    unsigned ks[3]={k0,k1,0x1BD11BDAu^k0^k1};
    unsigned x0=c0+ks[0],x1=c1+ks[1];
    const int ra[4]={13,15,26,6}, rb[4]={17,29,16,24};
    #pragma unroll
    for(int i=0;i<5;i++){
        const int* rr=((i&1)==0)?ra:rb;
        #pragma unroll
        for(int j=0;j<4;j++){ x0+=x1; x1=rotl32(x1,rr[j]); x1^=x0; }
        x0+=ks[(i+1)%3]; x1+=ks[(i+2)%3]+(unsigned)(i+1);
    }
    o0=x0;o1=x1;
}
__device__ __forceinline__ unsigned rbits32(unsigned k0,unsigned k1,unsigned i){
    unsigned a,b; threefry(k0,k1,0u,i,a,b); return a^b;
}
__device__ __forceinline__ float bits2unif(unsigned b){
    return __uint_as_float((b>>9)|0x3F800000u)-1.0f;
}

__device__ __forceinline__ uint32_t s2u(const void* p){
    uint32_t a; asm("{ .reg .u64 t; cvta.to.shared.u64 t, %1; cvt.u32.u64 %0, t; }":"=r"(a):"l"(p)); return a;
}
__device__ __forceinline__ unsigned packh(float a,float b){
    __half x=__float2half_rn(a), y=__float2half_rn(b);
    return ((unsigned)__half_as_ushort(y)<<16)|__half_as_ushort(x);
}

// ---- merged prep: pad-image build + border zero + weight fragments ----
__global__ void k_prep(const float* __restrict__ x, const float* __restrict__ e1w){
    __shared__ float sx[64][57];
    int xb=blockIdx.x, b=blockIdx.y, tid=threadIdx.x;
    if(xb<56){
        int h=xb;
        for(int i=tid;i<64*56;i+=256){ int ci=i/56,w=i%56; sx[ci][w]=x[((size_t)(b*64+ci))*NPIX+h*56+w]; }
        __syncthreads();
        for(int i=tid;i<56*32;i+=256){
            int px=i>>5, pr=i&31;
            size_t row=(size_t)b*XR+(size_t)(h+1)*58+(px+1);
            ((unsigned*)g_xh)[row*32+pr]=packh(sx[2*pr][px],sx[2*pr+1][px]);
        }
        if(tid<64){
            int col=(tid>=32)?57:0, pr=tid&31;
            size_t row=(size_t)b*XR+(size_t)(h+1)*58+col;
            ((unsigned*)g_xh)[row*32+pr]=0u;
        }
    } else {
        for(int i=tid;i<2*58*32;i+=256){
            int hf=i/(58*32), px=(i/32)%58, pr=i&31;
            size_t row=(size_t)b*XR+(size_t)(hf*57)*58+px;
            ((unsigned*)g_xh)[row*32+pr]=0u;
        }
        for(int i=b*432+tid;i<b*432+432;i+=256){
            int lane=i&31, f=i>>5;
            int ntp=f&3, k=(f>>2)&3, s=(f>>4)%9, e=f/144;
            int kb=(lane&3)*2, ci0=k*16+kb;
            int co_e=16*ntp+(lane>>2), co_o=co_e+8;
            unsigned o0=packh(e1w[((size_t)(e*64+co_e)*64+ci0)*9+s],   e1w[((size_t)(e*64+co_e)*64+ci0+1)*9+s]);
            unsigned o1=packh(e1w[((size_t)(e*64+co_e)*64+ci0+8)*9+s], e1w[((size_t)(e*64+co_e)*64+ci0+9)*9+s]);
            unsigned o2=packh(e1w[((size_t)(e*64+co_o)*64+ci0)*9+s],   e1w[((size_t)(e*64+co_o)*64+ci0+1)*9+s]);
            unsigned o3=packh(e1w[((size_t)(e*64+co_o)*64+ci0+8)*9+s], e1w[((size_t)(e*64+co_o)*64+ci0+9)*9+s]);
            unsigned* dst=&g_wf[f*128+lane*4];
            dst[0]=o0; dst[1]=o1; dst[2]=o2; dst[3]=o3;
        }
    }
}

__global__ void k_phase(const float* __restrict__ x, const float* __restrict__ matching,
                        float* __restrict__ out_match){
    int c=blockIdx.x, b=blockIdx.y, tid=threadIdx.x;
    int rr=tid/56, w=tid%56;
    bool ism=(c>=64);
    const float* src = ism ? (matching+(size_t)(b*32+(c-64))*NPIX) : (x+(size_t)(b*64+c)*NPIX);
    float* dst = ism ? (out_match+(size_t)(b*32+(c-64))*NPIX) : (float*)0;
    float acc=0.f;
    #pragma unroll
    for(int k=0;k<14;k++){ int idx=(rr+4*k)*56+w; float v=src[idx]; acc+=v; if(ism) dst[idx]=v; }
    __shared__ float part[224];
    part[tid]=acc; __syncthreads();
    if(tid<16){
        int p=tid/4,q=tid%4; float s=0.f;
        #pragma unroll
        for(int t=0;t<14;t++) s+=part[p*56+q+4*t];
        if(!ism){ g_S1x[(b*64+c)*16+tid]=s; g_Pconv[(b*64+c)*16+tid]=0.f; }
        else g_SM[(b*32+(c-64))*16+tid]=s;
    }
}

// ---- router1 logit dots: grid (3,32) x 256 ----
__global__ void k_dot1(const float* __restrict__ r1w, const float* __restrict__ r1b){
    __shared__ float red[256];
    int e=blockIdx.x, b=blockIdx.y, tid=threadIdx.x;
    const float* S=&g_S1x[b*1024];
    const float* W=&r1w[e*1024];
    float acc=0.f;
    for(int i=tid;i<1024;i+=256) acc+=S[i]*W[i];
    red[tid]=acc; __syncthreads();
    for(int s=128;s>0;s>>=1){ if(tid<s) red[tid]+=red[tid+s]; __syncthreads(); }
    if(tid==0) g_lg1[b*3+e]=red[0]*(1.0f/196.0f)+r1b[e];
}

// ---- router1 finisher: noise + softmax + top2 + layer1 losses ----
__global__ void k_top(){
    __shared__ unsigned key1[2],key2[2];
    __shared__ float noise1[96], lg[96], sall[32][3];
    __shared__ int iall[32][2];
    int tid=threadIdx.x;   // 128
    if(tid==0){
        unsigned a0,b0,a1,b1;
        threefry(0u,42u,0u,0u,a0,b0); threefry(0u,42u,0u,1u,a1,b1);
        key1[0]=a0;key1[1]=b0;key2[0]=a1;key2[1]=b1;
    }
    __syncthreads();
    if(tid<96){ noise1[tid]=bits2unif(rbits32(key1[0],key1[1],(unsigned)tid));
                g_noise2[tid]=bits2unif(rbits32(key2[0],key2[1],(unsigned)tid));
                lg[tid]=g_lg1[tid]+0.05f*noise1[tid]; }
    __syncthreads();
    if(tid<32){
        int b=tid;
        float l0=lg[b*3],l1=lg[b*3+1],l2=lg[b*3+2];
        float m=fmaxf(l0,fmaxf(l1,l2));
        float x0=expf(l0-m),x1=expf(l1-m),x2=expf(l2-m);
        float s=x0+x1+x2;
        float pv[3]={x0/s,x1/s,x2/s};
        int i0=0; if(pv[1]>pv[i0])i0=1; if(pv[2]>pv[i0])i0=2;
        int i1=-1;
        for(int e=0;e<3;e++){ if(e==i0)continue; if(i1<0||pv[e]>pv[i1])i1=e; }
        int e3=3-i0-i1;
        g_topidx[b*2]=i0; g_topidx[b*2+1]=i1;
        g_topval[b*2]=pv[i0]; g_topval[b*2+1]=pv[i1];
        g_tb[b]=pv[i0]+pv[i1]; g_e3[b]=e3; g_s3[b]=pv[e3];
        sall[b][0]=pv[0];sall[b][1]=pv[1];sall[b][2]=pv[2];
        iall[b][0]=i0; iall[b][1]=i1;
    }
    __syncthreads();
    if(tid==0){
        float sbar[3]={0,0,0},cnt[3]={0,0,0},ent=0.f;
        for(int b=0;b<32;b++){
            for(int e=0;e<3;e++){ float sv=sall[b][e]; sbar[e]+=sv; ent-=sv*logf(sv+1e-9f); }
            cnt[iall[b][0]]+=1.f; cnt[iall[b][1]]+=1.f;
        }
        float lb=0.f;
        for(int e=0;e<3;e++) lb+=(sbar[e]/32.f)*(cnt[e]/32.f);
        g_lbent=lb+0.01f*(ent/32.f);
    }
}

// smem layout (bytes)
#define SM_PL   0        // 4096
#define SM_BIAS 4096     // 256
#define SM_A    4608     // 384 rows * 128B = 49152
#define SM_W    53760    // 18432 u32 = 73728
#define SM_TOT  127488

// ---- fp16 mma.sync conv: grid (2 halves, 2 slots, 32 b), 512 threads, 256-px tiles ----
__global__ void __launch_bounds__(512,1) k_conv_mma(const float* __restrict__ e1b){
    extern __shared__ char smem[];
    uint32_t sb=s2u(smem);
    int tid=threadIdx.x, wid=tid>>5, lane=tid&31;
    int half=blockIdx.x, slot=blockIdx.y, b=blockIdx.z;
    int e=g_topidx[b*2+slot];
    float gate=g_topval[b*2+slot];

    float* plf=(float*)(smem+SM_PL);
    for(int i=tid;i<1024;i+=512) plf[i]=0.f;
    if(tid<64) *(float*)(smem+SM_BIAS+tid*4)=e1b[e*64+tid];
    {
        const uint4* src=(const uint4*)&g_wf[(size_t)e*18432];
        uint4* dst=(uint4*)(smem+SM_W);
        for(int i=tid;i<4608;i+=512) dst[i]=src[i];
    }
    const float* biasS=(const float*)(smem+SM_BIAS);
    const char* xb=(const char*)(g_xh+(size_t)b*XR*64);

    const int offs[9]={-59,-58,-57,-1,0,1,57,58,59};
    int m0=wid*16;
    int lrow=(lane&7)+8*((lane>>3)&1);
    int lcg=(lane>=16)?1:0;
    int prow=lane>>2;

    int t0=half*7, t1=t0+7;
    for(int t=t0;t<t1;t++){
        int p0=t*256;
        __syncthreads();
        for(int i=tid;i<3072;i+=512){
            int r=i>>3, j=i&7;
            int pp=p0-64+r; pp=min(max(pp,0),XR-1);
            uint4 v=*(const uint4*)(xb+(size_t)pp*128+j*16);
            *(uint4*)(smem+SM_A+r*128+((j^(r&7))*16))=v;
        }
        __syncthreads();

        float c[8][4];
        #pragma unroll
        for(int nt=0;nt<8;nt++){ c[nt][0]=0.f;c[nt][1]=0.f;c[nt][2]=0.f;c[nt][3]=0.f; }

        #pragma unroll 3
        for(int s=0;s<9;s++){
            int R=64+m0+lrow+offs[s];
            uint32_t rowaddr=sb+SM_A+R*128;
            int rx=R&7;
            #pragma unroll
            for(int k=0;k<4;k++){
                int j=k*2+lcg;
                uint32_t aaddr=rowaddr+((j^rx)<<4);
                uint32_t a0,a1,a2,a3;
                asm volatile("ldmatrix.sync.aligned.m8n8.x4.shared.b16 {%0,%1,%2,%3}, [%4];"
                    :"=r"(a0),"=r"(a1),"=r"(a2),"=r"(a3):"r"(aaddr));
                const char* wptr=smem+SM_W+(size_t)(((s*4+k)*4)*128+lane*4)*4;
                #pragma unroll
                for(int ntp=0;ntp<4;ntp++){
                    uint4 wv=*(const uint4*)(wptr+ntp*512);
                    asm volatile("mma.sync.aligned.m16n8k16.row.col.f32.f16.f16.f32 "
                        "{%0,%1,%2,%3}, {%4,%5,%6,%7}, {%8,%9}, {%0,%1,%2,%3};"
                        :"+f"(c[2*ntp][0]),"+f"(c[2*ntp][1]),"+f"(c[2*ntp][2]),"+f"(c[2*ntp][3])
                        :"r"(a0),"r"(a1),"r"(a2),"r"(a3),"r"(wv.x),"r"(wv.y));
                    asm volatile("mma.sync.aligned.m16n8k16.row.col.f32.f16.f16.f32 "
                        "{%0,%1,%2,%3}, {%4,%5,%6,%7}, {%8,%9}, {%0,%1,%2,%3};"
                        :"+f"(c[2*ntp+1][0]),"+f"(c[2*ntp+1][1]),"+f"(c[2*ntp+1][2]),"+f"(c[2*ntp+1][3])
                        :"r"(a0),"r"(a1),"r"(a2),"r"(a3),"r"(wv.z),"r"(wv.w));
                }
            }
        }
        int px0=p0+m0+prow, px1=px0+8;
        int r0=px0/58, c0_=px0%58, r1=px1/58, c1_=px1%58;
        bool v0=(px0<XR)&&(r0>=1)&&(r0<=56)&&(c0_>=1)&&(c0_<=56);
        bool v1=(px1<XR)&&(r1>=1)&&(r1<=56)&&(c1_>=1)&&(c1_<=56);
        int bin0=((r0-1)&3)*4+((c0_-1)&3);
        int bin1=((r1-1)&3)*4+((c1_-1)&3);
        bool m01=(bin0==bin1);
        int ob0=__shfl_xor_sync(0xFFFFFFFFu,bin0,16);
        int ob1=__shfl_xor_sync(0xFFFFFFFFu,bin1,16);
        bool pair=(ob0==bin0)&&(ob1==bin1);
        int cobase=(lane&3)*2;
        #pragma unroll
        for(int nt=0;nt<8;nt++){
            int co=nt*8+cobase;
            float b0v=biasS[co], b1v=biasS[co+1];
            float x0=v0?gate*fmaxf(0.f,c[nt][0]+b0v):0.f;
            float x1=v0?gate*fmaxf(0.f,c[nt][1]+b1v):0.f;
            float y0=v1?gate*fmaxf(0.f,c[nt][2]+b0v):0.f;
            float y1=v1?gate*fmaxf(0.f,c[nt][3]+b1v):0.f;
            float a0=x0+(m01?y0:0.f), a1=x1+(m01?y1:0.f);
            float e0=m01?0.f:y0,      e1=m01?0.f:y1;
            float pa0=__shfl_xor_sync(0xFFFFFFFFu,a0,16);
            float pa1=__shfl_xor_sync(0xFFFFFFFFu,a1,16);
            float pe0=__shfl_xor_sync(0xFFFFFFFFu,e0,16);
            float pe1=__shfl_xor_sync(0xFFFFFFFFu,e1,16);
            if(pair){ a0+=pa0; a1+=pa1; e0+=pe0; e1+=pe1; }
            if(!pair || lane<16){
                atomicAdd(&plf[co*16+bin0], a0);
                atomicAdd(&plf[(co+1)*16+bin0], a1);
                if(!m01){
                    atomicAdd(&plf[co*16+bin1], e0);
                    atomicAdd(&plf[(co+1)*16+bin1], e1);
                }
            }
        }
    }
    __syncthreads();
    for(int i=tid;i<1024;i+=512)
        atomicAdd(&g_Pconv[(size_t)b*1024+i],plf[i]);
}

// ---- feature vector: grid 32 x 160 threads ----
__global__ void k_feat(const float* __restrict__ e1b){
    int b=blockIdx.x, c=threadIdx.x;
    float sum=0.f,v;
    if(c<64){
        const float* P=&g_Pconv[(b*64+c)*16];
        for(int k=0;k<16;k++) sum+=P[k];
        float c3=g_s3[b]*fmaxf(0.f,e1b[g_e3[b]*64+c]);
        v=sum*(1.f/3136.f)+c3;
    }else if(c<128){
        const float* P=&g_S1x[(b*64+(c-64))*16];
        for(int k=0;k<16;k++) sum+=P[k];
        v=g_tb[b]*sum*(1.f/3136.f);
    }else{
        const float* P=&g_SM[(b*32+(c-128))*16];
        for(int k=0;k<16;k++) sum+=P[k];
        v=sum*(1.f/3136.f);
    }
    g_feat[b*160+c]=v;
}

// ---- router2 logit dots: grid (3,32) x 256 ----
__global__ void k_dot2(const float* __restrict__ r2w, const float* __restrict__ r2b,
                       const float* __restrict__ e1b){
    __shared__ float red1[256], red2[256];
    int e=blockIdx.x, b=blockIdx.y, tid=threadIdx.x;
    float tb=g_tb[b]; int e3=g_e3[b]; float s3=g_s3[b];
    const float* W=&r2w[(size_t)e*2560];
    float a1=0.f,a2=0.f;
    for(int i=tid;i<2560;i+=256){
        int c=i>>4,k=i&15;
        float w=W[i], P;
        if(c<64){
            P=g_Pconv[(b*64+c)*16+k];
            a2+=s3*fmaxf(0.f,e1b[e3*64+c])*w;
        }else if(c<128){
            P=tb*g_S1x[(b*64+(c-64))*16+k];
        }else{
            P=g_SM[(b*32+(c-128))*16+k];
        }
        a1+=P*w;
    }
    red1[tid]=a1; red2[tid]=a2; __syncthreads();
    for(int s=128;s>0;s>>=1){ if(tid<s){red1[tid]+=red1[tid+s];red2[tid]+=red2[tid+s];} __syncthreads(); }
    if(tid==0) g_lg2[b*3+e]=red1[0]*(1.f/196.f)+red2[0]+r2b[e];
}

// ---- router2 finisher: softmax + losses + scalar outputs ----
__global__ void k_fin(float* __restrict__ out, const int* __restrict__ epoch_p){
    __shared__ float sels[96];
    int tid=threadIdx.x;  // 64
    int epoch=epoch_p?epoch_p[0]:35;
    if(tid<32){
        int b=tid;
        if(epoch<30){ sels[b*3]=sels[b*3+1]=sels[b*3+2]=1.f/3.f; }
        else{
            float l0=g_lg2[b*3]+0.05f*g_noise2[b*3];
            float l1=g_lg2[b*3+1]+0.05f*g_noise2[b*3+1];
            float l2=g_lg2[b*3+2]+0.05f*g_noise2[b*3+2];
            float m=fmaxf(l0,fmaxf(l1,l2));
            float x0=expf(l0-m),x1=expf(l1-m),x2=expf(l2-m);
            float sm=x0+x1+x2;
            sels[b*3]=(x0/sm+0.01f)/1.03f;
            sels[b*3+1]=(x1/sm+0.01f)/1.03f;
            sels[b*3+2]=(x2/sm+0.01f)/1.03f;
        }
        g_sel2eff[b*3]=sels[b*3]; g_sel2eff[b*3+1]=sels[b*3+1]; g_sel2eff[b*3+2]=sels[b*3+2];
    }
    __syncthreads();
    if(tid==0){
        float loss2=0.f;
        if(epoch>=30){
            for(int e=0;e<3;e++){
                float imp=0.f;
                for(int b=0;b<32;b++) imp+=sels[b*3+e];
                imp/=32.f;
                loss2+=imp*imp;
            }
            loss2*=3.f;
        }
        out[8192]=g_lbent+loss2;
        out[8192+1+32*32*NPIX]=loss2;
    }
}

__global__ void k_out(const float* __restrict__ e2w, const float* __restrict__ e2b,
                      float* __restrict__ out){
    __shared__ float F[160];
    int b=blockIdx.x, a=threadIdx.x;
    for(int i=a;i<160;i+=256) F[i]=g_feat[b*160+i];
    __syncthreads();
    float acc=0.f;
    for(int e=0;e<3;e++){
        float se=g_sel2eff[b*3+e];
        acc+=se*e2b[e*256+a];
        const float* W=&e2w[(size_t)e*160*256+a];
        for(int c=0;c<160;c++) acc+=se*F[c]*W[(size_t)c*256];
    }
    out[b*256+a]=acc;
}

extern "C" void kernel_launch(void* const* d_in, const int* in_sizes, int n_in,
                              void* d_out, int out_size) {
    const float* x   =(const float*)d_in[0];
    const float* mat =(const float*)d_in[1];
    const float* r1w =(const float*)d_in[2];
    const float* r1b =(const float*)d_in[3];
    const float* r2w =(const float*)d_in[4];
    const float* r2b =(const float*)d_in[5];
    const float* e1w =(const float*)d_in[6];
    const float* e1b =(const float*)d_in[7];
    const float* e2w =(const float*)d_in[8];
    const float* e2b =(const float*)d_in[9];
    const int*   ep  =(n_in>10)?(const int*)d_in[10]:(const int*)0;
    float* out=(float*)d_out;

    cudaFuncSetAttribute(k_conv_mma, cudaFuncAttributeMaxDynamicSharedMemorySize, SM_TOT);
    k_prep<<<dim3(57,32),256>>>(x,e1w);
    k_phase<<<dim3(96,32),224>>>(x,mat,out+8193);
    k_dot1<<<dim3(3,32),256>>>(r1w,r1b);
    k_top<<<1,128>>>();
    k_conv_mma<<<dim3(2,2,32),512,SM_TOT>>>(e1b);
    k_feat<<<32,160>>>(e1b);
    k_dot2<<<dim3(3,32),256>>>(r2w,r2b,e1b);
    k_fin<<<1,64>>>(out,ep);
    k_out<<<32,256>>>(e2w,e2b,out);
}

// round 16
// speedup vs baseline: 5.4591x; 1.0150x over previous
#include <cuda_runtime.h>
#include <cuda_fp16.h>
#include <cstdint>

#define NPIX 3136
#define XR 3364   // 58*58 padded pixels

__device__ __align__(16) __half g_xh[32u*XR*64];
__device__ __align__(16) unsigned g_wf[3*9*4*4*128];   // frag-ordered fp16 weights
__device__ float g_S1x[32*64*16];
__device__ float g_SM [32*32*16];
__device__ float g_Pconv[32*64*16];
__device__ float g_lg2[96];
__device__ int   g_topidx[32*2];
__device__ float g_topval[32*2];
__device__ float g_tb[32];
__device__ int   g_e3[32];
__device__ float g_s3[32];
__device__ float g_noise2[96];
__device__ float g_lbent;
__device__ float g_sel2eff[96];
__device__ float g_feat[32*160];

// ---- threefry (jax partitionable) ----
__device__ __forceinline__ unsigned rotl32(unsigned x,int d){ return (x<<d)|(x>>(32-d)); }
__device__ void threefry(unsigned k0,unsigned k1,unsigned c0,unsigned c1,unsigned&o0,unsigned&o1){
    unsigned ks[3]={k0,k1,0x1BD11BDAu^k0^k1};
    unsigned x0=c0+ks[0],x1=c1+ks[1];
    const int ra[4]={13,15,26,6}, rb[4]={17,29,16,24};
    #pragma unroll
    for(int i=0;i<5;i++){
        const int* rr=((i&1)==0)?ra:rb;
        #pragma unroll
        for(int j=0;j<4;j++){ x0+=x1; x1=rotl32(x1,rr[j]); x1^=x0; }
        x0+=ks[(i+1)%3]; x1+=ks[(i+2)%3]+(unsigned)(i+1);
    }
    o0=x0;o1=x1;
}
__device__ __forceinline__ unsigned rbits32(unsigned k0,unsigned k1,unsigned i){
    unsigned a,b; threefry(k0,k1,0u,i,a,b); return a^b;
}
__device__ __forceinline__ float bits2unif(unsigned b){
    return __uint_as_float((b>>9)|0x3F800000u)-1.0f;
}

__device__ __forceinline__ uint32_t s2u(const void* p){
    uint32_t a; asm("{ .reg .u64 t; cvta.to.shared.u64 t, %1; cvt.u32.u64 %0, t; }":"=r"(a):"l"(p)); return a;
}
__device__ __forceinline__ unsigned packh(float a,float b){
    __half x=__float2half_rn(a), y=__float2half_rn(b);
    return ((unsigned)__half_as_ushort(y)<<16)|__half_as_ushort(x);
}

// ---- merged prep: pad-image build + border zero + weight fragments ----
__global__ void k_prep(const float* __restrict__ x, const float* __restrict__ e1w){
    __shared__ float sx[64][57];
    int xb=blockIdx.x, b=blockIdx.y, tid=threadIdx.x;
    if(xb<56){
        int h=xb;
        for(int i=tid;i<64*56;i+=256){ int ci=i/56,w=i%56; sx[ci][w]=x[((size_t)(b*64+ci))*NPIX+h*56+w]; }
        __syncthreads();
        for(int i=tid;i<56*32;i+=256){
            int px=i>>5, pr=i&31;
            size_t row=(size_t)b*XR+(size_t)(h+1)*58+(px+1);
            ((unsigned*)g_xh)[row*32+pr]=packh(sx[2*pr][px],sx[2*pr+1][px]);
        }
        if(tid<64){
            int col=(tid>=32)?57:0, pr=tid&31;
            size_t row=(size_t)b*XR+(size_t)(h+1)*58+col;
            ((unsigned*)g_xh)[row*32+pr]=0u;
        }
    } else {
        for(int i=tid;i<2*58*32;i+=256){
            int hf=i/(58*32), px=(i/32)%58, pr=i&31;
            size_t row=(size_t)b*XR+(size_t)(hf*57)*58+px;
            ((unsigned*)g_xh)[row*32+pr]=0u;
        }
        for(int i=b*432+tid;i<b*432+432;i+=256){
            int lane=i&31, f=i>>5;
            int ntp=f&3, k=(f>>2)&3, s=(f>>4)%9, e=f/144;
            int kb=(lane&3)*2, ci0=k*16+kb;
            int co_e=16*ntp+(lane>>2), co_o=co_e+8;
            unsigned o0=packh(e1w[((size_t)(e*64+co_e)*64+ci0)*9+s],   e1w[((size_t)(e*64+co_e)*64+ci0+1)*9+s]);
            unsigned o1=packh(e1w[((size_t)(e*64+co_e)*64+ci0+8)*9+s], e1w[((size_t)(e*64+co_e)*64+ci0+9)*9+s]);
            unsigned o2=packh(e1w[((size_t)(e*64+co_o)*64+ci0)*9+s],   e1w[((size_t)(e*64+co_o)*64+ci0+1)*9+s]);
            unsigned o3=packh(e1w[((size_t)(e*64+co_o)*64+ci0+8)*9+s], e1w[((size_t)(e*64+co_o)*64+ci0+9)*9+s]);
            unsigned* dst=&g_wf[f*128+lane*4];
            dst[0]=o0; dst[1]=o1; dst[2]=o2; dst[3]=o3;
        }
    }
}

__global__ void k_phase(const float* __restrict__ x, const float* __restrict__ matching,
                        float* __restrict__ out_match){
    int c=blockIdx.x, b=blockIdx.y, tid=threadIdx.x;
    int rr=tid/56, w=tid%56;
    bool ism=(c>=64);
    const float* src = ism ? (matching+(size_t)(b*32+(c-64))*NPIX) : (x+(size_t)(b*64+c)*NPIX);
    float* dst = ism ? (out_match+(size_t)(b*32+(c-64))*NPIX) : (float*)0;
    float acc=0.f;
    #pragma unroll
    for(int k=0;k<14;k++){ int idx=(rr+4*k)*56+w; float v=src[idx]; acc+=v; if(ism) dst[idx]=v; }
    __shared__ float part[224];
    part[tid]=acc; __syncthreads();
    if(tid<16){
        int p=tid/4,q=tid%4; float s=0.f;
        #pragma unroll
        for(int t=0;t<14;t++) s+=part[p*56+q+4*t];
        if(!ism){ g_S1x[(b*64+c)*16+tid]=s; g_Pconv[(b*64+c)*16+tid]=0.f; }
        else g_SM[(b*32+(c-64))*16+tid]=s;
    }
}

// ---- merged router1: dots + noise + softmax + top2 + losses (1 CTA x 1024) ----
__global__ void k_router(const float* __restrict__ r1w, const float* __restrict__ r1b){
    __shared__ unsigned key1[2],key2[2];
    __shared__ float lg[96], sall[96], entsh[96];
    __shared__ int iall[32][2];
    int tid=threadIdx.x, w=tid>>5, lane=tid&31;
    if(tid==0){
        unsigned a0,b0,a1,b1;
        threefry(0u,42u,0u,0u,a0,b0); threefry(0u,42u,0u,1u,a1,b1);
        key1[0]=a0;key1[1]=b0;key2[0]=a1;key2[1]=b1;
    }
    // 96 dots over 32 warps (3 each)
    for(int d=w;d<96;d+=32){
        int b=d/3, e=d%3;
        const float* S=&g_S1x[b*1024];
        const float* W=&r1w[e*1024];
        float acc=0.f;
        for(int i=lane;i<1024;i+=32) acc+=S[i]*W[i];
        acc+=__shfl_xor_sync(0xFFFFFFFFu,acc,16);
        acc+=__shfl_xor_sync(0xFFFFFFFFu,acc,8);
        acc+=__shfl_xor_sync(0xFFFFFFFFu,acc,4);
        acc+=__shfl_xor_sync(0xFFFFFFFFu,acc,2);
        acc+=__shfl_xor_sync(0xFFFFFFFFu,acc,1);
        if(lane==0) lg[d]=acc*(1.0f/196.0f)+r1b[e];
    }
    __syncthreads();
    if(tid<96){
        lg[tid]+=0.05f*bits2unif(rbits32(key1[0],key1[1],(unsigned)tid));
        g_noise2[tid]=bits2unif(rbits32(key2[0],key2[1],(unsigned)tid));
    }
    __syncthreads();
    if(tid<32){
        int b=tid;
        float l0=lg[b*3],l1=lg[b*3+1],l2=lg[b*3+2];
        float m=fmaxf(l0,fmaxf(l1,l2));
        float x0=expf(l0-m),x1=expf(l1-m),x2=expf(l2-m);
        float s=x0+x1+x2;
        float pv[3]={x0/s,x1/s,x2/s};
        int i0=0; if(pv[1]>pv[i0])i0=1; if(pv[2]>pv[i0])i0=2;
        int i1=-1;
        for(int e=0;e<3;e++){ if(e==i0)continue; if(i1<0||pv[e]>pv[i1])i1=e; }
        int e3=3-i0-i1;
        g_topidx[b*2]=i0; g_topidx[b*2+1]=i1;
        g_topval[b*2]=pv[i0]; g_topval[b*2+1]=pv[i1];
        g_tb[b]=pv[i0]+pv[i1]; g_e3[b]=e3; g_s3[b]=pv[e3];
        sall[b*3]=pv[0]; sall[b*3+1]=pv[1]; sall[b*3+2]=pv[2];
        iall[b][0]=i0; iall[b][1]=i1;
    }
    __syncthreads();
    if(tid<96){ float sv=sall[tid]; entsh[tid]=-sv*logf(sv+1e-9f); }
    __syncthreads();
    if(tid==0){
        float sbar[3]={0,0,0},cnt[3]={0,0,0},ent=0.f;
        for(int b=0;b<32;b++){
            sbar[0]+=sall[b*3]; sbar[1]+=sall[b*3+1]; sbar[2]+=sall[b*3+2];
            ent+=entsh[b*3]+entsh[b*3+1]+entsh[b*3+2];
            cnt[iall[b][0]]+=1.f; cnt[iall[b][1]]+=1.f;
        }
        float lb=0.f;
        for(int e=0;e<3;e++) lb+=(sbar[e]/32.f)*(cnt[e]/32.f);
        g_lbent=lb+0.01f*(ent/32.f);
    }
}

// smem layout (bytes)
#define SM_PL   0        // 4096
#define SM_BIAS 4096     // 256
#define SM_A    4608     // 384 rows * 128B = 49152
#define SM_W    53760    // 18432 u32 = 73728
#define SM_TOT  127488

// ---- fp16 mma.sync conv: grid (2 halves, 2 slots, 32 b), 512 threads, 256-px tiles ----
__global__ void __launch_bounds__(512,1) k_conv_mma(const float* __restrict__ e1b){
    extern __shared__ char smem[];
    uint32_t sb=s2u(smem);
    int tid=threadIdx.x, wid=tid>>5, lane=tid&31;
    int half=blockIdx.x, slot=blockIdx.y, b=blockIdx.z;
    int e=g_topidx[b*2+slot];
    float gate=g_topval[b*2+slot];

    float* plf=(float*)(smem+SM_PL);
    for(int i=tid;i<1024;i+=512) plf[i]=0.f;
    if(tid<64) *(float*)(smem+SM_BIAS+tid*4)=e1b[e*64+tid];
    {
        const uint4* src=(const uint4*)&g_wf[(size_t)e*18432];
        uint4* dst=(uint4*)(smem+SM_W);
        for(int i=tid;i<4608;i+=512) dst[i]=src[i];
    }
    const float* biasS=(const float*)(smem+SM_BIAS);
    const char* xb=(const char*)(g_xh+(size_t)b*XR*64);

    const int offs[9]={-59,-58,-57,-1,0,1,57,58,59};
    int m0=wid*16;
    int lrow=(lane&7)+8*((lane>>3)&1);
    int lcg=(lane>=16)?1:0;
    int prow=lane>>2;

    int t0=half*7, t1=t0+7;
    for(int t=t0;t<t1;t++){
        int p0=t*256;
        __syncthreads();
        for(int i=tid;i<3072;i+=512){
            int r=i>>3, j=i&7;
            int pp=p0-64+r; pp=min(max(pp,0),XR-1);
            uint4 v=*(const uint4*)(xb+(size_t)pp*128+j*16);
            *(uint4*)(smem+SM_A+r*128+((j^(r&7))*16))=v;
        }
        __syncthreads();

        float c[8][4];
        #pragma unroll
        for(int nt=0;nt<8;nt++){ c[nt][0]=0.f;c[nt][1]=0.f;c[nt][2]=0.f;c[nt][3]=0.f; }

        #pragma unroll 3
        for(int s=0;s<9;s++){
            int R=64+m0+lrow+offs[s];
            uint32_t rowaddr=sb+SM_A+R*128;
            int rx=R&7;
            #pragma unroll
            for(int k=0;k<4;k++){
                int j=k*2+lcg;
                uint32_t aaddr=rowaddr+((j^rx)<<4);
                uint32_t a0,a1,a2,a3;
                asm volatile("ldmatrix.sync.aligned.m8n8.x4.shared.b16 {%0,%1,%2,%3}, [%4];"
                    :"=r"(a0),"=r"(a1),"=r"(a2),"=r"(a3):"r"(aaddr));
                const char* wptr=smem+SM_W+(size_t)(((s*4+k)*4)*128+lane*4)*4;
                #pragma unroll
                for(int ntp=0;ntp<4;ntp++){
                    uint4 wv=*(const uint4*)(wptr+ntp*512);
                    asm volatile("mma.sync.aligned.m16n8k16.row.col.f32.f16.f16.f32 "
                        "{%0,%1,%2,%3}, {%4,%5,%6,%7}, {%8,%9}, {%0,%1,%2,%3};"
                        :"+f"(c[2*ntp][0]),"+f"(c[2*ntp][1]),"+f"(c[2*ntp][2]),"+f"(c[2*ntp][3])
                        :"r"(a0),"r"(a1),"r"(a2),"r"(a3),"r"(wv.x),"r"(wv.y));
                    asm volatile("mma.sync.aligned.m16n8k16.row.col.f32.f16.f16.f32 "
                        "{%0,%1,%2,%3}, {%4,%5,%6,%7}, {%8,%9}, {%0,%1,%2,%3};"
                        :"+f"(c[2*ntp+1][0]),"+f"(c[2*ntp+1][1]),"+f"(c[2*ntp+1][2]),"+f"(c[2*ntp+1][3])
                        :"r"(a0),"r"(a1),"r"(a2),"r"(a3),"r"(wv.z),"r"(wv.w));
                }
            }
        }
        int px0=p0+m0+prow, px1=px0+8;
        int r0=px0/58, c0_=px0%58, r1=px1/58, c1_=px1%58;
        bool v0=(px0<XR)&&(r0>=1)&&(r0<=56)&&(c0_>=1)&&(c0_<=56);
        bool v1=(px1<XR)&&(r1>=1)&&(r1<=56)&&(c1_>=1)&&(c1_<=56);
        int bin0=((r0-1)&3)*4+((c0_-1)&3);
        int bin1=((r1-1)&3)*4+((c1_-1)&3);
        bool m01=(bin0==bin1);
        int ob0=__shfl_xor_sync(0xFFFFFFFFu,bin0,16);
        int ob1=__shfl_xor_sync(0xFFFFFFFFu,bin1,16);
        bool pair=(ob0==bin0)&&(ob1==bin1);
        int cobase=(lane&3)*2;
        #pragma unroll
        for(int nt=0;nt<8;nt++){
            int co=nt*8+cobase;
            float b0v=biasS[co], b1v=biasS[co+1];
            float x0=v0?gate*fmaxf(0.f,c[nt][0]+b0v):0.f;
            float x1=v0?gate*fmaxf(0.f,c[nt][1]+b1v):0.f;
            float y0=v1?gate*fmaxf(0.f,c[nt][2]+b0v):0.f;
            float y1=v1?gate*fmaxf(0.f,c[nt][3]+b1v):0.f;
            float a0=x0+(m01?y0:0.f), a1=x1+(m01?y1:0.f);
            float e0=m01?0.f:y0,      e1=m01?0.f:y1;
            float pa0=__shfl_xor_sync(0xFFFFFFFFu,a0,16);
            float pa1=__shfl_xor_sync(0xFFFFFFFFu,a1,16);
            float pe0=__shfl_xor_sync(0xFFFFFFFFu,e0,16);
            float pe1=__shfl_xor_sync(0xFFFFFFFFu,e1,16);
            if(pair){ a0+=pa0; a1+=pa1; e0+=pe0; e1+=pe1; }
            if(!pair || lane<16){
                atomicAdd(&plf[co*16+bin0], a0);
                atomicAdd(&plf[(co+1)*16+bin0], a1);
                if(!m01){
                    atomicAdd(&plf[co*16+bin1], e0);
                    atomicAdd(&plf[(co+1)*16+bin1], e1);
                }
            }
        }
    }
    __syncthreads();
    for(int i=tid;i<1024;i+=512)
        atomicAdd(&g_Pconv[(size_t)b*1024+i],plf[i]);
}

// ---- merged feat + router2 dots: grid (4,32) x 256 ----
__global__ void k_featdot2(const float* __restrict__ r2w, const float* __restrict__ r2b,
                           const float* __restrict__ e1b){
    int eb=blockIdx.x, b=blockIdx.y, tid=threadIdx.x;
    if(eb==3){
        // feature vector for batch b
        if(tid<160){
            int c=tid; float sum=0.f,v;
            if(c<64){
                const float* P=&g_Pconv[(b*64+c)*16];
                for(int k=0;k<16;k++) sum+=P[k];
                float c3=g_s3[b]*fmaxf(0.f,e1b[g_e3[b]*64+c]);
                v=sum*(1.f/3136.f)+c3;
            }else if(c<128){
                const float* P=&g_S1x[(b*64+(c-64))*16];
                for(int k=0;k<16;k++) sum+=P[k];
                v=g_tb[b]*sum*(1.f/3136.f);
            }else{
                const float* P=&g_SM[(b*32+(c-128))*16];
                for(int k=0;k<16;k++) sum+=P[k];
                v=sum*(1.f/3136.f);
            }
            g_feat[b*160+c]=v;
        }
        return;
    }
    __shared__ float red1[256], red2[256];
    int e=eb;
    float tb=g_tb[b]; int e3=g_e3[b]; float s3=g_s3[b];
    const float* W=&r2w[(size_t)e*2560];
    float a1=0.f,a2=0.f;
    for(int i=tid;i<2560;i+=256){
        int c=i>>4,k=i&15;
        float w=W[i], P;
        if(c<64){
            P=g_Pconv[(b*64+c)*16+k];
            a2+=s3*fmaxf(0.f,e1b[e3*64+c])*w;
        }else if(c<128){
            P=tb*g_S1x[(b*64+(c-64))*16+k];
        }else{
            P=g_SM[(b*32+(c-128))*16+k];
        }
        a1+=P*w;
    }
    red1[tid]=a1; red2[tid]=a2; __syncthreads();
    for(int s=128;s>0;s>>=1){ if(tid<s){red1[tid]+=red1[tid+s];red2[tid]+=red2[tid+s];} __syncthreads(); }
    if(tid==0) g_lg2[b*3+e]=red1[0]*(1.f/196.f)+red2[0]+r2b[e];
}

// ---- router2 finisher: softmax + losses + scalar outputs ----
__global__ void k_fin(float* __restrict__ out, const int* __restrict__ epoch_p){
    __shared__ float sels[96];
    int tid=threadIdx.x;  // 64
    int epoch=epoch_p?epoch_p[0]:35;
    if(tid<32){
        int b=tid;
        if(epoch<30){ sels[b*3]=sels[b*3+1]=sels[b*3+2]=1.f/3.f; }
        else{
            float l0=g_lg2[b*3]+0.05f*g_noise2[b*3];
            float l1=g_lg2[b*3+1]+0.05f*g_noise2[b*3+1];
            float l2=g_lg2[b*3+2]+0.05f*g_noise2[b*3+2];
            float m=fmaxf(l0,fmaxf(l1,l2));
            float x0=expf(l0-m),x1=expf(l1-m),x2=expf(l2-m);
            float sm=x0+x1+x2;
            sels[b*3]=(x0/sm+0.01f)/1.03f;
            sels[b*3+1]=(x1/sm+0.01f)/1.03f;
            sels[b*3+2]=(x2/sm+0.01f)/1.03f;
        }
        g_sel2eff[b*3]=sels[b*3]; g_sel2eff[b*3+1]=sels[b*3+1]; g_sel2eff[b*3+2]=sels[b*3+2];
    }
    __syncthreads();
    if(tid==0){
        float loss2=0.f;
        if(epoch>=30){
            for(int e=0;e<3;e++){
                float imp=0.f;
                for(int b=0;b<32;b++) imp+=sels[b*3+e];
                imp/=32.f;
                loss2+=imp*imp;
            }
            loss2*=3.f;
        }
        out[8192]=g_lbent+loss2;
        out[8192+1+32*32*NPIX]=loss2;
    }
}

__global__ void k_out(const float* __restrict__ e2w, const float* __restrict__ e2b,
                      float* __restrict__ out){
    __shared__ float F[160];
    int b=blockIdx.x, a=threadIdx.x;
    for(int i=a;i<160;i+=256) F[i]=g_feat[b*160+i];
    __syncthreads();
    float acc=0.f;
    for(int e=0;e<3;e++){
        float se=g_sel2eff[b*3+e];
        acc+=se*e2b[e*256+a];
        const float* W=&e2w[(size_t)e*160*256+a];
        for(int c=0;c<160;c++) acc+=se*F[c]*W[(size_t)c*256];
    }
    out[b*256+a]=acc;
}

extern "C" void kernel_launch(void* const* d_in, const int* in_sizes, int n_in,
                              void* d_out, int out_size) {
    const float* x   =(const float*)d_in[0];
    const float* mat =(const float*)d_in[1];
    const float* r1w =(const float*)d_in[2];
    const float* r1b =(const float*)d_in[3];
    const float* r2w =(const float*)d_in[4];
    const float* r2b =(const float*)d_in[5];
    const float* e1w =(const float*)d_in[6];
    const float* e1b =(const float*)d_in[7];
    const float* e2w =(const float*)d_in[8];
    const float* e2b =(const float*)d_in[9];
    const int*   ep  =(n_in>10)?(const int*)d_in[10]:(const int*)0;
    float* out=(float*)d_out;

    cudaFuncSetAttribute(k_conv_mma, cudaFuncAttributeMaxDynamicSharedMemorySize, SM_TOT);
    k_prep<<<dim3(57,32),256>>>(x,e1w);
    k_phase<<<dim3(96,32),224>>>(x,mat,out+8193);
    k_router<<<1,1024>>>(r1w,r1b);
    k_conv_mma<<<dim3(2,2,32),512,SM_TOT>>>(e1b);
    k_featdot2<<<dim3(4,32),256>>>(r2w,r2b,e1b);
    k_fin<<<1,64>>>(out,ep);
    k_out<<<32,256>>>(e2w,e2b,out);
}

// round 17
// speedup vs baseline: 5.5384x; 1.0145x over previous
#include <cuda_runtime.h>
#include <cuda_fp16.h>
#include <cstdint>

#define NPIX 3136
#define XR 3364   // 58*58 padded pixels

__device__ __align__(16) __half g_xh[32u*XR*64];
__device__ __align__(16) unsigned g_wf[3*9*4*4*128];   // frag-ordered fp16 weights
__device__ float g_S1x[32*64*16];
__device__ float g_SM [32*32*16];
__device__ float g_Pconv[32*64*16];
__device__ float g_lg2[96];
__device__ int   g_topidx[32*2];
__device__ float g_topval[32*2];
__device__ float g_tb[32];
__device__ int   g_e3[32];
__device__ float g_s3[32];
__device__ float g_noise2[96];
__device__ float g_lbent;
__device__ float g_sel2eff[96];
__device__ float g_feat[32*160];

// ---- threefry (jax partitionable) ----
__device__ __forceinline__ unsigned rotl32(unsigned x,int d){ return (x<<d)|(x>>(32-d)); }
__device__ void threefry(unsigned k0,unsigned k1,unsigned c0,unsigned c1,unsigned&o0,unsigned&o1){
    unsigned ks[3]={k0,k1,0x1BD11BDAu^k0^k1};
    unsigned x0=c0+ks[0],x1=c1+ks[1];
    const int ra[4]={13,15,26,6}, rb[4]={17,29,16,24};
    #pragma unroll
    for(int i=0;i<5;i++){
        const int* rr=((i&1)==0)?ra:rb;
        #pragma unroll
        for(int j=0;j<4;j++){ x0+=x1; x1=rotl32(x1,rr[j]); x1^=x0; }
        x0+=ks[(i+1)%3]; x1+=ks[(i+2)%3]+(unsigned)(i+1);
    }
    o0=x0;o1=x1;
}
__device__ __forceinline__ unsigned rbits32(unsigned k0,unsigned k1,unsigned i){
    unsigned a,b; threefry(k0,k1,0u,i,a,b); return a^b;
}
__device__ __forceinline__ float bits2unif(unsigned b){
    return __uint_as_float((b>>9)|0x3F800000u)-1.0f;
}

__device__ __forceinline__ uint32_t s2u(const void* p){
    uint32_t a; asm("{ .reg .u64 t; cvta.to.shared.u64 t, %1; cvt.u32.u64 %0, t; }":"=r"(a):"l"(p)); return a;
}
__device__ __forceinline__ unsigned packh(float a,float b){
    __half x=__float2half_rn(a), y=__float2half_rn(b);
    return ((unsigned)__half_as_ushort(y)<<16)|__half_as_ushort(x);
}

// ---- merged prep: pad-image build + border zero + weight fragments ----
__global__ void k_prep(const float* __restrict__ x, const float* __restrict__ e1w){
    __shared__ float sx[64][57];
    int xb=blockIdx.x, b=blockIdx.y, tid=threadIdx.x;
    if(xb<56){
        int h=xb;
        for(int i=tid;i<64*56;i+=256){ int ci=i/56,w=i%56; sx[ci][w]=x[((size_t)(b*64+ci))*NPIX+h*56+w]; }
        __syncthreads();
        for(int i=tid;i<56*32;i+=256){
            int px=i>>5, pr=i&31;
            size_t row=(size_t)b*XR+(size_t)(h+1)*58+(px+1);
            ((unsigned*)g_xh)[row*32+pr]=packh(sx[2*pr][px],sx[2*pr+1][px]);
        }
        if(tid<64){
            int col=(tid>=32)?57:0, pr=tid&31;
            size_t row=(size_t)b*XR+(size_t)(h+1)*58+col;
            ((unsigned*)g_xh)[row*32+pr]=0u;
        }
    } else {
        for(int i=tid;i<2*58*32;i+=256){
            int hf=i/(58*32), px=(i/32)%58, pr=i&31;
            size_t row=(size_t)b*XR+(size_t)(hf*57)*58+px;
            ((unsigned*)g_xh)[row*32+pr]=0u;
        }
        for(int i=b*432+tid;i<b*432+432;i+=256){
            int lane=i&31, f=i>>5;
            int ntp=f&3, k=(f>>2)&3, s=(f>>4)%9, e=f/144;
            int kb=(lane&3)*2, ci0=k*16+kb;
            int co_e=16*ntp+(lane>>2), co_o=co_e+8;
            unsigned o0=packh(e1w[((size_t)(e*64+co_e)*64+ci0)*9+s],   e1w[((size_t)(e*64+co_e)*64+ci0+1)*9+s]);
            unsigned o1=packh(e1w[((size_t)(e*64+co_e)*64+ci0+8)*9+s], e1w[((size_t)(e*64+co_e)*64+ci0+9)*9+s]);
            unsigned o2=packh(e1w[((size_t)(e*64+co_o)*64+ci0)*9+s],   e1w[((size_t)(e*64+co_o)*64+ci0+1)*9+s]);
            unsigned o3=packh(e1w[((size_t)(e*64+co_o)*64+ci0+8)*9+s], e1w[((size_t)(e*64+co_o)*64+ci0+9)*9+s]);
            unsigned* dst=&g_wf[f*128+lane*4];
            dst[0]=o0; dst[1]=o1; dst[2]=o2; dst[3]=o3;
        }
    }
}

__global__ void k_phase(const float* __restrict__ x, const float* __restrict__ matching,
                        float* __restrict__ out_match){
    int c=blockIdx.x, b=blockIdx.y, tid=threadIdx.x;
    int rr=tid/56, w=tid%56;
    bool ism=(c>=64);
    const float* src = ism ? (matching+(size_t)(b*32+(c-64))*NPIX) : (x+(size_t)(b*64+c)*NPIX);
    float* dst = ism ? (out_match+(size_t)(b*32+(c-64))*NPIX) : (float*)0;
    float acc=0.f;
    #pragma unroll
    for(int k=0;k<14;k++){ int idx=(rr+4*k)*56+w; float v=src[idx]; acc+=v; if(ism) dst[idx]=v; }
    __shared__ float part[224];
    part[tid]=acc; __syncthreads();
    if(tid<16){
        int p=tid/4,q=tid%4; float s=0.f;
        #pragma unroll
        for(int t=0;t<14;t++) s+=part[p*56+q+4*t];
        if(!ism){ g_S1x[(b*64+c)*16+tid]=s; g_Pconv[(b*64+c)*16+tid]=0.f; }
        else g_SM[(b*32+(c-64))*16+tid]=s;
    }
}

// ---- merged router1: dots + noise + softmax + top2 + losses (1 CTA x 1024) ----
__global__ void k_router(const float* __restrict__ r1w, const float* __restrict__ r1b){
    __shared__ unsigned key1[2],key2[2];
    __shared__ float lg[96], sall[96], entsh[96];
    __shared__ int iall[32][2];
    int tid=threadIdx.x, w=tid>>5, lane=tid&31;
    if(tid==0){
        unsigned a0,b0,a1,b1;
        threefry(0u,42u,0u,0u,a0,b0); threefry(0u,42u,0u,1u,a1,b1);
        key1[0]=a0;key1[1]=b0;key2[0]=a1;key2[1]=b1;
    }
    for(int d=w;d<96;d+=32){
        int b=d/3, e=d%3;
        const float* S=&g_S1x[b*1024];
        const float* W=&r1w[e*1024];
        float acc=0.f;
        for(int i=lane;i<1024;i+=32) acc+=S[i]*W[i];
        acc+=__shfl_xor_sync(0xFFFFFFFFu,acc,16);
        acc+=__shfl_xor_sync(0xFFFFFFFFu,acc,8);
        acc+=__shfl_xor_sync(0xFFFFFFFFu,acc,4);
        acc+=__shfl_xor_sync(0xFFFFFFFFu,acc,2);
        acc+=__shfl_xor_sync(0xFFFFFFFFu,acc,1);
        if(lane==0) lg[d]=acc*(1.0f/196.0f)+r1b[e];
    }
    __syncthreads();
    if(tid<96){
        lg[tid]+=0.05f*bits2unif(rbits32(key1[0],key1[1],(unsigned)tid));
        g_noise2[tid]=bits2unif(rbits32(key2[0],key2[1],(unsigned)tid));
    }
    __syncthreads();
    if(tid<32){
        int b=tid;
        float l0=lg[b*3],l1=lg[b*3+1],l2=lg[b*3+2];
        float m=fmaxf(l0,fmaxf(l1,l2));
        float x0=expf(l0-m),x1=expf(l1-m),x2=expf(l2-m);
        float s=x0+x1+x2;
        float pv[3]={x0/s,x1/s,x2/s};
        int i0=0; if(pv[1]>pv[i0])i0=1; if(pv[2]>pv[i0])i0=2;
        int i1=-1;
        for(int e=0;e<3;e++){ if(e==i0)continue; if(i1<0||pv[e]>pv[i1])i1=e; }
        int e3=3-i0-i1;
        g_topidx[b*2]=i0; g_topidx[b*2+1]=i1;
        g_topval[b*2]=pv[i0]; g_topval[b*2+1]=pv[i1];
        g_tb[b]=pv[i0]+pv[i1]; g_e3[b]=e3; g_s3[b]=pv[e3];
        sall[b*3]=pv[0]; sall[b*3+1]=pv[1]; sall[b*3+2]=pv[2];
        iall[b][0]=i0; iall[b][1]=i1;
    }
    __syncthreads();
    if(tid<96){ float sv=sall[tid]; entsh[tid]=-sv*logf(sv+1e-9f); }
    __syncthreads();
    if(tid==0){
        float sbar[3]={0,0,0},cnt[3]={0,0,0},ent=0.f;
        for(int b=0;b<32;b++){
            sbar[0]+=sall[b*3]; sbar[1]+=sall[b*3+1]; sbar[2]+=sall[b*3+2];
            ent+=entsh[b*3]+entsh[b*3+1]+entsh[b*3+2];
            cnt[iall[b][0]]+=1.f; cnt[iall[b][1]]+=1.f;
        }
        float lb=0.f;
        for(int e=0;e<3;e++) lb+=(sbar[e]/32.f)*(cnt[e]/32.f);
        g_lbent=lb+0.01f*(ent/32.f);
    }
}

// smem layout (bytes)
#define SM_PL   0        // 4096
#define SM_BIAS 4096     // 256
#define SM_A    4608     // 384 rows * 128B = 49152
#define SM_W    53760    // 18432 u32 = 73728
#define SM_TOT  127488

// ---- fp16 mma.sync conv: grid (2 halves, 2 slots, 32 b), 256 threads, M=32/warp ----
__global__ void __launch_bounds__(256,1) k_conv_mma(const float* __restrict__ e1b){
    extern __shared__ char smem[];
    uint32_t sb=s2u(smem);
    int tid=threadIdx.x, wid=tid>>5, lane=tid&31;
    int half=blockIdx.x, slot=blockIdx.y, b=blockIdx.z;
    int e=g_topidx[b*2+slot];
    float gate=g_topval[b*2+slot];

    float* plf=(float*)(smem+SM_PL);
    for(int i=tid;i<1024;i+=256) plf[i]=0.f;
    if(tid<64) *(float*)(smem+SM_BIAS+tid*4)=e1b[e*64+tid];
    {
        const uint4* src=(const uint4*)&g_wf[(size_t)e*18432];
        uint4* dst=(uint4*)(smem+SM_W);
        for(int i=tid;i<4608;i+=256) dst[i]=src[i];
    }
    const float* biasS=(const float*)(smem+SM_BIAS);
    const char* xb=(const char*)(g_xh+(size_t)b*XR*64);

    const int offs[9]={-59,-58,-57,-1,0,1,57,58,59};
    int m0=wid*32;                 // 0..224 within 256-px tile
    int lrow=(lane&7)+8*((lane>>3)&1);
    int lcg=(lane>=16)?1:0;
    int prow=lane>>2;

    int t0=half*7, t1=t0+7;
    for(int t=t0;t<t1;t++){
        int p0=t*256;
        __syncthreads();
        for(int i=tid;i<3072;i+=256){
            int r=i>>3, j=i&7;
            int pp=p0-64+r; pp=min(max(pp,0),XR-1);
            uint4 v=*(const uint4*)(xb+(size_t)pp*128+j*16);
            *(uint4*)(smem+SM_A+r*128+((j^(r&7))*16))=v;
        }
        __syncthreads();

        float c[2][8][4];
        #pragma unroll
        for(int rb=0;rb<2;rb++)
            #pragma unroll
            for(int nt=0;nt<8;nt++){ c[rb][nt][0]=0.f;c[rb][nt][1]=0.f;c[rb][nt][2]=0.f;c[rb][nt][3]=0.f; }

        #pragma unroll 3
        for(int s=0;s<9;s++){
            #pragma unroll
            for(int k=0;k<4;k++){
                int j=k*2+lcg;
                uint32_t a[2][4];
                #pragma unroll
                for(int rb=0;rb<2;rb++){
                    int R=64+m0+rb*16+lrow+offs[s];
                    uint32_t aaddr=sb+SM_A+R*128+(((j^(R&7)))<<4);
                    asm volatile("ldmatrix.sync.aligned.m8n8.x4.shared.b16 {%0,%1,%2,%3}, [%4];"
                        :"=r"(a[rb][0]),"=r"(a[rb][1]),"=r"(a[rb][2]),"=r"(a[rb][3]):"r"(aaddr));
                }
                const char* wptr=smem+SM_W+(size_t)(((s*4+k)*4)*128+lane*4)*4;
                #pragma unroll
                for(int ntp=0;ntp<4;ntp++){
                    uint4 wv=*(const uint4*)(wptr+ntp*512);
                    #pragma unroll
                    for(int rb=0;rb<2;rb++){
                        asm volatile("mma.sync.aligned.m16n8k16.row.col.f32.f16.f16.f32 "
                            "{%0,%1,%2,%3}, {%4,%5,%6,%7}, {%8,%9}, {%0,%1,%2,%3};"
                            :"+f"(c[rb][2*ntp][0]),"+f"(c[rb][2*ntp][1]),"+f"(c[rb][2*ntp][2]),"+f"(c[rb][2*ntp][3])
                            :"r"(a[rb][0]),"r"(a[rb][1]),"r"(a[rb][2]),"r"(a[rb][3]),"r"(wv.x),"r"(wv.y));
                        asm volatile("mma.sync.aligned.m16n8k16.row.col.f32.f16.f16.f32 "
                            "{%0,%1,%2,%3}, {%4,%5,%6,%7}, {%8,%9}, {%0,%1,%2,%3};"
                            :"+f"(c[rb][2*ntp+1][0]),"+f"(c[rb][2*ntp+1][1]),"+f"(c[rb][2*ntp+1][2]),"+f"(c[rb][2*ntp+1][3])
                            :"r"(a[rb][0]),"r"(a[rb][1]),"r"(a[rb][2]),"r"(a[rb][3]),"r"(wv.z),"r"(wv.w));
                    }
                }
            }
        }
        // ---- reduced-atomic epilogue, once per row-block ----
        #pragma unroll
        for(int rb=0;rb<2;rb++){
            int px0=p0+m0+rb*16+prow, px1=px0+8;
            int r0=px0/58, c0_=px0%58, r1=px1/58, c1_=px1%58;
            bool v0=(px0<XR)&&(r0>=1)&&(r0<=56)&&(c0_>=1)&&(c0_<=56);
            bool v1=(px1<XR)&&(r1>=1)&&(r1<=56)&&(c1_>=1)&&(c1_<=56);
            int bin0=((r0-1)&3)*4+((c0_-1)&3);
            int bin1=((r1-1)&3)*4+((c1_-1)&3);
            bool m01=(bin0==bin1);
            int ob0=__shfl_xor_sync(0xFFFFFFFFu,bin0,16);
            int ob1=__shfl_xor_sync(0xFFFFFFFFu,bin1,16);
            bool pair=(ob0==bin0)&&(ob1==bin1);
            int cobase=(lane&3)*2;
            #pragma unroll
            for(int nt=0;nt<8;nt++){
                int co=nt*8+cobase;
                float b0v=biasS[co], b1v=biasS[co+1];
                float x0=v0?gate*fmaxf(0.f,c[rb][nt][0]+b0v):0.f;
                float x1=v0?gate*fmaxf(0.f,c[rb][nt][1]+b1v):0.f;
                float y0=v1?gate*fmaxf(0.f,c[rb][nt][2]+b0v):0.f;
                float y1=v1?gate*fmaxf(0.f,c[rb][nt][3]+b1v):0.f;
                float a0=x0+(m01?y0:0.f), a1=x1+(m01?y1:0.f);
                float e0=m01?0.f:y0,      e1=m01?0.f:y1;
                float pa0=__shfl_xor_sync(0xFFFFFFFFu,a0,16);
                float pa1=__shfl_xor_sync(0xFFFFFFFFu,a1,16);
                float pe0=__shfl_xor_sync(0xFFFFFFFFu,e0,16);
                float pe1=__shfl_xor_sync(0xFFFFFFFFu,e1,16);
                if(pair){ a0+=pa0; a1+=pa1; e0+=pe0; e1+=pe1; }
                if(!pair || lane<16){
                    atomicAdd(&plf[co*16+bin0], a0);
                    atomicAdd(&plf[(co+1)*16+bin0], a1);
                    if(!m01){
                        atomicAdd(&plf[co*16+bin1], e0);
                        atomicAdd(&plf[(co+1)*16+bin1], e1);
                    }
                }
            }
        }
    }
    __syncthreads();
    for(int i=tid;i<1024;i+=256)
        atomicAdd(&g_Pconv[(size_t)b*1024+i],plf[i]);
}

// ---- merged feat + router2 dots: grid (4,32) x 256 ----
__global__ void k_featdot2(const float* __restrict__ r2w, const float* __restrict__ r2b,
                           const float* __restrict__ e1b){
    int eb=blockIdx.x, b=blockIdx.y, tid=threadIdx.x;
    if(eb==3){
        if(tid<160){
            int c=tid; float sum=0.f,v;
            if(c<64){
                const float* P=&g_Pconv[(b*64+c)*16];
                for(int k=0;k<16;k++) sum+=P[k];
                float c3=g_s3[b]*fmaxf(0.f,e1b[g_e3[b]*64+c]);
                v=sum*(1.f/3136.f)+c3;
            }else if(c<128){
                const float* P=&g_S1x[(b*64+(c-64))*16];
                for(int k=0;k<16;k++) sum+=P[k];
                v=g_tb[b]*sum*(1.f/3136.f);
            }else{
                const float* P=&g_SM[(b*32+(c-128))*16];
                for(int k=0;k<16;k++) sum+=P[k];
                v=sum*(1.f/3136.f);
            }
            g_feat[b*160+c]=v;
        }
        return;
    }
    __shared__ float red1[256], red2[256];
    int e=eb;
    float tb=g_tb[b]; int e3=g_e3[b]; float s3=g_s3[b];
    const float* W=&r2w[(size_t)e*2560];
    float a1=0.f,a2=0.f;
    for(int i=tid;i<2560;i+=256){
        int c=i>>4,k=i&15;
        float w=W[i], P;
        if(c<64){
            P=g_Pconv[(b*64+c)*16+k];
            a2+=s3*fmaxf(0.f,e1b[e3*64+c])*w;
        }else if(c<128){
            P=tb*g_S1x[(b*64+(c-64))*16+k];
        }else{
            P=g_SM[(b*32+(c-128))*16+k];
        }
        a1+=P*w;
    }
    red1[tid]=a1; red2[tid]=a2; __syncthreads();
    for(int s=128;s>0;s>>=1){ if(tid<s){red1[tid]+=red1[tid+s];red2[tid]+=red2[tid+s];} __syncthreads(); }
    if(tid==0) g_lg2[b*3+e]=red1[0]*(1.f/196.f)+red2[0]+r2b[e];
}

// ---- router2 finisher ----
__global__ void k_fin(float* __restrict__ out, const int* __restrict__ epoch_p){
    __shared__ float sels[96];
    int tid=threadIdx.x;  // 64
    int epoch=epoch_p?epoch_p[0]:35;
    if(tid<32){
        int b=tid;
        if(epoch<30){ sels[b*3]=sels[b*3+1]=sels[b*3+2]=1.f/3.f; }
        else{
            float l0=g_lg2[b*3]+0.05f*g_noise2[b*3];
            float l1=g_lg2[b*3+1]+0.05f*g_noise2[b*3+1];
            float l2=g_lg2[b*3+2]+0.05f*g_noise2[b*3+2];
            float m=fmaxf(l0,fmaxf(l1,l2));
            float x0=expf(l0-m),x1=expf(l1-m),x2=expf(l2-m);
            float sm=x0+x1+x2;
            sels[b*3]=(x0/sm+0.01f)/1.03f;
            sels[b*3+1]=(x1/sm+0.01f)/1.03f;
            sels[b*3+2]=(x2/sm+0.01f)/1.03f;
        }
        g_sel2eff[b*3]=sels[b*3]; g_sel2eff[b*3+1]=sels[b*3+1]; g_sel2eff[b*3+2]=sels[b*3+2];
    }
    __syncthreads();
    if(tid==0){
        float loss2=0.f;
        if(epoch>=30){
            for(int e=0;e<3;e++){
                float imp=0.f;
                for(int b=0;b<32;b++) imp+=sels[b*3+e];
                imp/=32.f;
                loss2+=imp*imp;
            }
            loss2*=3.f;
        }
        out[8192]=g_lbent+loss2;
        out[8192+1+32*32*NPIX]=loss2;
    }
}

__global__ void k_out(const float* __restrict__ e2w, const float* __restrict__ e2b,
                      float* __restrict__ out){
    __shared__ float F[160];
    int b=blockIdx.x, a=threadIdx.x;
    for(int i=a;i<160;i+=256) F[i]=g_feat[b*160+i];
    __syncthreads();
    float acc=0.f;
    for(int e=0;e<3;e++){
        float se=g_sel2eff[b*3+e];
        acc+=se*e2b[e*256+a];
        const float* W=&e2w[(size_t)e*160*256+a];
        for(int c=0;c<160;c++) acc+=se*F[c]*W[(size_t)c*256];
    }
    out[b*256+a]=acc;
}

extern "C" void kernel_launch(void* const* d_in, const int* in_sizes, int n_in,
                              void* d_out, int out_size) {
    const float* x   =(const float*)d_in[0];
    const float* mat =(const float*)d_in[1];
    const float* r1w =(const float*)d_in[2];
    const float* r1b =(const float*)d_in[3];
    const float* r2w =(const float*)d_in[4];
    const float* r2b =(const float*)d_in[5];
    const float* e1w =(const float*)d_in[6];
    const float* e1b =(const float*)d_in[7];
    const float* e2w =(const float*)d_in[8];
    const float* e2b =(const float*)d_in[9];
    const int*   ep  =(n_in>10)?(const int*)d_in[10]:(const int*)0;
    float* out=(float*)d_out;

    cudaFuncSetAttribute(k_conv_mma, cudaFuncAttributeMaxDynamicSharedMemorySize, SM_TOT);
    k_prep<<<dim3(57,32),256>>>(x,e1w);
    k_phase<<<dim3(96,32),224>>>(x,mat,out+8193);
    k_router<<<1,1024>>>(r1w,r1b);
    k_conv_mma<<<dim3(2,2,32),256,SM_TOT>>>(e1b);
    k_featdot2<<<dim3(4,32),256>>>(r2w,r2b,e1b);
    k_fin<<<1,64>>>(out,ep);
    k_out<<<32,256>>>(e2w,e2b,out);
}